// round 6
// baseline (speedup 1.0000x reference)
#include <cuda_runtime.h>
#include <cuda_bf16.h>
#include <math.h>
#include <stdint.h>

// Problem constants
#define S_LEN 1024
#define BATCH 2
#define DMODEL 1024
#define HEADS 16
#define HDIM 64
#define TLEN 2048
#define FFDIM 4096
#define ROWS_X (S_LEN * BATCH)     // 2048
#define ROWS_T (TLEN * BATCH)      // 4096

// ---------------- scratch buffers (device globals) ---------------------------
__device__ float g_q  [ROWS_X * DMODEL];
__device__ float g_ke [ROWS_T * DMODEL];
__device__ float g_kr [ROWS_T * DMODEL];
__device__ float g_v  [ROWS_T * DMODEL];
__device__ float g_t  [ROWS_X * DMODEL];
__device__ float g_u  [ROWS_X * DMODEL];
__device__ float g_h1p[ROWS_X * FFDIM];      // permuted+rounded (w1 out)
// permuted + tf32-rounded GEMM inputs
__device__ float g_xp  [ROWS_X * DMODEL];
__device__ float g_memp[ROWS_X * DMODEL];
__device__ float g_pp  [ROWS_T * DMODEL];
__device__ float g_wqp [DMODEL * DMODEL];
__device__ float g_wkep[DMODEL * DMODEL];
__device__ float g_wkrp[DMODEL * DMODEL];
__device__ float g_wvp [DMODEL * DMODEL];
__device__ float g_wcp [DMODEL * DMODEL];
__device__ float g_w1p [FFDIM * DMODEL];
__device__ float g_w2p [DMODEL * FFDIM];
__device__ float g_avp [ROWS_X * DMODEL];    // flash out, permuted+rounded
__device__ float g_up_ [ROWS_X * DMODEL];    // LN1 out, permuted+rounded
// flash-prep outputs
__device__ uint32_t g_kk2 [BATCH * HEADS * TLEN * HDIM];
__device__ uint32_t g_v2  [BATCH * HEADS * TLEN * HDIM];
__device__ float    g_bias[BATCH * HEADS * TLEN];

// ---------------- common PTX helpers ----------------------------------------
__device__ __forceinline__ uint32_t f2tf32(float f) {
    uint32_t r;
    asm("cvt.rna.tf32.f32 %0, %1;" : "=r"(r) : "f"(f));
    return r;
}
__device__ __forceinline__ float roundtf(float f) {
    return __uint_as_float(f2tf32(f));
}
__device__ __forceinline__ void cp_async16(uint32_t saddr, const void* gptr) {
    asm volatile("cp.async.cg.shared.global [%0], [%1], 16;\n"
                 :: "r"(saddr), "l"(gptr));
}
__device__ __forceinline__ void cp_commit() {
    asm volatile("cp.async.commit_group;\n");
}
template <int N>
__device__ __forceinline__ void cp_wait() {
    asm volatile("cp.async.wait_group %0;\n" :: "n"(N));
}
__device__ __forceinline__ void mma_tf32(float* d, const uint32_t* a, const uint32_t* b) {
    asm volatile(
        "mma.sync.aligned.m16n8k8.row.col.f32.tf32.tf32.f32 "
        "{%0,%1,%2,%3}, {%4,%5,%6,%7}, {%8,%9}, {%0,%1,%2,%3};\n"
        : "+f"(d[0]), "+f"(d[1]), "+f"(d[2]), "+f"(d[3])
        : "r"(a[0]), "r"(a[1]), "r"(a[2]), "r"(a[3]), "r"(b[0]), "r"(b[1]));
}
// permutation within 8-blocks: old col c -> new pos
__device__ __forceinline__ int perm8(int c) {
    return (c & ~7) + 2 * (c & 3) + ((c >> 2) & 1);
}
// swizzled index for element (row, c) in a [rows]x32 float tile
__device__ __forceinline__ int sw_idx(int row, int c) {
    return (row << 5) + ((((c >> 2) ^ row) & 7) << 2) + (c & 3);
}

// ---------------- merged repack: tf32-round + k-permute ----------------------
// one launch handles all tensors via a segment table
#define MAXSEG 12
struct RepackSegs {
    const float* src[MAXSEG];
    float*       dst[MAXSEG];
    int          end8[MAXSEG];   // cumulative ends (in 8-element blocks)
    int          nseg;
};

__global__ void __launch_bounds__(256)
repack_all_kernel(RepackSegs segs, int total8)
{
    int idx = blockIdx.x * 256 + threadIdx.x;
    if (idx >= total8) return;
    int s = 0;
#pragma unroll
    for (int i = 0; i < MAXSEG; i++)
        if (i < segs.nseg && idx >= segs.end8[i]) s = i + 1;
    const int base = s ? segs.end8[s - 1] : 0;
    const int off = idx - base;

    const float4* s4 = (const float4*)(segs.src[s] + (size_t)off * 8);
    float4 a = s4[0], b = s4[1];
    float4 o0, o1;
    o0.x = roundtf(a.x); o0.y = roundtf(b.x); o0.z = roundtf(a.y); o0.w = roundtf(b.y);
    o1.x = roundtf(a.z); o1.y = roundtf(b.z); o1.z = roundtf(a.w); o1.w = roundtf(b.w);
    float4* d4 = (float4*)(segs.dst[s] + (size_t)off * 8);
    d4[0] = o0; d4[1] = o1;
}

// ---------------- tf32 tensor-core GEMM v3 -----------------------------------
// C[M,N] = A[M,Kd] * W[N,Kd]^T. A and W are PRE-ROUNDED + k-PERMUTED.
// 256 threads (8 warps, 2m x 4n), warp tile 64x32, CTA 128x128, BK=32, 3 stages.
struct GemmPtrs {
    const float* A[7];
    const float* W[7];
    float*       C[7];
};

#define G2_SMEM (3 * 8192 * 4)   // 3 stages x (A 4096 + B 4096 floats) = 98304 B

// flags: 1 = relu, 2 = permute+round output
__global__ void __launch_bounds__(256, 2)
tf32gemm3_kernel(GemmPtrs ptrs, const float* __restrict__ bias,
                 int M, int N, int Kd, int flags)
{
    extern __shared__ float smem[];
    const float* A = ptrs.A[blockIdx.z];
    const float* W = ptrs.W[blockIdx.z];
    float*       C = ptrs.C[blockIdx.z];

    const int tid = threadIdx.x;
    const int lane = tid & 31, wrp = tid >> 5;
    const int wm = wrp & 1, wn = wrp >> 1;     // 2 x 4 warp grid
    const int q = lane >> 2, r = lane & 3;
    const int m0 = blockIdx.y * 128;
    const int n0 = blockIdx.x * 128;

    float acc[4][4][4];
#pragma unroll
    for (int i = 0; i < 4; i++)
#pragma unroll
        for (int j = 0; j < 4; j++)
#pragma unroll
            for (int e = 0; e < 4; e++) acc[i][j][e] = 0.f;

    const uint32_t sbase = (uint32_t)__cvta_generic_to_shared(smem);

    auto issue = [&](int buf, int k0) {
        uint32_t so = sbase + (uint32_t)buf * 8192u * 4u;
#pragma unroll
        for (int i = 0; i < 4; i++) {
            int cid = tid + i * 256;          // 0..1023
            int row = cid >> 3, c = cid & 7;
            int pc = c ^ (row & 7);
            uint32_t soff = (uint32_t)((row << 5) + (pc << 2)) * 4u;
            cp_async16(so + soff,            A + (size_t)(m0 + row) * Kd + k0 + c * 4);
            cp_async16(so + 16384u + soff,   W + (size_t)(n0 + row) * Kd + k0 + c * 4);
        }
    };

    const int KT = Kd >> 5;
    issue(0, 0);  cp_commit();
    issue(1, 32); cp_commit();

    for (int kt = 0; kt < KT; kt++) {
        cp_wait<1>();
        __syncthreads();
        if (kt + 2 < KT) { issue((kt + 2) % 3, (kt + 2) << 5); cp_commit(); }

        const float* As = smem + (size_t)(kt % 3) * 8192;
        const float* Ws = As + 4096;

#pragma unroll
        for (int kk = 0; kk < 32; kk += 8) {
            uint32_t av[4][4];
#pragma unroll
            for (int mt = 0; mt < 4; mt++) {
                int mr = wm * 64 + mt * 16 + q;
                uint2 lo = *(const uint2*)&As[sw_idx(mr,     kk + 2 * r)];
                uint2 hi = *(const uint2*)&As[sw_idx(mr + 8, kk + 2 * r)];
                av[mt][0] = lo.x; av[mt][1] = hi.x;
                av[mt][2] = lo.y; av[mt][3] = hi.y;
            }
            uint32_t bv[4][2];
#pragma unroll
            for (int nt = 0; nt < 4; nt++) {
                int nr = wn * 32 + nt * 8 + q;
                uint2 bb = *(const uint2*)&Ws[sw_idx(nr, kk + 2 * r)];
                bv[nt][0] = bb.x; bv[nt][1] = bb.y;
            }
#pragma unroll
            for (int mt = 0; mt < 4; mt++)
#pragma unroll
                for (int nt = 0; nt < 4; nt++)
                    mma_tf32(acc[mt][nt], av[mt], bv[nt]);
        }
        __syncthreads();
    }

    // epilogue
#pragma unroll
    for (int mt = 0; mt < 4; mt++) {
        const int row0 = m0 + wm * 64 + mt * 16 + q;
#pragma unroll
        for (int nt = 0; nt < 4; nt++) {
            const int col = n0 + wn * 32 + nt * 8 + 2 * r;
            float b0 = bias ? bias[col]     : 0.f;
            float b1 = bias ? bias[col + 1] : 0.f;
            float v0 = acc[mt][nt][0] + b0, v1 = acc[mt][nt][1] + b1;
            float v2 = acc[mt][nt][2] + b0, v3 = acc[mt][nt][3] + b1;
            if (flags & 1) {
                v0 = fmaxf(v0, 0.f); v1 = fmaxf(v1, 0.f);
                v2 = fmaxf(v2, 0.f); v3 = fmaxf(v3, 0.f);
            }
            if (flags & 2) {
                const int p0 = perm8(col), p1 = perm8(col + 1);
                C[(size_t)row0 * N + p0]       = roundtf(v0);
                C[(size_t)row0 * N + p1]       = roundtf(v1);
                C[(size_t)(row0 + 8) * N + p0] = roundtf(v2);
                C[(size_t)(row0 + 8) * N + p1] = roundtf(v3);
            } else {
                *(float2*)(C + (size_t)row0 * N + col)       = make_float2(v0, v1);
                *(float2*)(C + (size_t)(row0 + 8) * N + col) = make_float2(v2, v3);
            }
        }
    }
}

// ---------------- prep: KK = ke+kr (tf32), bias = u.ke + v.kr, repack V -----
__global__ void __launch_bounds__(256)
prep_kernel(const float* __restrict__ ke, const float* __restrict__ kr,
            const float* __restrict__ v,
            const float* __restrict__ ub, const float* __restrict__ vb,
            uint32_t* __restrict__ kk2, uint32_t* __restrict__ v2,
            float* __restrict__ biasO)
{
    const int row = blockIdx.x;          // = t*BATCH + b
    const int t = row / BATCH, b = row % BATCH;
    const int tid = threadIdx.x;
    const int h = tid >> 4, l16 = tid & 15, d0 = l16 * 4;

    const size_t src = (size_t)row * DMODEL + h * HDIM + d0;
    float4 kev = *(const float4*)(ke + src);
    float4 krv = *(const float4*)(kr + src);
    float4 vv  = *(const float4*)(v  + src);

    const size_t dst = ((size_t)(b * HEADS + h) * TLEN + t) * HDIM + d0;
    uint4 kko, vvo;
    kko.x = f2tf32(kev.x + krv.x); kko.y = f2tf32(kev.y + krv.y);
    kko.z = f2tf32(kev.z + krv.z); kko.w = f2tf32(kev.w + krv.w);
    vvo.x = f2tf32(vv.x); vvo.y = f2tf32(vv.y);
    vvo.z = f2tf32(vv.z); vvo.w = f2tf32(vv.w);
    *(uint4*)(kk2 + dst) = kko;
    *(uint4*)(v2  + dst) = vvo;

    float4 u4 = *(const float4*)(ub + h * HDIM + d0);
    float4 w4 = *(const float4*)(vb + h * HDIM + d0);
    float bsum = u4.x * kev.x + u4.y * kev.y + u4.z * kev.z + u4.w * kev.w
               + w4.x * krv.x + w4.y * krv.y + w4.z * krv.z + w4.w * krv.w;
#pragma unroll
    for (int off = 8; off; off >>= 1)
        bsum += __shfl_xor_sync(0xffffffffu, bsum, off, 16);
    if (l16 == 0) biasO[(size_t)(b * HEADS + h) * TLEN + t] = bsum;
}

// ---------------- tensor-core flash attention --------------------------------
#define FQS  0
#define FPS  8192
#define FKK  16384
#define FVS  20480
#define FBI  24576
#define FLASH_SMEM ((24576 + 64) * 4)

__device__ __forceinline__ int sw64(int row, int c) {
    return (row << 6) + (((c >> 2) ^ (row & 7)) << 2) + (c & 3);
}

__global__ void __launch_bounds__(256, 2)
flash_tc_kernel(const float* __restrict__ qg,
                const uint32_t* __restrict__ kk2,
                const uint32_t* __restrict__ v2,
                const float* __restrict__ biasG,
                float* __restrict__ out)   // permuted+rounded
{
    extern __shared__ uint32_t fsm[];
    uint32_t* Qs  = fsm + FQS;
    uint32_t* Ps  = fsm + FPS;
    uint32_t* KKs = fsm + FKK;
    uint32_t* Vs  = fsm + FVS;
    float*    biasS = (float*)(fsm + FBI);

    const int qb = blockIdx.x, h = blockIdx.y, b = blockIdx.z;
    const int tid = threadIdx.x;
    const int lane = tid & 31, wid = tid >> 5;
    const int q = lane >> 2, r = lane & 3;
    const int mw = wid * 16;

    const uint32_t sbase = (uint32_t)__cvta_generic_to_shared(fsm);
    const size_t   bh    = (size_t)(b * HEADS + h) * TLEN;
    const uint32_t* kkbh = kk2 + bh * HDIM;
    const uint32_t* vbh  = v2  + bh * HDIM;
    const float*    bibh = biasG + bh;

#pragma unroll
    for (int it = 0; it < 8; it++) {
        int idx = tid + it * 256;
        int row = idx >> 4, g4 = (idx & 15) * 4;
        const float4 qv = *(const float4*)(qg +
            ((size_t)((qb * 128 + row) * BATCH + b)) * DMODEL + h * HDIM + g4);
        uint4 qo;
        qo.x = f2tf32(qv.x); qo.y = f2tf32(qv.y);
        qo.z = f2tf32(qv.z); qo.w = f2tf32(qv.w);
        *(uint4*)(Qs + sw64(row, g4)) = qo;
    }

    auto issueKV = [&](int t0) {
#pragma unroll
        for (int it = 0; it < 4; it++) {
            int idx = tid + it * 256;
            int row = idx >> 4, g4 = (idx & 15) * 4;
            size_t src = (size_t)(t0 + row) * HDIM + g4;
            uint32_t sdst = sbase + (uint32_t)sw64(row, g4) * 4;
            cp_async16(sdst + FKK * 4, kkbh + src);
            cp_async16(sdst + FVS * 4, vbh + src);
        }
        if (tid < 16)
            cp_async16(sbase + FBI * 4 + tid * 16, bibh + t0 + tid * 4);
    };

    issueKV(0);
    cp_commit();
    cp_wait<0>();
    __syncthreads();

    float m0 = -1e30f, m1 = -1e30f, l0 = 0.f, l1 = 0.f;
    float O[8][4];
#pragma unroll
    for (int nt = 0; nt < 8; nt++)
#pragma unroll
        for (int e = 0; e < 4; e++) O[nt][e] = 0.f;

    const int ntiles = 18 + 2 * qb;
    const int srow0 = qb * 128 + mw + q;

    for (int tt = 0; tt < ntiles; tt++) {
        const int t0 = tt * 64;

        float sc[8][4];
#pragma unroll
        for (int nt = 0; nt < 8; nt++)
#pragma unroll
            for (int e = 0; e < 4; e++) sc[nt][e] = 0.f;

#pragma unroll
        for (int kk = 0; kk < 64; kk += 8) {
            uint32_t a[4];
            a[0] = Qs[sw64(mw + q,     kk + r)];
            a[1] = Qs[sw64(mw + q + 8, kk + r)];
            a[2] = Qs[sw64(mw + q,     kk + r + 4)];
            a[3] = Qs[sw64(mw + q + 8, kk + r + 4)];
#pragma unroll
            for (int nt = 0; nt < 8; nt++) {
                uint32_t bb[2];
                bb[0] = KKs[sw64(nt * 8 + q, kk + r)];
                bb[1] = KKs[sw64(nt * 8 + q, kk + r + 4)];
                mma_tf32(sc[nt], a, bb);
            }
        }

        const bool mt_ = (tt >= 16 + 2 * qb);
        float tmax0 = -1e30f, tmax1 = -1e30f;
#pragma unroll
        for (int nt = 0; nt < 8; nt++) {
            const int colb = nt * 8 + 2 * r;
            const float bi0 = biasS[colb], bi1 = biasS[colb + 1];
            float v0 = (sc[nt][0] + bi0) * 0.125f;
            float v1 = (sc[nt][1] + bi1) * 0.125f;
            float v2 = (sc[nt][2] + bi0) * 0.125f;
            float v3 = (sc[nt][3] + bi1) * 0.125f;
            if (mt_) {
                const int tc = t0 + colb;
                if (tc     > S_LEN + srow0)     v0 = -1e30f;
                if (tc + 1 > S_LEN + srow0)     v1 = -1e30f;
                if (tc     > S_LEN + srow0 + 8) v2 = -1e30f;
                if (tc + 1 > S_LEN + srow0 + 8) v3 = -1e30f;
            }
            sc[nt][0] = v0; sc[nt][1] = v1; sc[nt][2] = v2; sc[nt][3] = v3;
            tmax0 = fmaxf(tmax0, fmaxf(v0, v1));
            tmax1 = fmaxf(tmax1, fmaxf(v2, v3));
        }
        tmax0 = fmaxf(tmax0, __shfl_xor_sync(0xffffffffu, tmax0, 1));
        tmax0 = fmaxf(tmax0, __shfl_xor_sync(0xffffffffu, tmax0, 2));
        tmax1 = fmaxf(tmax1, __shfl_xor_sync(0xffffffffu, tmax1, 1));
        tmax1 = fmaxf(tmax1, __shfl_xor_sync(0xffffffffu, tmax1, 2));

        const float mnew0 = fmaxf(m0, tmax0);
        const float mnew1 = fmaxf(m1, tmax1);
        const float c0 = __expf(m0 - mnew0);
        const float c1 = __expf(m1 - mnew1);
        m0 = mnew0; m1 = mnew1;
        l0 *= c0; l1 *= c1;

        float ps0 = 0.f, ps1 = 0.f;
#pragma unroll
        for (int nt = 0; nt < 8; nt++) {
            float p0 = __expf(sc[nt][0] - mnew0);
            float p1 = __expf(sc[nt][1] - mnew0);
            float p2 = __expf(sc[nt][2] - mnew1);
            float p3 = __expf(sc[nt][3] - mnew1);
            ps0 += p0 + p1; ps1 += p2 + p3;
            O[nt][0] *= c0; O[nt][1] *= c0;
            O[nt][2] *= c1; O[nt][3] *= c1;
            uint2 s0, s1;
            s0.x = f2tf32(p0); s0.y = f2tf32(p1);
            s1.x = f2tf32(p2); s1.y = f2tf32(p3);
            *(uint2*)&Ps[sw64(mw + q,     nt * 8 + 2 * r)] = s0;
            *(uint2*)&Ps[sw64(mw + q + 8, nt * 8 + 2 * r)] = s1;
        }
        l0 += ps0; l1 += ps1;
        __syncwarp();

#pragma unroll
        for (int kk = 0; kk < 64; kk += 8) {
            uint32_t a[4];
            a[0] = Ps[sw64(mw + q,     kk + r)];
            a[1] = Ps[sw64(mw + q + 8, kk + r)];
            a[2] = Ps[sw64(mw + q,     kk + r + 4)];
            a[3] = Ps[sw64(mw + q + 8, kk + r + 4)];
#pragma unroll
            for (int nt = 0; nt < 8; nt++) {
                uint32_t bb[2];
                bb[0] = Vs[sw64(kk + r,     nt * 8 + q)];
                bb[1] = Vs[sw64(kk + r + 4, nt * 8 + q)];
                mma_tf32(O[nt], a, bb);
            }
        }
        __syncthreads();

        if (tt + 1 < ntiles) {
            issueKV(t0 + 64);
            cp_commit();
            cp_wait<0>();
            __syncthreads();
        }
    }

    // finalize: normalize + store PERMUTED + ROUNDED (consumed by wc GEMM)
    l0 += __shfl_xor_sync(0xffffffffu, l0, 1);
    l0 += __shfl_xor_sync(0xffffffffu, l0, 2);
    l1 += __shfl_xor_sync(0xffffffffu, l1, 1);
    l1 += __shfl_xor_sync(0xffffffffu, l1, 2);
    const float inv0 = 1.f / l0, inv1 = 1.f / l1;

#pragma unroll
    for (int nt = 0; nt < 8; nt++) {
        const int col = h * HDIM + nt * 8 + 2 * r;
        const int p0 = perm8(col), p1 = perm8(col + 1);
        const int row0 = qb * 128 + mw + q;
        float* o0 = out + ((size_t)(row0 * BATCH + b)) * DMODEL;
        float* o1 = out + ((size_t)((row0 + 8) * BATCH + b)) * DMODEL;
        o0[p0] = roundtf(O[nt][0] * inv0);
        o0[p1] = roundtf(O[nt][1] * inv0);
        o1[p0] = roundtf(O[nt][2] * inv1);
        o1[p1] = roundtf(O[nt][3] * inv1);
    }
}

// ---------------- LayerNorm(a + res) * g + b --------------------------------
// out: normal fp32; out_p (optional): tf32-rounded + permuted (GEMM input)
__global__ void __launch_bounds__(256)
ln_kernel(const float* __restrict__ a, const float* __restrict__ res,
          const float* __restrict__ g, const float* __restrict__ bta,
          float* __restrict__ out, float* __restrict__ out_p)
{
    const int row = blockIdx.x;
    const int tid = threadIdx.x;
    const int lane = tid & 31, wrp = tid >> 5;
    __shared__ float red[8];
    __shared__ float bc;

    float vals[4];
    float s = 0.f;
    const float* ar = a + (size_t)row * DMODEL;
    const float* rr = res + (size_t)row * DMODEL;
#pragma unroll
    for (int i = 0; i < 4; i++) {
        int d = tid + i * 256;
        vals[i] = ar[d] + rr[d];
        s += vals[i];
    }
#pragma unroll
    for (int off = 16; off; off >>= 1) s += __shfl_xor_sync(0xffffffffu, s, off);
    if (lane == 0) red[wrp] = s;
    __syncthreads();
    if (tid == 0) {
        float t = 0.f;
#pragma unroll
        for (int w = 0; w < 8; w++) t += red[w];
        bc = t * (1.f / DMODEL);
    }
    __syncthreads();
    const float mu = bc;

    float vs = 0.f;
#pragma unroll
    for (int i = 0; i < 4; i++) {
        float dd = vals[i] - mu;
        vs += dd * dd;
    }
#pragma unroll
    for (int off = 16; off; off >>= 1) vs += __shfl_xor_sync(0xffffffffu, vs, off);
    __syncthreads();
    if (lane == 0) red[wrp] = vs;
    __syncthreads();
    if (tid == 0) {
        float t = 0.f;
#pragma unroll
        for (int w = 0; w < 8; w++) t += red[w];
        bc = rsqrtf(t * (1.f / DMODEL) + 1e-5f);
    }
    __syncthreads();
    const float rstd = bc;

    float* orow = out + (size_t)row * DMODEL;
    float* prow = out_p ? out_p + (size_t)row * DMODEL : nullptr;
#pragma unroll
    for (int i = 0; i < 4; i++) {
        int d = tid + i * 256;
        float vv = (vals[i] - mu) * rstd * g[d] + bta[d];
        orow[d] = vv;
        if (prow) prow[perm8(d)] = roundtf(vv);
    }
}

// ---------------- launcher ---------------------------------------------------
extern "C" void kernel_launch(void* const* d_in, const int* in_sizes, int n_in,
                              void* d_out, int out_size)
{
    const float* x      = (const float*)d_in[0];
    const float* p      = (const float*)d_in[1];
    /* mask d_in[2] is analytic: unused */
    const float* memory = (const float*)d_in[3];
    const float* u_bias = (const float*)d_in[4];
    const float* v_bias = (const float*)d_in[5];
    const float* wq  = (const float*)d_in[6];
    const float* wke = (const float*)d_in[7];
    const float* wkr = (const float*)d_in[8];
    const float* wv  = (const float*)d_in[9];
    const float* wc  = (const float*)d_in[10];
    const float* w1  = (const float*)d_in[11];
    const float* w1b = (const float*)d_in[12];
    const float* w2  = (const float*)d_in[13];
    const float* w2b = (const float*)d_in[14];
    const float* ln1g = (const float*)d_in[15];
    const float* ln1b = (const float*)d_in[16];
    const float* ln2g = (const float*)d_in[17];
    const float* ln2b = (const float*)d_in[18];
    float* out = (float*)d_out;

    float *q, *ke, *kr, *v, *tbuf, *ubuf, *h1p;
    float *xp, *memp, *pp, *wqp, *wkep, *wkrp, *wvp, *wcp, *w1p, *w2p, *avp, *up;
    uint32_t *kk2, *v2;
    float *bias2;
    cudaGetSymbolAddress((void**)&q,    g_q);
    cudaGetSymbolAddress((void**)&ke,   g_ke);
    cudaGetSymbolAddress((void**)&kr,   g_kr);
    cudaGetSymbolAddress((void**)&v,    g_v);
    cudaGetSymbolAddress((void**)&tbuf, g_t);
    cudaGetSymbolAddress((void**)&ubuf, g_u);
    cudaGetSymbolAddress((void**)&h1p,  g_h1p);
    cudaGetSymbolAddress((void**)&xp,   g_xp);
    cudaGetSymbolAddress((void**)&memp, g_memp);
    cudaGetSymbolAddress((void**)&pp,   g_pp);
    cudaGetSymbolAddress((void**)&wqp,  g_wqp);
    cudaGetSymbolAddress((void**)&wkep, g_wkep);
    cudaGetSymbolAddress((void**)&wkrp, g_wkrp);
    cudaGetSymbolAddress((void**)&wvp,  g_wvp);
    cudaGetSymbolAddress((void**)&wcp,  g_wcp);
    cudaGetSymbolAddress((void**)&w1p,  g_w1p);
    cudaGetSymbolAddress((void**)&w2p,  g_w2p);
    cudaGetSymbolAddress((void**)&avp,  g_avp);
    cudaGetSymbolAddress((void**)&up,   g_up_);
    cudaGetSymbolAddress((void**)&kk2,  g_kk2);
    cudaGetSymbolAddress((void**)&v2,   g_v2);
    cudaGetSymbolAddress((void**)&bias2, g_bias);

    cudaFuncSetAttribute(tf32gemm3_kernel,
                         cudaFuncAttributeMaxDynamicSharedMemorySize, G2_SMEM);
    cudaFuncSetAttribute(flash_tc_kernel,
                         cudaFuncAttributeMaxDynamicSharedMemorySize, FLASH_SMEM);

    const dim3 blk256(256);
    const size_t half = (size_t)ROWS_X * DMODEL;

    // ---- merged repack: one launch for all tensors --------------------------
    {
        RepackSegs rs{};
        int acc = 0, i = 0;
        auto add = [&](const float* s, float* d, int n8) {
            rs.src[i] = s; rs.dst[i] = d; acc += n8; rs.end8[i] = acc; i++;
        };
        add(x,      xp,   ROWS_X * DMODEL / 8);
        add(memory, memp, ROWS_X * DMODEL / 8);
        add(p,      pp,   ROWS_T * DMODEL / 8);
        add(wq,  wqp,  DMODEL * DMODEL / 8);
        add(wke, wkep, DMODEL * DMODEL / 8);
        add(wkr, wkrp, DMODEL * DMODEL / 8);
        add(wv,  wvp,  DMODEL * DMODEL / 8);
        add(wc,  wcp,  DMODEL * DMODEL / 8);
        add(w1,  w1p,  FFDIM * DMODEL / 8);
        add(w2,  w2p,  FFDIM * DMODEL / 8);
        rs.nseg = i;
        repack_all_kernel<<<(acc + 255) / 256, blk256>>>(rs, acc);
    }

    // ---- all 6 projections in ONE launch (z = 0..6) -------------------------
    {
        GemmPtrs gp{};
        gp.A[0] = xp;   gp.W[0] = wqp;  gp.C[0] = q;
        gp.A[1] = xp;   gp.W[1] = wkep; gp.C[1] = ke + half;
        gp.A[2] = xp;   gp.W[2] = wvp;  gp.C[2] = v + half;
        gp.A[3] = memp; gp.W[3] = wkep; gp.C[3] = ke;
        gp.A[4] = memp; gp.W[4] = wvp;  gp.C[4] = v;
        gp.A[5] = pp;            gp.W[5] = wkrp; gp.C[5] = kr;
        gp.A[6] = pp + half;     gp.W[6] = wkrp; gp.C[6] = kr + half;
        tf32gemm3_kernel<<<dim3(8, 16, 7), blk256, G2_SMEM>>>(
            gp, nullptr, ROWS_X, DMODEL, DMODEL, 0);
    }

    // prep: fuse KK, bias, repack V
    prep_kernel<<<ROWS_T, blk256>>>(ke, kr, v, u_bias, v_bias, kk2, v2, bias2);

    // tensor-core flash attention (writes avp permuted+rounded)
    flash_tc_kernel<<<dim3(8, HEADS, BATCH), blk256, FLASH_SMEM>>>(
        q, kk2, v2, bias2, avp);

    // output proj + LN1
    {
        GemmPtrs gp{};
        gp.A[0] = avp; gp.W[0] = wcp; gp.C[0] = tbuf;
        tf32gemm3_kernel<<<dim3(8, 16, 1), blk256, G2_SMEM>>>(
            gp, nullptr, ROWS_X, DMODEL, DMODEL, 0);
    }
    ln_kernel<<<ROWS_X, blk256>>>(tbuf, x, ln1g, ln1b, ubuf, up);

    // FFN + LN2
    {
        GemmPtrs gp{};
        gp.A[0] = up; gp.W[0] = w1p; gp.C[0] = h1p;
        tf32gemm3_kernel<<<dim3(32, 16, 1), blk256, G2_SMEM>>>(
            gp, w1b, ROWS_X, FFDIM, DMODEL, 3);   // relu + permute-out
    }
    {
        GemmPtrs gp{};
        gp.A[0] = h1p; gp.W[0] = w2p; gp.C[0] = tbuf;
        tf32gemm3_kernel<<<dim3(8, 16, 1), blk256, G2_SMEM>>>(
            gp, w2b, ROWS_X, DMODEL, FFDIM, 0);
    }
    ln_kernel<<<ROWS_X, blk256>>>(tbuf, ubuf, ln2g, ln2b, out, nullptr);
}

// round 7
// speedup vs baseline: 1.1689x; 1.1689x over previous
#include <cuda_runtime.h>
#include <cuda_bf16.h>
#include <math.h>
#include <stdint.h>

// Problem constants
#define S_LEN 1024
#define BATCH 2
#define DMODEL 1024
#define HEADS 16
#define HDIM 64
#define TLEN 2048
#define FFDIM 4096
#define ROWS_X (S_LEN * DMODEL >= 0 ? S_LEN * BATCH : 0)   // 2048
#define ROWS_T (TLEN * BATCH)      // 4096

// ---------------- scratch buffers (device globals) ---------------------------
__device__ float g_q [ROWS_X * DMODEL];
__device__ float g_ke[ROWS_T * DMODEL];
__device__ float g_kr[ROWS_T * DMODEL];
__device__ float g_v [ROWS_T * DMODEL];
__device__ float g_av[ROWS_X * DMODEL];
__device__ float g_t [ROWS_X * DMODEL];
__device__ float g_u [ROWS_X * DMODEL];
__device__ float g_h1[ROWS_X * FFDIM];
// flash-prep outputs
__device__ uint32_t g_kk2 [BATCH * HEADS * TLEN * HDIM];
__device__ uint32_t g_v2  [BATCH * HEADS * TLEN * HDIM];
__device__ float    g_bias[BATCH * HEADS * TLEN];

// ---------------- common PTX helpers ----------------------------------------
__device__ __forceinline__ uint32_t f2tf32(float f) {
    uint32_t r;
    asm("cvt.rna.tf32.f32 %0, %1;" : "=r"(r) : "f"(f));
    return r;
}
__device__ __forceinline__ void cp_async16(uint32_t saddr, const void* gptr) {
    asm volatile("cp.async.cg.shared.global [%0], [%1], 16;\n"
                 :: "r"(saddr), "l"(gptr));
}
__device__ __forceinline__ void cp_commit() {
    asm volatile("cp.async.commit_group;\n");
}
template <int N>
__device__ __forceinline__ void cp_wait() {
    asm volatile("cp.async.wait_group %0;\n" :: "n"(N));
}
__device__ __forceinline__ void mma_tf32(float* d, const uint32_t* a, const uint32_t* b) {
    asm volatile(
        "mma.sync.aligned.m16n8k8.row.col.f32.tf32.tf32.f32 "
        "{%0,%1,%2,%3}, {%4,%5,%6,%7}, {%8,%9}, {%0,%1,%2,%3};\n"
        : "+f"(d[0]), "+f"(d[1]), "+f"(d[2]), "+f"(d[3])
        : "r"(a[0]), "r"(a[1]), "r"(a[2]), "r"(a[3]), "r"(b[0]), "r"(b[1]));
}
// swizzled index for element (row, c) in a [rows]x32 float tile
__device__ __forceinline__ int sw_idx(int row, int c) {
    return (row << 5) + ((((c >> 2) ^ row) & 7) << 2) + (c & 3);
}

// ---------------- tf32 tensor-core GEMM (R4 v1, 7-slot table) ----------------
// C[M,N] = A[M,Kd] * W[N,Kd]^T (+bias)(+relu), blockIdx.z selects (A,W,C).
// BM=BN=128, BK=32, 256 thr (8 warps, 2m x 4n), warp tile 64x32, mma m16n8k8.
// Double-buffered cp.async, XOR-swizzled smem, in-loop cvt, fp32 accum.
struct GemmPtrs {
    const float* A[7];
    const float* W[7];
    float*       C[7];
};

#define GEMM_SMEM (2 * 2 * 128 * 32 * 4)   // 65536 bytes

__global__ void __launch_bounds__(256)
tf32gemm_kernel(GemmPtrs ptrs, const float* __restrict__ bias,
                int M, int N, int Kd, int act)
{
    extern __shared__ float smem[];

    const float* A = ptrs.A[blockIdx.z];
    const float* W = ptrs.W[blockIdx.z];
    float*       C = ptrs.C[blockIdx.z];

    const int tid = threadIdx.x;
    const int lane = tid & 31, wrp = tid >> 5;
    const int wm = wrp & 1;
    const int wn = wrp >> 1;
    const int q = lane >> 2, r = lane & 3;
    const int m0 = blockIdx.y * 128;
    const int n0 = blockIdx.x * 128;

    const int lrow = tid >> 3;
    const int lb   = tid & 7;

    float acc[4][4][4];
#pragma unroll
    for (int i = 0; i < 4; i++)
#pragma unroll
        for (int j = 0; j < 4; j++)
#pragma unroll
            for (int e = 0; e < 4; e++) acc[i][j][e] = 0.f;

    uint32_t sbase = (uint32_t)__cvta_generic_to_shared(smem);

    auto issue = [&](int buf, int k0) {
        uint32_t so = sbase + (uint32_t)buf * 8192u * 4u;
#pragma unroll
        for (int i = 0; i < 4; i++) {
            int row = lrow + i * 32;
            int sidx = (row << 5) + (((lb ^ (row & 7))) << 2);
            cp_async16(so + sidx * 4, A + (size_t)(m0 + row) * Kd + k0 + lb * 4);
            cp_async16(so + (4096 + sidx) * 4, W + (size_t)(n0 + row) * Kd + k0 + lb * 4);
        }
    };

    const int KT = Kd >> 5;
    issue(0, 0);
    cp_commit();

    for (int kt = 0; kt < KT; kt++) {
        const int cur = kt & 1;
        if (kt + 1 < KT) {
            issue(cur ^ 1, (kt + 1) << 5);
            cp_commit();
            cp_wait<1>();
        } else {
            cp_wait<0>();
        }
        __syncthreads();

        const float* As = smem + (size_t)cur * 8192;
        const float* Ws = As + 4096;

#pragma unroll
        for (int kk = 0; kk < 32; kk += 8) {
            uint32_t afr[4][4];
#pragma unroll
            for (int mt = 0; mt < 4; mt++) {
                int mr = wm * 64 + mt * 16 + q;
                afr[mt][0] = f2tf32(As[sw_idx(mr,     kk + r)]);
                afr[mt][1] = f2tf32(As[sw_idx(mr + 8, kk + r)]);
                afr[mt][2] = f2tf32(As[sw_idx(mr,     kk + 4 + r)]);
                afr[mt][3] = f2tf32(As[sw_idx(mr + 8, kk + 4 + r)]);
            }
            uint32_t bfr[4][2];
#pragma unroll
            for (int nt = 0; nt < 4; nt++) {
                int nr = wn * 32 + nt * 8 + q;
                bfr[nt][0] = f2tf32(Ws[sw_idx(nr, kk + r)]);
                bfr[nt][1] = f2tf32(Ws[sw_idx(nr, kk + 4 + r)]);
            }
#pragma unroll
            for (int mt = 0; mt < 4; mt++)
#pragma unroll
                for (int nt = 0; nt < 4; nt++)
                    mma_tf32(acc[mt][nt], afr[mt], bfr[nt]);
        }
        __syncthreads();
    }

#pragma unroll
    for (int mt = 0; mt < 4; mt++) {
        int row0 = m0 + wm * 64 + mt * 16 + q;
#pragma unroll
        for (int nt = 0; nt < 4; nt++) {
            int col = n0 + wn * 32 + nt * 8 + r * 2;
            float b0 = bias ? bias[col]     : 0.f;
            float b1 = bias ? bias[col + 1] : 0.f;
            float v0 = acc[mt][nt][0] + b0, v1 = acc[mt][nt][1] + b1;
            float v2 = acc[mt][nt][2] + b0, v3 = acc[mt][nt][3] + b1;
            if (act == 1) {
                v0 = fmaxf(v0, 0.f); v1 = fmaxf(v1, 0.f);
                v2 = fmaxf(v2, 0.f); v3 = fmaxf(v3, 0.f);
            }
            *(float2*)(C + (size_t)row0 * N + col)       = make_float2(v0, v1);
            *(float2*)(C + (size_t)(row0 + 8) * N + col) = make_float2(v2, v3);
        }
    }
}

// ---------------- prep: KK = ke+kr (tf32), bias = u.ke + v.kr, repack V -----
__global__ void __launch_bounds__(256)
prep_kernel(const float* __restrict__ ke, const float* __restrict__ kr,
            const float* __restrict__ v,
            const float* __restrict__ ub, const float* __restrict__ vb,
            uint32_t* __restrict__ kk2, uint32_t* __restrict__ v2,
            float* __restrict__ biasO)
{
    const int row = blockIdx.x;          // = t*BATCH + b
    const int t = row / BATCH, b = row % BATCH;
    const int tid = threadIdx.x;
    const int h = tid >> 4, l16 = tid & 15, d0 = l16 * 4;

    const size_t src = (size_t)row * DMODEL + h * HDIM + d0;
    float4 kev = *(const float4*)(ke + src);
    float4 krv = *(const float4*)(kr + src);
    float4 vv  = *(const float4*)(v  + src);

    const size_t dst = ((size_t)(b * HEADS + h) * TLEN + t) * HDIM + d0;
    uint4 kko, vvo;
    kko.x = f2tf32(kev.x + krv.x); kko.y = f2tf32(kev.y + krv.y);
    kko.z = f2tf32(kev.z + krv.z); kko.w = f2tf32(kev.w + krv.w);
    vvo.x = f2tf32(vv.x); vvo.y = f2tf32(vv.y);
    vvo.z = f2tf32(vv.z); vvo.w = f2tf32(vv.w);
    *(uint4*)(kk2 + dst) = kko;
    *(uint4*)(v2  + dst) = vvo;

    float4 u4 = *(const float4*)(ub + h * HDIM + d0);
    float4 w4 = *(const float4*)(vb + h * HDIM + d0);
    float bsum = u4.x * kev.x + u4.y * kev.y + u4.z * kev.z + u4.w * kev.w
               + w4.x * krv.x + w4.y * krv.y + w4.z * krv.z + w4.w * krv.w;
#pragma unroll
    for (int off = 8; off; off >>= 1)
        bsum += __shfl_xor_sync(0xffffffffu, bsum, off, 16);
    if (l16 == 0) biasO[(size_t)(b * HEADS + h) * TLEN + t] = bsum;
}

// ---------------- tensor-core flash attention (pipelined KV) -----------------
// Query tile 128, key tile 64. 8 warps x 16 query rows.
// KK(t+1) prefetch overlaps softmax+PV; V(t+1) prefetch overlaps next QK.
// smem: Qs 128x64 | Ps 128x64 | KKs 64x64 | Vs 64x64 | bias 2x64
#define FQS  0
#define FPS  8192
#define FKK  16384
#define FVS  20480
#define FBI  24576
#define FLASH_SMEM ((24576 + 128) * 4)

__device__ __forceinline__ int sw64(int row, int c) {
    return (row << 6) + (((c >> 2) ^ (row & 7)) << 2) + (c & 3);
}

__global__ void __launch_bounds__(256, 2)
flash_tc_kernel(const float* __restrict__ qg,
                const uint32_t* __restrict__ kk2,
                const uint32_t* __restrict__ v2,
                const float* __restrict__ biasG,
                float* __restrict__ out)
{
    extern __shared__ uint32_t fsm[];
    uint32_t* Qs  = fsm + FQS;
    uint32_t* Ps  = fsm + FPS;
    uint32_t* KKs = fsm + FKK;
    uint32_t* Vs  = fsm + FVS;
    float*    biasS = (float*)(fsm + FBI);   // [2][64]

    const int qb = blockIdx.x, h = blockIdx.y, b = blockIdx.z;
    const int tid = threadIdx.x;
    const int lane = tid & 31, wid = tid >> 5;
    const int q = lane >> 2, r = lane & 3;
    const int mw = wid * 16;

    const uint32_t sbase = (uint32_t)__cvta_generic_to_shared(fsm);
    const size_t   bh    = (size_t)(b * HEADS + h) * TLEN;
    const uint32_t* kkbh = kk2 + bh * HDIM;
    const uint32_t* vbh  = v2  + bh * HDIM;
    const float*    bibh = biasG + bh;

    auto issueKK = [&](int t0, int pb) {
#pragma unroll
        for (int it = 0; it < 4; it++) {
            int idx = tid + it * 256;
            int row = idx >> 4, g4 = (idx & 15) * 4;
            cp_async16(sbase + (uint32_t)(FKK + sw64(row, g4)) * 4,
                       kkbh + (size_t)(t0 + row) * HDIM + g4);
        }
        if (tid < 16)
            cp_async16(sbase + (uint32_t)(FBI + pb * 64 + tid * 4) * 4,
                       bibh + t0 + tid * 4);
    };
    auto issueV = [&](int t0) {
#pragma unroll
        for (int it = 0; it < 4; it++) {
            int idx = tid + it * 256;
            int row = idx >> 4, g4 = (idx & 15) * 4;
            cp_async16(sbase + (uint32_t)(FVS + sw64(row, g4)) * 4,
                       vbh + (size_t)(t0 + row) * HDIM + g4);
        }
    };

    // prologue: KK0 (group), V0 (group), Q tile (plain stores)
    issueKK(0, 0);
    cp_commit();
    issueV(0);
    cp_commit();
    // in flight: [KK0, V0]

#pragma unroll
    for (int it = 0; it < 8; it++) {
        int idx = tid + it * 256;
        int row = idx >> 4, g4 = (idx & 15) * 4;
        const float4 qv = *(const float4*)(qg +
            ((size_t)((qb * 128 + row) * BATCH + b)) * DMODEL + h * HDIM + g4);
        uint4 qo;
        qo.x = f2tf32(qv.x); qo.y = f2tf32(qv.y);
        qo.z = f2tf32(qv.z); qo.w = f2tf32(qv.w);
        *(uint4*)(Qs + sw64(row, g4)) = qo;
    }

    float m0 = -1e30f, m1 = -1e30f, l0 = 0.f, l1 = 0.f;
    float O[8][4];
#pragma unroll
    for (int nt = 0; nt < 8; nt++)
#pragma unroll
        for (int e = 0; e < 4; e++) O[nt][e] = 0.f;

    const int ntiles = 18 + 2 * qb;
    const int srow0 = qb * 128 + mw + q;

    for (int tt = 0; tt < ntiles; tt++) {
        const int t0 = tt * 64;
        const int pb = tt & 1;
        const bool more = (tt + 1 < ntiles);

        cp_wait<1>();          // KK(tt) [+bias] complete (V(tt) may be pending)
        __syncthreads();       // visibility of KK to all warps (+Q on tt=0)

        // ---- scores: S = Q @ KK^T ------------------------------------------
        float sc[8][4];
#pragma unroll
        for (int nt = 0; nt < 8; nt++)
#pragma unroll
            for (int e = 0; e < 4; e++) sc[nt][e] = 0.f;

#pragma unroll
        for (int kk = 0; kk < 64; kk += 8) {
            uint32_t a[4];
            a[0] = Qs[sw64(mw + q,     kk + r)];
            a[1] = Qs[sw64(mw + q + 8, kk + r)];
            a[2] = Qs[sw64(mw + q,     kk + r + 4)];
            a[3] = Qs[sw64(mw + q + 8, kk + r + 4)];
#pragma unroll
            for (int nt = 0; nt < 8; nt++) {
                uint32_t bb[2];
                bb[0] = KKs[sw64(nt * 8 + q, kk + r)];
                bb[1] = KKs[sw64(nt * 8 + q, kk + r + 4)];
                mma_tf32(sc[nt], a, bb);
            }
        }
        __syncthreads();       // all warps done reading KKs

        if (more) { issueKK(t0 + 64, pb ^ 1); cp_commit(); }
        // in flight: [V(tt), KK(tt+1)?]

        // ---- bias + scale + causal mask + online softmax --------------------
        const float* bS = biasS + pb * 64;
        const bool mt_ = (tt >= 16 + 2 * qb);
        float tmax0 = -1e30f, tmax1 = -1e30f;
#pragma unroll
        for (int nt = 0; nt < 8; nt++) {
            const int colb = nt * 8 + 2 * r;
            const float bi0 = bS[colb], bi1 = bS[colb + 1];
            float v0 = (sc[nt][0] + bi0) * 0.125f;
            float v1 = (sc[nt][1] + bi1) * 0.125f;
            float v2 = (sc[nt][2] + bi0) * 0.125f;
            float v3 = (sc[nt][3] + bi1) * 0.125f;
            if (mt_) {
                const int tc = t0 + colb;
                if (tc     > S_LEN + srow0)     v0 = -1e30f;
                if (tc + 1 > S_LEN + srow0)     v1 = -1e30f;
                if (tc     > S_LEN + srow0 + 8) v2 = -1e30f;
                if (tc + 1 > S_LEN + srow0 + 8) v3 = -1e30f;
            }
            sc[nt][0] = v0; sc[nt][1] = v1; sc[nt][2] = v2; sc[nt][3] = v3;
            tmax0 = fmaxf(tmax0, fmaxf(v0, v1));
            tmax1 = fmaxf(tmax1, fmaxf(v2, v3));
        }
        tmax0 = fmaxf(tmax0, __shfl_xor_sync(0xffffffffu, tmax0, 1));
        tmax0 = fmaxf(tmax0, __shfl_xor_sync(0xffffffffu, tmax0, 2));
        tmax1 = fmaxf(tmax1, __shfl_xor_sync(0xffffffffu, tmax1, 1));
        tmax1 = fmaxf(tmax1, __shfl_xor_sync(0xffffffffu, tmax1, 2));

        const float mnew0 = fmaxf(m0, tmax0);
        const float mnew1 = fmaxf(m1, tmax1);
        const float c0 = __expf(m0 - mnew0);
        const float c1 = __expf(m1 - mnew1);
        m0 = mnew0; m1 = mnew1;
        l0 *= c0; l1 *= c1;

        float ps0 = 0.f, ps1 = 0.f;
#pragma unroll
        for (int nt = 0; nt < 8; nt++) {
            float p0 = __expf(sc[nt][0] - mnew0);
            float p1 = __expf(sc[nt][1] - mnew0);
            float p2 = __expf(sc[nt][2] - mnew1);
            float p3 = __expf(sc[nt][3] - mnew1);
            ps0 += p0 + p1; ps1 += p2 + p3;
            O[nt][0] *= c0; O[nt][1] *= c0;
            O[nt][2] *= c1; O[nt][3] *= c1;
            uint2 s0, s1;
            s0.x = f2tf32(p0); s0.y = f2tf32(p1);
            s1.x = f2tf32(p2); s1.y = f2tf32(p3);
            *(uint2*)&Ps[sw64(mw + q,     nt * 8 + 2 * r)] = s0;
            *(uint2*)&Ps[sw64(mw + q + 8, nt * 8 + 2 * r)] = s1;
        }
        l0 += ps0; l1 += ps1;
        __syncwarp();

        // ---- ensure V(tt) landed, then O += P @ V ---------------------------
        if (more) { cp_wait<1>(); } else { cp_wait<0>(); }
        __syncthreads();       // visibility of Vs to all warps

#pragma unroll
        for (int kk = 0; kk < 64; kk += 8) {
            uint32_t a[4];
            a[0] = Ps[sw64(mw + q,     kk + r)];
            a[1] = Ps[sw64(mw + q + 8, kk + r)];
            a[2] = Ps[sw64(mw + q,     kk + r + 4)];
            a[3] = Ps[sw64(mw + q + 8, kk + r + 4)];
#pragma unroll
            for (int nt = 0; nt < 8; nt++) {
                uint32_t bb[2];
                bb[0] = Vs[sw64(kk + r,     nt * 8 + q)];
                bb[1] = Vs[sw64(kk + r + 4, nt * 8 + q)];
                mma_tf32(O[nt], a, bb);
            }
        }
        __syncthreads();       // all warps done reading Vs

        if (more) { issueV(t0 + 64); cp_commit(); }
        // in flight: [KK(tt+1), V(tt+1)]
    }

    // ---- finalize: reduce l over quad, normalize, store ---------------------
    l0 += __shfl_xor_sync(0xffffffffu, l0, 1);
    l0 += __shfl_xor_sync(0xffffffffu, l0, 2);
    l1 += __shfl_xor_sync(0xffffffffu, l1, 1);
    l1 += __shfl_xor_sync(0xffffffffu, l1, 2);
    const float inv0 = 1.f / l0, inv1 = 1.f / l1;

#pragma unroll
    for (int nt = 0; nt < 8; nt++) {
        const int col = nt * 8 + 2 * r;
        const int row0 = qb * 128 + mw + q;
        *(float2*)(out + ((size_t)(row0 * BATCH + b)) * DMODEL + h * HDIM + col)
            = make_float2(O[nt][0] * inv0, O[nt][1] * inv0);
        *(float2*)(out + ((size_t)((row0 + 8) * BATCH + b)) * DMODEL + h * HDIM + col)
            = make_float2(O[nt][2] * inv1, O[nt][3] * inv1);
    }
}

// ---------------- LayerNorm(a + res) * g + b --------------------------------
__global__ void __launch_bounds__(256)
ln_kernel(const float* __restrict__ a, const float* __restrict__ res,
          const float* __restrict__ g, const float* __restrict__ bta,
          float* __restrict__ out)
{
    const int row = blockIdx.x;
    const int tid = threadIdx.x;
    const int lane = tid & 31, wrp = tid >> 5;
    __shared__ float red[8];
    __shared__ float bc;

    float vals[4];
    float s = 0.f;
    const float* ar = a + (size_t)row * DMODEL;
    const float* rr = res + (size_t)row * DMODEL;
#pragma unroll
    for (int i = 0; i < 4; i++) {
        int d = tid + i * 256;
        vals[i] = ar[d] + rr[d];
        s += vals[i];
    }
#pragma unroll
    for (int off = 16; off; off >>= 1) s += __shfl_xor_sync(0xffffffffu, s, off);
    if (lane == 0) red[wrp] = s;
    __syncthreads();
    if (tid == 0) {
        float t = 0.f;
#pragma unroll
        for (int w = 0; w < 8; w++) t += red[w];
        bc = t * (1.f / DMODEL);
    }
    __syncthreads();
    const float mu = bc;

    float vs = 0.f;
#pragma unroll
    for (int i = 0; i < 4; i++) {
        float dd = vals[i] - mu;
        vs += dd * dd;
    }
#pragma unroll
    for (int off = 16; off; off >>= 1) vs += __shfl_xor_sync(0xffffffffu, vs, off);
    __syncthreads();
    if (lane == 0) red[wrp] = vs;
    __syncthreads();
    if (tid == 0) {
        float t = 0.f;
#pragma unroll
        for (int w = 0; w < 8; w++) t += red[w];
        bc = rsqrtf(t * (1.f / DMODEL) + 1e-5f);
    }
    __syncthreads();
    const float rstd = bc;

    float* orow = out + (size_t)row * DMODEL;
#pragma unroll
    for (int i = 0; i < 4; i++) {
        int d = tid + i * 256;
        orow[d] = (vals[i] - mu) * rstd * g[d] + bta[d];
    }
}

// ---------------- launcher ---------------------------------------------------
extern "C" void kernel_launch(void* const* d_in, const int* in_sizes, int n_in,
                              void* d_out, int out_size)
{
    const float* x      = (const float*)d_in[0];
    const float* p      = (const float*)d_in[1];
    /* mask d_in[2] is analytic: unused */
    const float* memory = (const float*)d_in[3];
    const float* u_bias = (const float*)d_in[4];
    const float* v_bias = (const float*)d_in[5];
    const float* wq  = (const float*)d_in[6];
    const float* wke = (const float*)d_in[7];
    const float* wkr = (const float*)d_in[8];
    const float* wv  = (const float*)d_in[9];
    const float* wc  = (const float*)d_in[10];
    const float* w1  = (const float*)d_in[11];
    const float* w1b = (const float*)d_in[12];
    const float* w2  = (const float*)d_in[13];
    const float* w2b = (const float*)d_in[14];
    const float* ln1g = (const float*)d_in[15];
    const float* ln1b = (const float*)d_in[16];
    const float* ln2g = (const float*)d_in[17];
    const float* ln2b = (const float*)d_in[18];
    float* out = (float*)d_out;

    float *q, *ke, *kr, *v, *av, *tbuf, *ubuf, *h1, *bias2;
    uint32_t *kk2, *v2;
    cudaGetSymbolAddress((void**)&q,    g_q);
    cudaGetSymbolAddress((void**)&ke,   g_ke);
    cudaGetSymbolAddress((void**)&kr,   g_kr);
    cudaGetSymbolAddress((void**)&v,    g_v);
    cudaGetSymbolAddress((void**)&av,   g_av);
    cudaGetSymbolAddress((void**)&tbuf, g_t);
    cudaGetSymbolAddress((void**)&ubuf, g_u);
    cudaGetSymbolAddress((void**)&h1,   g_h1);
    cudaGetSymbolAddress((void**)&kk2,  g_kk2);
    cudaGetSymbolAddress((void**)&v2,   g_v2);
    cudaGetSymbolAddress((void**)&bias2, g_bias);

    cudaFuncSetAttribute(tf32gemm_kernel,
                         cudaFuncAttributeMaxDynamicSharedMemorySize, GEMM_SMEM);
    cudaFuncSetAttribute(flash_tc_kernel,
                         cudaFuncAttributeMaxDynamicSharedMemorySize, FLASH_SMEM);

    const dim3 blk(256);
    const size_t half = (size_t)ROWS_X * DMODEL;

    // ---- all 6 projections in ONE launch (z = 0..6) -------------------------
    {
        GemmPtrs gp{};
        gp.A[0] = x;      gp.W[0] = wq;  gp.C[0] = q;
        gp.A[1] = x;      gp.W[1] = wke; gp.C[1] = ke + half;
        gp.A[2] = x;      gp.W[2] = wv;  gp.C[2] = v + half;
        gp.A[3] = memory; gp.W[3] = wke; gp.C[3] = ke;
        gp.A[4] = memory; gp.W[4] = wv;  gp.C[4] = v;
        gp.A[5] = p;            gp.W[5] = wkr; gp.C[5] = kr;
        gp.A[6] = p + half;     gp.W[6] = wkr; gp.C[6] = kr + half;
        tf32gemm_kernel<<<dim3(8, 16, 7), blk, GEMM_SMEM>>>(
            gp, nullptr, ROWS_X, DMODEL, DMODEL, 0);
    }

    // prep: fuse KK, bias, repack V
    prep_kernel<<<ROWS_T, blk>>>(ke, kr, v, u_bias, v_bias, kk2, v2, bias2);

    // tensor-core flash attention (pipelined KV prefetch)
    flash_tc_kernel<<<dim3(8, HEADS, BATCH), blk, FLASH_SMEM>>>(
        q, kk2, v2, bias2, av);

    // output proj + LN1
    {
        GemmPtrs gp{};
        gp.A[0] = av; gp.W[0] = wc; gp.C[0] = tbuf;
        tf32gemm_kernel<<<dim3(8, 16, 1), blk, GEMM_SMEM>>>(
            gp, nullptr, ROWS_X, DMODEL, DMODEL, 0);
    }
    ln_kernel<<<ROWS_X, blk>>>(tbuf, x, ln1g, ln1b, ubuf);

    // FFN + LN2
    {
        GemmPtrs gp{};
        gp.A[0] = ubuf; gp.W[0] = w1; gp.C[0] = h1;
        tf32gemm_kernel<<<dim3(32, 16, 1), blk, GEMM_SMEM>>>(
            gp, w1b, ROWS_X, FFDIM, DMODEL, 1);
    }
    {
        GemmPtrs gp{};
        gp.A[0] = h1; gp.W[0] = w2; gp.C[0] = tbuf;
        tf32gemm_kernel<<<dim3(8, 16, 1), blk, GEMM_SMEM>>>(
            gp, w2b, ROWS_X, DMODEL, FFDIM, 0);
    }
    ln_kernel<<<ROWS_X, blk>>>(tbuf, ubuf, ln2g, ln2b, out);
}

// round 8
// speedup vs baseline: 1.1804x; 1.0098x over previous
#include <cuda_runtime.h>
#include <cuda_bf16.h>
#include <math.h>
#include <stdint.h>

// Problem constants
#define S_LEN 1024
#define BATCH 2
#define DMODEL 1024
#define HEADS 16
#define HDIM 64
#define TLEN 2048
#define FFDIM 4096
#define ROWS_X (S_LEN * BATCH)     // 2048
#define ROWS_T (TLEN * BATCH)      // 4096

// ---------------- scratch buffers (device globals) ---------------------------
__device__ float g_q [ROWS_X * DMODEL];
__device__ float g_ke[ROWS_T * DMODEL];
__device__ float g_kr[ROWS_T * DMODEL];
__device__ float g_v [ROWS_T * DMODEL];
__device__ float g_av[ROWS_X * DMODEL];
__device__ float g_t [ROWS_X * DMODEL];
__device__ float g_t2[ROWS_X * DMODEL];      // second split-K partial
__device__ float g_u [ROWS_X * DMODEL];
__device__ float g_h1[ROWS_X * FFDIM];
// flash-prep outputs
__device__ uint32_t g_kk2 [BATCH * HEADS * TLEN * HDIM];
__device__ uint32_t g_v2  [BATCH * HEADS * TLEN * HDIM];
__device__ float    g_bias[BATCH * HEADS * TLEN];

// ---------------- common PTX helpers ----------------------------------------
__device__ __forceinline__ uint32_t f2tf32(float f) {
    uint32_t r;
    asm("cvt.rna.tf32.f32 %0, %1;" : "=r"(r) : "f"(f));
    return r;
}
__device__ __forceinline__ void cp_async16(uint32_t saddr, const void* gptr) {
    asm volatile("cp.async.cg.shared.global [%0], [%1], 16;\n"
                 :: "r"(saddr), "l"(gptr));
}
__device__ __forceinline__ void cp_commit() {
    asm volatile("cp.async.commit_group;\n");
}
template <int N>
__device__ __forceinline__ void cp_wait() {
    asm volatile("cp.async.wait_group %0;\n" :: "n"(N));
}
__device__ __forceinline__ void mma_tf32(float* d, const uint32_t* a, const uint32_t* b) {
    asm volatile(
        "mma.sync.aligned.m16n8k8.row.col.f32.tf32.tf32.f32 "
        "{%0,%1,%2,%3}, {%4,%5,%6,%7}, {%8,%9}, {%0,%1,%2,%3};\n"
        : "+f"(d[0]), "+f"(d[1]), "+f"(d[2]), "+f"(d[3])
        : "r"(a[0]), "r"(a[1]), "r"(a[2]), "r"(a[3]), "r"(b[0]), "r"(b[1]));
}
// swizzled index for element (row, c) in a [rows]x32 float tile
__device__ __forceinline__ int sw_idx(int row, int c) {
    return (row << 5) + ((((c >> 2) ^ row) & 7) << 2) + (c & 3);
}

// ---------------- tf32 tensor-core GEMM (z-table, split-K capable) ----------
// C[M,N] = A[M,Klen] * W[N,Klen]^T (+bias)(+relu); rows strided by Kstride.
// blockIdx.z selects (A, W, C, bias) — supports batched GEMMs AND split-K
// slices (pre-offset pointers, partials into separate C buffers).
// BM=BN=128, BK=32, 256 thr (8 warps, 2m x 4n), warp tile 64x32, mma m16n8k8.
struct GemmPtrs {
    const float* A[7];
    const float* W[7];
    float*       C[7];
    const float* bias[7];
};

#define GEMM_SMEM (2 * 2 * 128 * 32 * 4)   // 65536 bytes

__global__ void __launch_bounds__(256)
tf32gemm_kernel(GemmPtrs ptrs, int M, int N, int Klen, int Kstride, int act)
{
    extern __shared__ float smem[];

    const float* A    = ptrs.A[blockIdx.z];
    const float* W    = ptrs.W[blockIdx.z];
    float*       C    = ptrs.C[blockIdx.z];
    const float* bias = ptrs.bias[blockIdx.z];

    const int tid = threadIdx.x;
    const int lane = tid & 31, wrp = tid >> 5;
    const int wm = wrp & 1;
    const int wn = wrp >> 1;
    const int q = lane >> 2, r = lane & 3;
    const int m0 = blockIdx.y * 128;
    const int n0 = blockIdx.x * 128;

    const int lrow = tid >> 3;
    const int lb   = tid & 7;

    float acc[4][4][4];
#pragma unroll
    for (int i = 0; i < 4; i++)
#pragma unroll
        for (int j = 0; j < 4; j++)
#pragma unroll
            for (int e = 0; e < 4; e++) acc[i][j][e] = 0.f;

    uint32_t sbase = (uint32_t)__cvta_generic_to_shared(smem);

    auto issue = [&](int buf, int k0) {
        uint32_t so = sbase + (uint32_t)buf * 8192u * 4u;
#pragma unroll
        for (int i = 0; i < 4; i++) {
            int row = lrow + i * 32;
            int sidx = (row << 5) + (((lb ^ (row & 7))) << 2);
            cp_async16(so + sidx * 4, A + (size_t)(m0 + row) * Kstride + k0 + lb * 4);
            cp_async16(so + (4096 + sidx) * 4, W + (size_t)(n0 + row) * Kstride + k0 + lb * 4);
        }
    };

    const int KT = Klen >> 5;
    issue(0, 0);
    cp_commit();

    for (int kt = 0; kt < KT; kt++) {
        const int cur = kt & 1;
        if (kt + 1 < KT) {
            issue(cur ^ 1, (kt + 1) << 5);
            cp_commit();
            cp_wait<1>();
        } else {
            cp_wait<0>();
        }
        __syncthreads();

        const float* As = smem + (size_t)cur * 8192;
        const float* Ws = As + 4096;

#pragma unroll
        for (int kk = 0; kk < 32; kk += 8) {
            uint32_t afr[4][4];
#pragma unroll
            for (int mt = 0; mt < 4; mt++) {
                int mr = wm * 64 + mt * 16 + q;
                afr[mt][0] = f2tf32(As[sw_idx(mr,     kk + r)]);
                afr[mt][1] = f2tf32(As[sw_idx(mr + 8, kk + r)]);
                afr[mt][2] = f2tf32(As[sw_idx(mr,     kk + 4 + r)]);
                afr[mt][3] = f2tf32(As[sw_idx(mr + 8, kk + 4 + r)]);
            }
            uint32_t bfr[4][2];
#pragma unroll
            for (int nt = 0; nt < 4; nt++) {
                int nr = wn * 32 + nt * 8 + q;
                bfr[nt][0] = f2tf32(Ws[sw_idx(nr, kk + r)]);
                bfr[nt][1] = f2tf32(Ws[sw_idx(nr, kk + 4 + r)]);
            }
#pragma unroll
            for (int mt = 0; mt < 4; mt++)
#pragma unroll
                for (int nt = 0; nt < 4; nt++)
                    mma_tf32(acc[mt][nt], afr[mt], bfr[nt]);
        }
        __syncthreads();
    }

#pragma unroll
    for (int mt = 0; mt < 4; mt++) {
        int row0 = m0 + wm * 64 + mt * 16 + q;
#pragma unroll
        for (int nt = 0; nt < 4; nt++) {
            int col = n0 + wn * 32 + nt * 8 + r * 2;
            float b0 = bias ? bias[col]     : 0.f;
            float b1 = bias ? bias[col + 1] : 0.f;
            float v0 = acc[mt][nt][0] + b0, v1 = acc[mt][nt][1] + b1;
            float v2 = acc[mt][nt][2] + b0, v3 = acc[mt][nt][3] + b1;
            if (act == 1) {
                v0 = fmaxf(v0, 0.f); v1 = fmaxf(v1, 0.f);
                v2 = fmaxf(v2, 0.f); v3 = fmaxf(v3, 0.f);
            }
            *(float2*)(C + (size_t)row0 * N + col)       = make_float2(v0, v1);
            *(float2*)(C + (size_t)(row0 + 8) * N + col) = make_float2(v2, v3);
        }
    }
}

// ---------------- prep: KK = ke+kr (tf32), bias = u.ke + v.kr, repack V -----
__global__ void __launch_bounds__(256)
prep_kernel(const float* __restrict__ ke, const float* __restrict__ kr,
            const float* __restrict__ v,
            const float* __restrict__ ub, const float* __restrict__ vb,
            uint32_t* __restrict__ kk2, uint32_t* __restrict__ v2,
            float* __restrict__ biasO)
{
    const int row = blockIdx.x;          // = t*BATCH + b
    const int t = row / BATCH, b = row % BATCH;
    const int tid = threadIdx.x;
    const int h = tid >> 4, l16 = tid & 15, d0 = l16 * 4;

    const size_t src = (size_t)row * DMODEL + h * HDIM + d0;
    float4 kev = *(const float4*)(ke + src);
    float4 krv = *(const float4*)(kr + src);
    float4 vv  = *(const float4*)(v  + src);

    const size_t dst = ((size_t)(b * HEADS + h) * TLEN + t) * HDIM + d0;
    uint4 kko, vvo;
    kko.x = f2tf32(kev.x + krv.x); kko.y = f2tf32(kev.y + krv.y);
    kko.z = f2tf32(kev.z + krv.z); kko.w = f2tf32(kev.w + krv.w);
    vvo.x = f2tf32(vv.x); vvo.y = f2tf32(vv.y);
    vvo.z = f2tf32(vv.z); vvo.w = f2tf32(vv.w);
    *(uint4*)(kk2 + dst) = kko;
    *(uint4*)(v2  + dst) = vvo;

    float4 u4 = *(const float4*)(ub + h * HDIM + d0);
    float4 w4 = *(const float4*)(vb + h * HDIM + d0);
    float bsum = u4.x * kev.x + u4.y * kev.y + u4.z * kev.z + u4.w * kev.w
               + w4.x * krv.x + w4.y * krv.y + w4.z * krv.z + w4.w * krv.w;
#pragma unroll
    for (int off = 8; off; off >>= 1)
        bsum += __shfl_xor_sync(0xffffffffu, bsum, off, 16);
    if (l16 == 0) biasO[(size_t)(b * HEADS + h) * TLEN + t] = bsum;
}

// ---------------- tensor-core flash attention (pipelined KV) -----------------
#define FQS  0
#define FPS  8192
#define FKK  16384
#define FVS  20480
#define FBI  24576
#define FLASH_SMEM ((24576 + 128) * 4)

__device__ __forceinline__ int sw64(int row, int c) {
    return (row << 6) + (((c >> 2) ^ (row & 7)) << 2) + (c & 3);
}

__global__ void __launch_bounds__(256, 2)
flash_tc_kernel(const float* __restrict__ qg,
                const uint32_t* __restrict__ kk2,
                const uint32_t* __restrict__ v2,
                const float* __restrict__ biasG,
                float* __restrict__ out)
{
    extern __shared__ uint32_t fsm[];
    uint32_t* Qs  = fsm + FQS;
    uint32_t* Ps  = fsm + FPS;
    uint32_t* KKs = fsm + FKK;
    uint32_t* Vs  = fsm + FVS;
    float*    biasS = (float*)(fsm + FBI);   // [2][64]

    const int qb = blockIdx.x, h = blockIdx.y, b = blockIdx.z;
    const int tid = threadIdx.x;
    const int lane = tid & 31, wid = tid >> 5;
    const int q = lane >> 2, r = lane & 3;
    const int mw = wid * 16;

    const uint32_t sbase = (uint32_t)__cvta_generic_to_shared(fsm);
    const size_t   bh    = (size_t)(b * HEADS + h) * TLEN;
    const uint32_t* kkbh = kk2 + bh * HDIM;
    const uint32_t* vbh  = v2  + bh * HDIM;
    const float*    bibh = biasG + bh;

    auto issueKK = [&](int t0, int pb) {
#pragma unroll
        for (int it = 0; it < 4; it++) {
            int idx = tid + it * 256;
            int row = idx >> 4, g4 = (idx & 15) * 4;
            cp_async16(sbase + (uint32_t)(FKK + sw64(row, g4)) * 4,
                       kkbh + (size_t)(t0 + row) * HDIM + g4);
        }
        if (tid < 16)
            cp_async16(sbase + (uint32_t)(FBI + pb * 64 + tid * 4) * 4,
                       bibh + t0 + tid * 4);
    };
    auto issueV = [&](int t0) {
#pragma unroll
        for (int it = 0; it < 4; it++) {
            int idx = tid + it * 256;
            int row = idx >> 4, g4 = (idx & 15) * 4;
            cp_async16(sbase + (uint32_t)(FVS + sw64(row, g4)) * 4,
                       vbh + (size_t)(t0 + row) * HDIM + g4);
        }
    };

    // prologue: KK0 (group), V0 (group), Q tile (plain stores)
    issueKK(0, 0);
    cp_commit();
    issueV(0);
    cp_commit();
    // in flight: [KK0, V0]

#pragma unroll
    for (int it = 0; it < 8; it++) {
        int idx = tid + it * 256;
        int row = idx >> 4, g4 = (idx & 15) * 4;
        const float4 qv = *(const float4*)(qg +
            ((size_t)((qb * 128 + row) * BATCH + b)) * DMODEL + h * HDIM + g4);
        uint4 qo;
        qo.x = f2tf32(qv.x); qo.y = f2tf32(qv.y);
        qo.z = f2tf32(qv.z); qo.w = f2tf32(qv.w);
        *(uint4*)(Qs + sw64(row, g4)) = qo;
    }

    float m0 = -1e30f, m1 = -1e30f, l0 = 0.f, l1 = 0.f;
    float O[8][4];
#pragma unroll
    for (int nt = 0; nt < 8; nt++)
#pragma unroll
        for (int e = 0; e < 4; e++) O[nt][e] = 0.f;

    const int ntiles = 18 + 2 * qb;
    const int srow0 = qb * 128 + mw + q;

    for (int tt = 0; tt < ntiles; tt++) {
        const int t0 = tt * 64;
        const int pb = tt & 1;
        const bool more = (tt + 1 < ntiles);

        cp_wait<1>();          // KK(tt) [+bias] complete (V(tt) may be pending)
        __syncthreads();       // visibility of KK to all warps (+Q on tt=0)

        // ---- scores: S = Q @ KK^T ------------------------------------------
        float sc[8][4];
#pragma unroll
        for (int nt = 0; nt < 8; nt++)
#pragma unroll
            for (int e = 0; e < 4; e++) sc[nt][e] = 0.f;

#pragma unroll
        for (int kk = 0; kk < 64; kk += 8) {
            uint32_t a[4];
            a[0] = Qs[sw64(mw + q,     kk + r)];
            a[1] = Qs[sw64(mw + q + 8, kk + r)];
            a[2] = Qs[sw64(mw + q,     kk + r + 4)];
            a[3] = Qs[sw64(mw + q + 8, kk + r + 4)];
#pragma unroll
            for (int nt = 0; nt < 8; nt++) {
                uint32_t bb[2];
                bb[0] = KKs[sw64(nt * 8 + q, kk + r)];
                bb[1] = KKs[sw64(nt * 8 + q, kk + r + 4)];
                mma_tf32(sc[nt], a, bb);
            }
        }
        __syncthreads();       // all warps done reading KKs

        if (more) { issueKK(t0 + 64, pb ^ 1); cp_commit(); }
        // in flight: [V(tt), KK(tt+1)?]

        // ---- bias + scale + causal mask + online softmax --------------------
        const float* bS = biasS + pb * 64;
        const bool mt_ = (tt >= 16 + 2 * qb);
        float tmax0 = -1e30f, tmax1 = -1e30f;
#pragma unroll
        for (int nt = 0; nt < 8; nt++) {
            const int colb = nt * 8 + 2 * r;
            const float bi0 = bS[colb], bi1 = bS[colb + 1];
            float v0 = (sc[nt][0] + bi0) * 0.125f;
            float v1 = (sc[nt][1] + bi1) * 0.125f;
            float v2 = (sc[nt][2] + bi0) * 0.125f;
            float v3 = (sc[nt][3] + bi1) * 0.125f;
            if (mt_) {
                const int tc = t0 + colb;
                if (tc     > S_LEN + srow0)     v0 = -1e30f;
                if (tc + 1 > S_LEN + srow0)     v1 = -1e30f;
                if (tc     > S_LEN + srow0 + 8) v2 = -1e30f;
                if (tc + 1 > S_LEN + srow0 + 8) v3 = -1e30f;
            }
            sc[nt][0] = v0; sc[nt][1] = v1; sc[nt][2] = v2; sc[nt][3] = v3;
            tmax0 = fmaxf(tmax0, fmaxf(v0, v1));
            tmax1 = fmaxf(tmax1, fmaxf(v2, v3));
        }
        tmax0 = fmaxf(tmax0, __shfl_xor_sync(0xffffffffu, tmax0, 1));
        tmax0 = fmaxf(tmax0, __shfl_xor_sync(0xffffffffu, tmax0, 2));
        tmax1 = fmaxf(tmax1, __shfl_xor_sync(0xffffffffu, tmax1, 1));
        tmax1 = fmaxf(tmax1, __shfl_xor_sync(0xffffffffu, tmax1, 2));

        const float mnew0 = fmaxf(m0, tmax0);
        const float mnew1 = fmaxf(m1, tmax1);
        const float c0 = __expf(m0 - mnew0);
        const float c1 = __expf(m1 - mnew1);
        m0 = mnew0; m1 = mnew1;
        l0 *= c0; l1 *= c1;

        float ps0 = 0.f, ps1 = 0.f;
#pragma unroll
        for (int nt = 0; nt < 8; nt++) {
            float p0 = __expf(sc[nt][0] - mnew0);
            float p1 = __expf(sc[nt][1] - mnew0);
            float p2 = __expf(sc[nt][2] - mnew1);
            float p3 = __expf(sc[nt][3] - mnew1);
            ps0 += p0 + p1; ps1 += p2 + p3;
            O[nt][0] *= c0; O[nt][1] *= c0;
            O[nt][2] *= c1; O[nt][3] *= c1;
            uint2 s0, s1;
            s0.x = f2tf32(p0); s0.y = f2tf32(p1);
            s1.x = f2tf32(p2); s1.y = f2tf32(p3);
            *(uint2*)&Ps[sw64(mw + q,     nt * 8 + 2 * r)] = s0;
            *(uint2*)&Ps[sw64(mw + q + 8, nt * 8 + 2 * r)] = s1;
        }
        l0 += ps0; l1 += ps1;
        __syncwarp();

        // ---- ensure V(tt) landed, then O += P @ V ---------------------------
        if (more) { cp_wait<1>(); } else { cp_wait<0>(); }
        __syncthreads();       // visibility of Vs to all warps

#pragma unroll
        for (int kk = 0; kk < 64; kk += 8) {
            uint32_t a[4];
            a[0] = Ps[sw64(mw + q,     kk + r)];
            a[1] = Ps[sw64(mw + q + 8, kk + r)];
            a[2] = Ps[sw64(mw + q,     kk + r + 4)];
            a[3] = Ps[sw64(mw + q + 8, kk + r + 4)];
#pragma unroll
            for (int nt = 0; nt < 8; nt++) {
                uint32_t bb[2];
                bb[0] = Vs[sw64(kk + r,     nt * 8 + q)];
                bb[1] = Vs[sw64(kk + r + 4, nt * 8 + q)];
                mma_tf32(O[nt], a, bb);
            }
        }
        __syncthreads();       // all warps done reading Vs

        if (more) { issueV(t0 + 64); cp_commit(); }
        // in flight: [KK(tt+1), V(tt+1)]
    }

    // ---- finalize: reduce l over quad, normalize, store ---------------------
    l0 += __shfl_xor_sync(0xffffffffu, l0, 1);
    l0 += __shfl_xor_sync(0xffffffffu, l0, 2);
    l1 += __shfl_xor_sync(0xffffffffu, l1, 1);
    l1 += __shfl_xor_sync(0xffffffffu, l1, 2);
    const float inv0 = 1.f / l0, inv1 = 1.f / l1;

#pragma unroll
    for (int nt = 0; nt < 8; nt++) {
        const int col = nt * 8 + 2 * r;
        const int row0 = qb * 128 + mw + q;
        *(float2*)(out + ((size_t)(row0 * BATCH + b)) * DMODEL + h * HDIM + col)
            = make_float2(O[nt][0] * inv0, O[nt][1] * inv0);
        *(float2*)(out + ((size_t)((row0 + 8) * BATCH + b)) * DMODEL + h * HDIM + col)
            = make_float2(O[nt][2] * inv1, O[nt][3] * inv1);
    }
}

// ---------------- LayerNorm(a0 + a1 + res) * g + b ---------------------------
// a1 nullable: fuses the split-K partial-sum add for free.
__global__ void __launch_bounds__(256)
ln_kernel(const float* __restrict__ a0, const float* __restrict__ a1,
          const float* __restrict__ res,
          const float* __restrict__ g, const float* __restrict__ bta,
          float* __restrict__ out)
{
    const int row = blockIdx.x;
    const int tid = threadIdx.x;
    const int lane = tid & 31, wrp = tid >> 5;
    __shared__ float red[8];
    __shared__ float bc;

    float vals[4];
    float s = 0.f;
    const float* ar = a0 + (size_t)row * DMODEL;
    const float* br = a1 ? a1 + (size_t)row * DMODEL : nullptr;
    const float* rr = res + (size_t)row * DMODEL;
#pragma unroll
    for (int i = 0; i < 4; i++) {
        int d = tid + i * 256;
        float v = ar[d] + rr[d];
        if (br) v += br[d];
        vals[i] = v;
        s += v;
    }
#pragma unroll
    for (int off = 16; off; off >>= 1) s += __shfl_xor_sync(0xffffffffu, s, off);
    if (lane == 0) red[wrp] = s;
    __syncthreads();
    if (tid == 0) {
        float t = 0.f;
#pragma unroll
        for (int w = 0; w < 8; w++) t += red[w];
        bc = t * (1.f / DMODEL);
    }
    __syncthreads();
    const float mu = bc;

    float vs = 0.f;
#pragma unroll
    for (int i = 0; i < 4; i++) {
        float dd = vals[i] - mu;
        vs += dd * dd;
    }
#pragma unroll
    for (int off = 16; off; off >>= 1) vs += __shfl_xor_sync(0xffffffffu, vs, off);
    __syncthreads();
    if (lane == 0) red[wrp] = vs;
    __syncthreads();
    if (tid == 0) {
        float t = 0.f;
#pragma unroll
        for (int w = 0; w < 8; w++) t += red[w];
        bc = rsqrtf(t * (1.f / DMODEL) + 1e-5f);
    }
    __syncthreads();
    const float rstd = bc;

    float* orow = out + (size_t)row * DMODEL;
#pragma unroll
    for (int i = 0; i < 4; i++) {
        int d = tid + i * 256;
        orow[d] = (vals[i] - mu) * rstd * g[d] + bta[d];
    }
}

// ---------------- launcher ---------------------------------------------------
extern "C" void kernel_launch(void* const* d_in, const int* in_sizes, int n_in,
                              void* d_out, int out_size)
{
    const float* x      = (const float*)d_in[0];
    const float* p      = (const float*)d_in[1];
    /* mask d_in[2] is analytic: unused */
    const float* memory = (const float*)d_in[3];
    const float* u_bias = (const float*)d_in[4];
    const float* v_bias = (const float*)d_in[5];
    const float* wq  = (const float*)d_in[6];
    const float* wke = (const float*)d_in[7];
    const float* wkr = (const float*)d_in[8];
    const float* wv  = (const float*)d_in[9];
    const float* wc  = (const float*)d_in[10];
    const float* w1  = (const float*)d_in[11];
    const float* w1b = (const float*)d_in[12];
    const float* w2  = (const float*)d_in[13];
    const float* w2b = (const float*)d_in[14];
    const float* ln1g = (const float*)d_in[15];
    const float* ln1b = (const float*)d_in[16];
    const float* ln2g = (const float*)d_in[17];
    const float* ln2b = (const float*)d_in[18];
    float* out = (float*)d_out;

    float *q, *ke, *kr, *v, *av, *tbuf, *t2buf, *ubuf, *h1, *bias2;
    uint32_t *kk2, *v2;
    cudaGetSymbolAddress((void**)&q,     g_q);
    cudaGetSymbolAddress((void**)&ke,    g_ke);
    cudaGetSymbolAddress((void**)&kr,    g_kr);
    cudaGetSymbolAddress((void**)&v,     g_v);
    cudaGetSymbolAddress((void**)&av,    g_av);
    cudaGetSymbolAddress((void**)&tbuf,  g_t);
    cudaGetSymbolAddress((void**)&t2buf, g_t2);
    cudaGetSymbolAddress((void**)&ubuf,  g_u);
    cudaGetSymbolAddress((void**)&h1,    g_h1);
    cudaGetSymbolAddress((void**)&kk2,   g_kk2);
    cudaGetSymbolAddress((void**)&v2,    g_v2);
    cudaGetSymbolAddress((void**)&bias2, g_bias);

    cudaFuncSetAttribute(tf32gemm_kernel,
                         cudaFuncAttributeMaxDynamicSharedMemorySize, GEMM_SMEM);
    cudaFuncSetAttribute(flash_tc_kernel,
                         cudaFuncAttributeMaxDynamicSharedMemorySize, FLASH_SMEM);

    const dim3 blk(256);
    const size_t half = (size_t)ROWS_X * DMODEL;

    // ---- all 6 projections in ONE launch (z = 0..6) -------------------------
    {
        GemmPtrs gp{};
        gp.A[0] = x;      gp.W[0] = wq;  gp.C[0] = q;
        gp.A[1] = x;      gp.W[1] = wke; gp.C[1] = ke + half;
        gp.A[2] = x;      gp.W[2] = wv;  gp.C[2] = v + half;
        gp.A[3] = memory; gp.W[3] = wke; gp.C[3] = ke;
        gp.A[4] = memory; gp.W[4] = wv;  gp.C[4] = v;
        gp.A[5] = p;        gp.W[5] = wkr; gp.C[5] = kr;
        gp.A[6] = p + half; gp.W[6] = wkr; gp.C[6] = kr + half;
        tf32gemm_kernel<<<dim3(8, 16, 7), blk, GEMM_SMEM>>>(
            gp, ROWS_X, DMODEL, DMODEL, DMODEL, 0);
    }

    // prep: fuse KK, bias, repack V
    prep_kernel<<<ROWS_T, blk>>>(ke, kr, v, u_bias, v_bias, kk2, v2, bias2);

    // tensor-core flash attention (pipelined KV prefetch)
    flash_tc_kernel<<<dim3(8, HEADS, BATCH), blk, FLASH_SMEM>>>(
        q, kk2, v2, bias2, av);

    // output proj (split-K=2: partials into tbuf/t2buf) + LN1 (fused add)
    {
        GemmPtrs gp{};
        gp.A[0] = av;       gp.W[0] = wc;       gp.C[0] = tbuf;
        gp.A[1] = av + 512; gp.W[1] = wc + 512; gp.C[1] = t2buf;
        tf32gemm_kernel<<<dim3(8, 16, 2), blk, GEMM_SMEM>>>(
            gp, ROWS_X, DMODEL, 512, DMODEL, 0);
    }
    ln_kernel<<<ROWS_X, blk>>>(tbuf, t2buf, x, ln1g, ln1b, ubuf);

    // FFN: w1 (relu, single), w2 (split-K=2) + LN2 (fused add)
    {
        GemmPtrs gp{};
        gp.A[0] = ubuf; gp.W[0] = w1; gp.C[0] = h1; gp.bias[0] = w1b;
        tf32gemm_kernel<<<dim3(32, 16, 1), blk, GEMM_SMEM>>>(
            gp, ROWS_X, FFDIM, DMODEL, DMODEL, 1);
    }
    {
        GemmPtrs gp{};
        gp.A[0] = h1;        gp.W[0] = w2;        gp.C[0] = tbuf;  gp.bias[0] = w2b;
        gp.A[1] = h1 + 2048; gp.W[1] = w2 + 2048; gp.C[1] = t2buf;
        tf32gemm_kernel<<<dim3(8, 16, 2), blk, GEMM_SMEM>>>(
            gp, ROWS_X, DMODEL, 2048, FFDIM, 0);
    }
    ln_kernel<<<ROWS_X, blk>>>(tbuf, t2buf, ubuf, ln2g, ln2b, out);
}

// round 10
// speedup vs baseline: 1.4737x; 1.2485x over previous
#include <cuda_runtime.h>
#include <cuda_fp16.h>
#include <math.h>
#include <stdint.h>

// Problem constants
#define S_LEN 1024
#define BATCH 2
#define DMODEL 1024
#define HEADS 16
#define HDIM 64
#define TLEN 2048
#define FFDIM 4096
#define ROWS_X (S_LEN * BATCH)     // 2048
#define ROWS_T (TLEN * BATCH)      // 4096

// ---------------- scratch buffers (device globals) ---------------------------
__device__ float g_q [ROWS_X * DMODEL];
__device__ float g_ke[ROWS_T * DMODEL];
__device__ float g_kr[ROWS_T * DMODEL];
__device__ float g_v [ROWS_T * DMODEL];
__device__ float g_t [ROWS_X * DMODEL];
__device__ float g_t2[ROWS_X * DMODEL];
__device__ float g_u [ROWS_X * DMODEL];
// fp16 tensors
__device__ __half g_xh  [ROWS_X * DMODEL];
__device__ __half g_memh[ROWS_X * DMODEL];
__device__ __half g_ph  [ROWS_T * DMODEL];
__device__ __half g_wqh [DMODEL * DMODEL];
__device__ __half g_wkeh[DMODEL * DMODEL];
__device__ __half g_wkrh[DMODEL * DMODEL];
__device__ __half g_wvh [DMODEL * DMODEL];
__device__ __half g_wch [DMODEL * DMODEL];
__device__ __half g_w1h [FFDIM * DMODEL];
__device__ __half g_w2h [DMODEL * FFDIM];
__device__ __half g_avh [ROWS_X * DMODEL];
__device__ __half g_uh  [ROWS_X * DMODEL];
__device__ __half g_h1h [ROWS_X * FFDIM];
// flash-prep outputs (tf32 bit patterns)
__device__ uint32_t g_kk2 [BATCH * HEADS * TLEN * HDIM];
__device__ uint32_t g_v2  [BATCH * HEADS * TLEN * HDIM];
__device__ float    g_bias[BATCH * HEADS * TLEN];

// ---------------- common PTX helpers ----------------------------------------
__device__ __forceinline__ uint32_t f2tf32(float f) {
    uint32_t r;
    asm("cvt.rna.tf32.f32 %0, %1;" : "=r"(r) : "f"(f));
    return r;
}
__device__ __forceinline__ void cp_async16(uint32_t saddr, const void* gptr) {
    asm volatile("cp.async.cg.shared.global [%0], [%1], 16;\n"
                 :: "r"(saddr), "l"(gptr));
}
__device__ __forceinline__ void cp_commit() {
    asm volatile("cp.async.commit_group;\n");
}
template <int N>
__device__ __forceinline__ void cp_wait() {
    asm volatile("cp.async.wait_group %0;\n" :: "n"(N));
}
__device__ __forceinline__ void mma_tf32(float* d, const uint32_t* a, const uint32_t* b) {
    asm volatile(
        "mma.sync.aligned.m16n8k8.row.col.f32.tf32.tf32.f32 "
        "{%0,%1,%2,%3}, {%4,%5,%6,%7}, {%8,%9}, {%0,%1,%2,%3};\n"
        : "+f"(d[0]), "+f"(d[1]), "+f"(d[2]), "+f"(d[3])
        : "r"(a[0]), "r"(a[1]), "r"(a[2]), "r"(a[3]), "r"(b[0]), "r"(b[1]));
}
__device__ __forceinline__ void mma_f16(float* d, const uint32_t* a, const uint32_t* b) {
    asm volatile(
        "mma.sync.aligned.m16n8k16.row.col.f32.f16.f16.f32 "
        "{%0,%1,%2,%3}, {%4,%5,%6,%7}, {%8,%9}, {%0,%1,%2,%3};\n"
        : "+f"(d[0]), "+f"(d[1]), "+f"(d[2]), "+f"(d[3])
        : "r"(a[0]), "r"(a[1]), "r"(a[2]), "r"(a[3]), "r"(b[0]), "r"(b[1]));
}
__device__ __forceinline__ void ldm_x4(uint32_t* r, uint32_t addr) {
    asm volatile("ldmatrix.sync.aligned.m8n8.x4.shared.b16 {%0,%1,%2,%3}, [%4];"
                 : "=r"(r[0]), "=r"(r[1]), "=r"(r[2]), "=r"(r[3]) : "r"(addr));
}

// ---------------- fp32 -> fp16 conversion (merged segments) ------------------
#define MAXSEG 10
struct CvtSegs {
    const float* src[MAXSEG];
    __half*      dst[MAXSEG];
    int          end8[MAXSEG];
    int          nseg;
};

__global__ void __launch_bounds__(256)
cvt_all_kernel(CvtSegs segs, int total8)
{
    int idx = blockIdx.x * 256 + threadIdx.x;
    if (idx >= total8) return;
    int s = 0;
#pragma unroll
    for (int i = 0; i < MAXSEG; i++)
        if (i < segs.nseg && idx >= segs.end8[i]) s = i + 1;
    const int off = idx - (s ? segs.end8[s - 1] : 0);

    const float4* s4 = (const float4*)(segs.src[s] + (size_t)off * 8);
    float4 a = s4[0], b = s4[1];
    __half2 h[4];
    h[0] = __floats2half2_rn(a.x, a.y);
    h[1] = __floats2half2_rn(a.z, a.w);
    h[2] = __floats2half2_rn(b.x, b.y);
    h[3] = __floats2half2_rn(b.z, b.w);
    *(uint4*)(segs.dst[s] + (size_t)off * 8) = *(uint4*)h;
}

// ---------------- fp16 tensor-core GEMM --------------------------------------
// C[M,N] = A[M,K] * W[N,K]^T (+bias fp32)(+relu). A, W are fp16.
// C (fp32) and Ch (fp16) outputs both nullable. blockIdx.z picks the job.
// 256 thr (8 warps, 2m x 4n), warp tile 64x32, BK=32, 2-stage cp.async,
// smem rows padded to 72 halves (144 B) -> conflict-free ldmatrix.
struct GemmPtrs {
    const __half* A[7];
    const __half* W[7];
    float*        C[7];
    __half*       Ch[7];
    const float*  bias[7];
};

#define HROW 144u                      // smem row stride in bytes (72 halves)
#define TILE16 (128u * HROW)           // 18432 B per operand tile
#define STAGE16 (2u * TILE16)          // 36864 B per stage
#define GEMM16_SMEM (2 * 36864)        // 73728 B

__global__ void __launch_bounds__(256)
gemm16_kernel(GemmPtrs ptrs, int M, int N, int Klen, int Kstride, int act)
{
    extern __shared__ char smem[];
    const uint32_t sbase = (uint32_t)__cvta_generic_to_shared(smem);

    const __half* A    = ptrs.A[blockIdx.z];
    const __half* W    = ptrs.W[blockIdx.z];
    float*        C    = ptrs.C[blockIdx.z];
    __half*       Ch   = ptrs.Ch[blockIdx.z];
    const float*  bias = ptrs.bias[blockIdx.z];

    const int tid = threadIdx.x;
    const int lane = tid & 31, wrp = tid >> 5;
    const int wm = wrp & 1, wn = wrp >> 1;
    const int q = lane >> 2, r = lane & 3;
    const int m0 = blockIdx.y * 128;
    const int n0 = blockIdx.x * 128;

    float acc[4][4][4];
#pragma unroll
    for (int i = 0; i < 4; i++)
#pragma unroll
        for (int j = 0; j < 4; j++)
#pragma unroll
            for (int e = 0; e < 4; e++) acc[i][j][e] = 0.f;

    auto issue = [&](int buf, int k0) {   // k0 in halves
        const uint32_t so = sbase + (uint32_t)buf * STAGE16;
#pragma unroll
        for (int i = 0; i < 2; i++) {
            int id = tid + i * 256;            // 0..511
            int row = id >> 2, c = id & 3;     // 4 x 16B chunks per row
            uint32_t d = (uint32_t)row * HROW + (uint32_t)c * 16u;
            cp_async16(so + d,          A + (size_t)(m0 + row) * Kstride + k0 + c * 8);
            cp_async16(so + TILE16 + d, W + (size_t)(n0 + row) * Kstride + k0 + c * 8);
        }
    };

    const int KT = Klen >> 5;
    issue(0, 0);
    cp_commit();

    const int alr = lane & 15, alc = lane >> 4;   // A ldmatrix lane mapping
    const int bg = lane >> 3,  blr = lane & 7;    // B ldmatrix lane mapping

    for (int kt = 0; kt < KT; kt++) {
        const int cur = kt & 1;
        if (kt + 1 < KT) {
            issue(cur ^ 1, (kt + 1) << 5);
            cp_commit();
            cp_wait<1>();
        } else {
            cp_wait<0>();
        }
        __syncthreads();

        const uint32_t aBase = sbase + (uint32_t)cur * STAGE16;
        const uint32_t bBase = aBase + TILE16;

#pragma unroll
        for (int ks = 0; ks < 2; ks++) {
            uint32_t afr[4][4];
#pragma unroll
            for (int mt = 0; mt < 4; mt++) {
                uint32_t addr = aBase +
                    (uint32_t)(wm * 64 + mt * 16 + alr) * HROW +
                    (uint32_t)(ks * 32 + alc * 16);
                ldm_x4(afr[mt], addr);
            }
            uint32_t bfr[4][2];
#pragma unroll
            for (int ntp = 0; ntp < 2; ntp++) {
                uint32_t addr = bBase +
                    (uint32_t)(wn * 32 + ntp * 16 + (bg >> 1) * 8 + blr) * HROW +
                    (uint32_t)(ks * 32 + (bg & 1) * 16);
                uint32_t tmp[4];
                ldm_x4(tmp, addr);
                bfr[ntp * 2 + 0][0] = tmp[0]; bfr[ntp * 2 + 0][1] = tmp[1];
                bfr[ntp * 2 + 1][0] = tmp[2]; bfr[ntp * 2 + 1][1] = tmp[3];
            }
#pragma unroll
            for (int mt = 0; mt < 4; mt++)
#pragma unroll
                for (int nt = 0; nt < 4; nt++)
                    mma_f16(acc[mt][nt], afr[mt], bfr[nt]);
        }
        __syncthreads();
    }

    // epilogue (same m16n8 C layout as tf32 path)
#pragma unroll
    for (int mt = 0; mt < 4; mt++) {
        const int row0 = m0 + wm * 64 + mt * 16 + q;
#pragma unroll
        for (int nt = 0; nt < 4; nt++) {
            const int col = n0 + wn * 32 + nt * 8 + r * 2;
            float b0 = bias ? bias[col]     : 0.f;
            float b1 = bias ? bias[col + 1] : 0.f;
            float v0 = acc[mt][nt][0] + b0, v1 = acc[mt][nt][1] + b1;
            float v2 = acc[mt][nt][2] + b0, v3 = acc[mt][nt][3] + b1;
            if (act == 1) {
                v0 = fmaxf(v0, 0.f); v1 = fmaxf(v1, 0.f);
                v2 = fmaxf(v2, 0.f); v3 = fmaxf(v3, 0.f);
            }
            if (C) {
                *(float2*)(C + (size_t)row0 * N + col)       = make_float2(v0, v1);
                *(float2*)(C + (size_t)(row0 + 8) * N + col) = make_float2(v2, v3);
            }
            if (Ch) {
                *(__half2*)(Ch + (size_t)row0 * N + col)       = __floats2half2_rn(v0, v1);
                *(__half2*)(Ch + (size_t)(row0 + 8) * N + col) = __floats2half2_rn(v2, v3);
            }
        }
    }
}

// ---------------- prep: KK = ke+kr (tf32), bias = u.ke + v.kr, repack V -----
__global__ void __launch_bounds__(256)
prep_kernel(const float* __restrict__ ke, const float* __restrict__ kr,
            const float* __restrict__ v,
            const float* __restrict__ ub, const float* __restrict__ vb,
            uint32_t* __restrict__ kk2, uint32_t* __restrict__ v2,
            float* __restrict__ biasO)
{
    const int row = blockIdx.x;          // = t*BATCH + b
    const int t = row / BATCH, b = row % BATCH;
    const int tid = threadIdx.x;
    const int h = tid >> 4, l16 = tid & 15, d0 = l16 * 4;

    const size_t src = (size_t)row * DMODEL + h * HDIM + d0;
    float4 kev = *(const float4*)(ke + src);
    float4 krv = *(const float4*)(kr + src);
    float4 vv  = *(const float4*)(v  + src);

    const size_t dst = ((size_t)(b * HEADS + h) * TLEN + t) * HDIM + d0;
    uint4 kko, vvo;
    kko.x = f2tf32(kev.x + krv.x); kko.y = f2tf32(kev.y + krv.y);
    kko.z = f2tf32(kev.z + krv.z); kko.w = f2tf32(kev.w + krv.w);
    vvo.x = f2tf32(vv.x); vvo.y = f2tf32(vv.y);
    vvo.z = f2tf32(vv.z); vvo.w = f2tf32(vv.w);
    *(uint4*)(kk2 + dst) = kko;
    *(uint4*)(v2  + dst) = vvo;

    float4 u4 = *(const float4*)(ub + h * HDIM + d0);
    float4 w4 = *(const float4*)(vb + h * HDIM + d0);
    float bsum = u4.x * kev.x + u4.y * kev.y + u4.z * kev.z + u4.w * kev.w
               + w4.x * krv.x + w4.y * krv.y + w4.z * krv.z + w4.w * krv.w;
#pragma unroll
    for (int off = 8; off; off >>= 1)
        bsum += __shfl_xor_sync(0xffffffffu, bsum, off, 16);
    if (l16 == 0) biasO[(size_t)(b * HEADS + h) * TLEN + t] = bsum;
}

// ---------------- tensor-core flash attention (pipelined KV, tf32) -----------
#define FQS  0
#define FPS  8192
#define FKK  16384
#define FVS  20480
#define FBI  24576
#define FLASH_SMEM ((24576 + 128) * 4)

__device__ __forceinline__ int sw64(int row, int c) {
    return (row << 6) + (((c >> 2) ^ (row & 7)) << 2) + (c & 3);
}

__global__ void __launch_bounds__(256, 2)
flash_tc_kernel(const float* __restrict__ qg,
                const uint32_t* __restrict__ kk2,
                const uint32_t* __restrict__ v2,
                const float* __restrict__ biasG,
                __half* __restrict__ out)     // fp16 output for wc GEMM
{
    extern __shared__ uint32_t fsm[];
    uint32_t* Qs  = fsm + FQS;
    uint32_t* Ps  = fsm + FPS;
    uint32_t* KKs = fsm + FKK;
    uint32_t* Vs  = fsm + FVS;
    float*    biasS = (float*)(fsm + FBI);   // [2][64]

    const int qb = blockIdx.x, h = blockIdx.y, b = blockIdx.z;
    const int tid = threadIdx.x;
    const int lane = tid & 31, wid = tid >> 5;
    const int q = lane >> 2, r = lane & 3;
    const int mw = wid * 16;

    const uint32_t sbase = (uint32_t)__cvta_generic_to_shared(fsm);
    const size_t   bh    = (size_t)(b * HEADS + h) * TLEN;
    const uint32_t* kkbh = kk2 + bh * HDIM;
    const uint32_t* vbh  = v2  + bh * HDIM;
    const float*    bibh = biasG + bh;

    auto issueKK = [&](int t0, int pb) {
#pragma unroll
        for (int it = 0; it < 4; it++) {
            int idx = tid + it * 256;
            int row = idx >> 4, g4 = (idx & 15) * 4;
            cp_async16(sbase + (uint32_t)(FKK + sw64(row, g4)) * 4,
                       kkbh + (size_t)(t0 + row) * HDIM + g4);
        }
        if (tid < 16)
            cp_async16(sbase + (uint32_t)(FBI + pb * 64 + tid * 4) * 4,
                       bibh + t0 + tid * 4);
    };
    auto issueV = [&](int t0) {
#pragma unroll
        for (int it = 0; it < 4; it++) {
            int idx = tid + it * 256;
            int row = idx >> 4, g4 = (idx & 15) * 4;
            cp_async16(sbase + (uint32_t)(FVS + sw64(row, g4)) * 4,
                       vbh + (size_t)(t0 + row) * HDIM + g4);
        }
    };

    issueKK(0, 0);
    cp_commit();
    issueV(0);
    cp_commit();

#pragma unroll
    for (int it = 0; it < 8; it++) {
        int idx = tid + it * 256;
        int row = idx >> 4, g4 = (idx & 15) * 4;
        const float4 qv = *(const float4*)(qg +
            ((size_t)((qb * 128 + row) * BATCH + b)) * DMODEL + h * HDIM + g4);
        uint4 qo;
        qo.x = f2tf32(qv.x); qo.y = f2tf32(qv.y);
        qo.z = f2tf32(qv.z); qo.w = f2tf32(qv.w);
        *(uint4*)(Qs + sw64(row, g4)) = qo;
    }

    float m0 = -1e30f, m1 = -1e30f, l0 = 0.f, l1 = 0.f;
    float O[8][4];
#pragma unroll
    for (int nt = 0; nt < 8; nt++)
#pragma unroll
        for (int e = 0; e < 4; e++) O[nt][e] = 0.f;

    const int ntiles = 18 + 2 * qb;
    const int srow0 = qb * 128 + mw + q;

    for (int tt = 0; tt < ntiles; tt++) {
        const int t0 = tt * 64;
        const int pb = tt & 1;
        const bool more = (tt + 1 < ntiles);

        cp_wait<1>();
        __syncthreads();

        float sc[8][4];
#pragma unroll
        for (int nt = 0; nt < 8; nt++)
#pragma unroll
            for (int e = 0; e < 4; e++) sc[nt][e] = 0.f;

#pragma unroll
        for (int kk = 0; kk < 64; kk += 8) {
            uint32_t a[4];
            a[0] = Qs[sw64(mw + q,     kk + r)];
            a[1] = Qs[sw64(mw + q + 8, kk + r)];
            a[2] = Qs[sw64(mw + q,     kk + r + 4)];
            a[3] = Qs[sw64(mw + q + 8, kk + r + 4)];
#pragma unroll
            for (int nt = 0; nt < 8; nt++) {
                uint32_t bb[2];
                bb[0] = KKs[sw64(nt * 8 + q, kk + r)];
                bb[1] = KKs[sw64(nt * 8 + q, kk + r + 4)];
                mma_tf32(sc[nt], a, bb);
            }
        }
        __syncthreads();

        if (more) { issueKK(t0 + 64, pb ^ 1); cp_commit(); }

        const float* bS = biasS + pb * 64;
        const bool mt_ = (tt >= 16 + 2 * qb);
        float tmax0 = -1e30f, tmax1 = -1e30f;
#pragma unroll
        for (int nt = 0; nt < 8; nt++) {
            const int colb = nt * 8 + 2 * r;
            const float bi0 = bS[colb], bi1 = bS[colb + 1];
            float v0 = (sc[nt][0] + bi0) * 0.125f;
            float v1 = (sc[nt][1] + bi1) * 0.125f;
            float v2 = (sc[nt][2] + bi0) * 0.125f;
            float v3 = (sc[nt][3] + bi1) * 0.125f;
            if (mt_) {
                const int tc = t0 + colb;
                if (tc     > S_LEN + srow0)     v0 = -1e30f;
                if (tc + 1 > S_LEN + srow0)     v1 = -1e30f;
                if (tc     > S_LEN + srow0 + 8) v2 = -1e30f;
                if (tc + 1 > S_LEN + srow0 + 8) v3 = -1e30f;
            }
            sc[nt][0] = v0; sc[nt][1] = v1; sc[nt][2] = v2; sc[nt][3] = v3;
            tmax0 = fmaxf(tmax0, fmaxf(v0, v1));
            tmax1 = fmaxf(tmax1, fmaxf(v2, v3));
        }
        tmax0 = fmaxf(tmax0, __shfl_xor_sync(0xffffffffu, tmax0, 1));
        tmax0 = fmaxf(tmax0, __shfl_xor_sync(0xffffffffu, tmax0, 2));
        tmax1 = fmaxf(tmax1, __shfl_xor_sync(0xffffffffu, tmax1, 1));
        tmax1 = fmaxf(tmax1, __shfl_xor_sync(0xffffffffu, tmax1, 2));

        const float mnew0 = fmaxf(m0, tmax0);
        const float mnew1 = fmaxf(m1, tmax1);
        const float c0 = __expf(m0 - mnew0);
        const float c1 = __expf(m1 - mnew1);
        m0 = mnew0; m1 = mnew1;
        l0 *= c0; l1 *= c1;

        float ps0 = 0.f, ps1 = 0.f;
#pragma unroll
        for (int nt = 0; nt < 8; nt++) {
            float p0 = __expf(sc[nt][0] - mnew0);
            float p1 = __expf(sc[nt][1] - mnew0);
            float p2 = __expf(sc[nt][2] - mnew1);
            float p3 = __expf(sc[nt][3] - mnew1);
            ps0 += p0 + p1; ps1 += p2 + p3;
            O[nt][0] *= c0; O[nt][1] *= c0;
            O[nt][2] *= c1; O[nt][3] *= c1;
            uint2 s0, s1;
            s0.x = f2tf32(p0); s0.y = f2tf32(p1);
            s1.x = f2tf32(p2); s1.y = f2tf32(p3);
            *(uint2*)&Ps[sw64(mw + q,     nt * 8 + 2 * r)] = s0;
            *(uint2*)&Ps[sw64(mw + q + 8, nt * 8 + 2 * r)] = s1;
        }
        l0 += ps0; l1 += ps1;
        __syncwarp();

        if (more) { cp_wait<1>(); } else { cp_wait<0>(); }
        __syncthreads();

#pragma unroll
        for (int kk = 0; kk < 64; kk += 8) {
            uint32_t a[4];
            a[0] = Ps[sw64(mw + q,     kk + r)];
            a[1] = Ps[sw64(mw + q + 8, kk + r)];
            a[2] = Ps[sw64(mw + q,     kk + r + 4)];
            a[3] = Ps[sw64(mw + q + 8, kk + r + 4)];
#pragma unroll
            for (int nt = 0; nt < 8; nt++) {
                uint32_t bb[2];
                bb[0] = Vs[sw64(kk + r,     nt * 8 + q)];
                bb[1] = Vs[sw64(kk + r + 4, nt * 8 + q)];
                mma_tf32(O[nt], a, bb);
            }
        }
        __syncthreads();

        if (more) { issueV(t0 + 64); cp_commit(); }
    }

    l0 += __shfl_xor_sync(0xffffffffu, l0, 1);
    l0 += __shfl_xor_sync(0xffffffffu, l0, 2);
    l1 += __shfl_xor_sync(0xffffffffu, l1, 1);
    l1 += __shfl_xor_sync(0xffffffffu, l1, 2);
    const float inv0 = 1.f / l0, inv1 = 1.f / l1;

#pragma unroll
    for (int nt = 0; nt < 8; nt++) {
        const int col = nt * 8 + 2 * r;
        const int row0 = qb * 128 + mw + q;
        *(__half2*)(out + ((size_t)(row0 * BATCH + b)) * DMODEL + h * HDIM + col)
            = __floats2half2_rn(O[nt][0] * inv0, O[nt][1] * inv0);
        *(__half2*)(out + ((size_t)((row0 + 8) * BATCH + b)) * DMODEL + h * HDIM + col)
            = __floats2half2_rn(O[nt][2] * inv1, O[nt][3] * inv1);
    }
}

// ---------------- LayerNorm(a0 [+ a1] + res) * g + b -------------------------
// out fp32; out_h (nullable) fp16 copy for the next fp16 GEMM.
__global__ void __launch_bounds__(256)
ln_kernel(const float* __restrict__ a0, const float* __restrict__ a1,
          const float* __restrict__ res,
          const float* __restrict__ g, const float* __restrict__ bta,
          float* __restrict__ out, __half* __restrict__ out_h)
{
    const int row = blockIdx.x;
    const int tid = threadIdx.x;
    const int lane = tid & 31, wrp = tid >> 5;
    __shared__ float red[8];
    __shared__ float bc;

    float vals[4];
    float s = 0.f;
    const float* ar = a0 + (size_t)row * DMODEL;
    const float* br = a1 ? a1 + (size_t)row * DMODEL : nullptr;
    const float* rr = res + (size_t)row * DMODEL;
#pragma unroll
    for (int i = 0; i < 4; i++) {
        int d = tid + i * 256;
        float v = ar[d] + rr[d];
        if (br) v += br[d];
        vals[i] = v;
        s += v;
    }
#pragma unroll
    for (int off = 16; off; off >>= 1) s += __shfl_xor_sync(0xffffffffu, s, off);
    if (lane == 0) red[wrp] = s;
    __syncthreads();
    if (tid == 0) {
        float t = 0.f;
#pragma unroll
        for (int w = 0; w < 8; w++) t += red[w];
        bc = t * (1.f / DMODEL);
    }
    __syncthreads();
    const float mu = bc;

    float vs = 0.f;
#pragma unroll
    for (int i = 0; i < 4; i++) {
        float dd = vals[i] - mu;
        vs += dd * dd;
    }
#pragma unroll
    for (int off = 16; off; off >>= 1) vs += __shfl_xor_sync(0xffffffffu, vs, off);
    __syncthreads();
    if (lane == 0) red[wrp] = vs;
    __syncthreads();
    if (tid == 0) {
        float t = 0.f;
#pragma unroll
        for (int w = 0; w < 8; w++) t += red[w];
        bc = rsqrtf(t * (1.f / DMODEL) + 1e-5f);
    }
    __syncthreads();
    const float rstd = bc;

    float* orow = out + (size_t)row * DMODEL;
    __half* hrow = out_h ? out_h + (size_t)row * DMODEL : nullptr;
#pragma unroll
    for (int i = 0; i < 4; i++) {
        int d = tid + i * 256;
        float vv = (vals[i] - mu) * rstd * g[d] + bta[d];
        orow[d] = vv;
        if (hrow) hrow[d] = __float2half(vv);
    }
}

// ---------------- launcher ---------------------------------------------------
extern "C" void kernel_launch(void* const* d_in, const int* in_sizes, int n_in,
                              void* d_out, int out_size)
{
    const float* x      = (const float*)d_in[0];
    const float* p      = (const float*)d_in[1];
    /* mask d_in[2] is analytic: unused */
    const float* memory = (const float*)d_in[3];
    const float* u_bias = (const float*)d_in[4];
    const float* v_bias = (const float*)d_in[5];
    const float* wq  = (const float*)d_in[6];
    const float* wke = (const float*)d_in[7];
    const float* wkr = (const float*)d_in[8];
    const float* wv  = (const float*)d_in[9];
    const float* wc  = (const float*)d_in[10];
    const float* w1  = (const float*)d_in[11];
    const float* w1b = (const float*)d_in[12];
    const float* w2  = (const float*)d_in[13];
    const float* w2b = (const float*)d_in[14];
    const float* ln1g = (const float*)d_in[15];
    const float* ln1b = (const float*)d_in[16];
    const float* ln2g = (const float*)d_in[17];
    const float* ln2b = (const float*)d_in[18];
    float* out = (float*)d_out;

    float *q, *ke, *kr, *v, *tbuf, *t2buf, *ubuf, *bias2;
    __half *xh, *memh, *ph, *wqh, *wkeh, *wkrh, *wvh, *wch, *w1h, *w2h;
    __half *avh, *uh, *h1h;
    uint32_t *kk2, *v2;
    cudaGetSymbolAddress((void**)&q,     g_q);
    cudaGetSymbolAddress((void**)&ke,    g_ke);
    cudaGetSymbolAddress((void**)&kr,    g_kr);
    cudaGetSymbolAddress((void**)&v,     g_v);
    cudaGetSymbolAddress((void**)&tbuf,  g_t);
    cudaGetSymbolAddress((void**)&t2buf, g_t2);
    cudaGetSymbolAddress((void**)&ubuf,  g_u);
    cudaGetSymbolAddress((void**)&xh,    g_xh);
    cudaGetSymbolAddress((void**)&memh,  g_memh);
    cudaGetSymbolAddress((void**)&ph,    g_ph);
    cudaGetSymbolAddress((void**)&wqh,   g_wqh);
    cudaGetSymbolAddress((void**)&wkeh,  g_wkeh);
    cudaGetSymbolAddress((void**)&wkrh,  g_wkrh);
    cudaGetSymbolAddress((void**)&wvh,   g_wvh);
    cudaGetSymbolAddress((void**)&wch,   g_wch);
    cudaGetSymbolAddress((void**)&w1h,   g_w1h);
    cudaGetSymbolAddress((void**)&w2h,   g_w2h);
    cudaGetSymbolAddress((void**)&avh,   g_avh);
    cudaGetSymbolAddress((void**)&uh,    g_uh);
    cudaGetSymbolAddress((void**)&h1h,   g_h1h);
    cudaGetSymbolAddress((void**)&kk2,   g_kk2);
    cudaGetSymbolAddress((void**)&v2,    g_v2);
    cudaGetSymbolAddress((void**)&bias2, g_bias);

    cudaFuncSetAttribute(gemm16_kernel,
                         cudaFuncAttributeMaxDynamicSharedMemorySize, GEMM16_SMEM);
    cudaFuncSetAttribute(flash_tc_kernel,
                         cudaFuncAttributeMaxDynamicSharedMemorySize, FLASH_SMEM);

    const dim3 blk(256);
    const size_t half = (size_t)ROWS_X * DMODEL;

    // ---- convert inputs + weights to fp16 (one merged launch) ---------------
    {
        CvtSegs cs{};
        int acc = 0, i = 0;
        auto add = [&](const float* s, __half* d, int n8) {
            cs.src[i] = s; cs.dst[i] = d; acc += n8; cs.end8[i] = acc; i++;
        };
        add(x,      xh,   ROWS_X * DMODEL / 8);
        add(memory, memh, ROWS_X * DMODEL / 8);
        add(p,      ph,   ROWS_T * DMODEL / 8);
        add(wq,  wqh,  DMODEL * DMODEL / 8);
        add(wke, wkeh, DMODEL * DMODEL / 8);
        add(wkr, wkrh, DMODEL * DMODEL / 8);
        add(wv,  wvh,  DMODEL * DMODEL / 8);
        add(wc,  wch,  DMODEL * DMODEL / 8);
        add(w1,  w1h,  FFDIM * DMODEL / 8);
        add(w2,  w2h,  FFDIM * DMODEL / 8);
        cs.nseg = i;
        cvt_all_kernel<<<(acc + 255) / 256, blk>>>(cs, acc);
    }

    // ---- all 6 projections in ONE launch (z = 0..6), fp16 mma ---------------
    {
        GemmPtrs gp{};
        gp.A[0] = xh;   gp.W[0] = wqh;  gp.C[0] = q;
        gp.A[1] = xh;   gp.W[1] = wkeh; gp.C[1] = ke + half;
        gp.A[2] = xh;   gp.W[2] = wvh;  gp.C[2] = v + half;
        gp.A[3] = memh; gp.W[3] = wkeh; gp.C[3] = ke;
        gp.A[4] = memh; gp.W[4] = wvh;  gp.C[4] = v;
        gp.A[5] = ph;                       gp.W[5] = wkrh; gp.C[5] = kr;
        gp.A[6] = ph + half;                gp.W[6] = wkrh; gp.C[6] = kr + half;
        gemm16_kernel<<<dim3(8, 16, 7), blk, GEMM16_SMEM>>>(
            gp, ROWS_X, DMODEL, DMODEL, DMODEL, 0);
    }

    // prep: fuse KK, bias, repack V (tf32)
    prep_kernel<<<ROWS_T, blk>>>(ke, kr, v, u_bias, v_bias, kk2, v2, bias2);

    // flash attention (tf32; writes avh fp16)
    flash_tc_kernel<<<dim3(8, HEADS, BATCH), blk, FLASH_SMEM>>>(
        q, kk2, v2, bias2, avh);

    // output proj (split-K=2) + LN1 (fused add; emits uh fp16)
    {
        GemmPtrs gp{};
        gp.A[0] = avh;       gp.W[0] = wch;       gp.C[0] = tbuf;
        gp.A[1] = avh + 512; gp.W[1] = wch + 512; gp.C[1] = t2buf;
        gemm16_kernel<<<dim3(8, 16, 2), blk, GEMM16_SMEM>>>(
            gp, ROWS_X, DMODEL, 512, DMODEL, 0);
    }
    ln_kernel<<<ROWS_X, blk>>>(tbuf, t2buf, x, ln1g, ln1b, ubuf, uh);

    // FFN: w1 (relu, fp16 out), w2 (split-K=2) + LN2 (fused add)
    {
        GemmPtrs gp{};
        gp.A[0] = uh; gp.W[0] = w1h; gp.Ch[0] = h1h; gp.bias[0] = w1b;
        gemm16_kernel<<<dim3(32, 16, 1), blk, GEMM16_SMEM>>>(
            gp, ROWS_X, FFDIM, DMODEL, DMODEL, 1);
    }
    {
        GemmPtrs gp{};
        gp.A[0] = h1h;        gp.W[0] = w2h;        gp.C[0] = tbuf;  gp.bias[0] = w2b;
        gp.A[1] = h1h + 2048; gp.W[1] = w2h + 2048; gp.C[1] = t2buf;
        gemm16_kernel<<<dim3(8, 16, 2), blk, GEMM16_SMEM>>>(
            gp, ROWS_X, DMODEL, 2048, FFDIM, 0);
    }
    ln_kernel<<<ROWS_X, blk>>>(tbuf, t2buf, ubuf, ln2g, ln2b, out, nullptr);
}

// round 11
// speedup vs baseline: 1.8431x; 1.2507x over previous
#include <cuda_runtime.h>
#include <cuda_fp16.h>
#include <math.h>
#include <stdint.h>

// Problem constants
#define S_LEN 1024
#define BATCH 2
#define DMODEL 1024
#define HEADS 16
#define HDIM 64
#define TLEN 2048
#define FFDIM 4096
#define ROWS_X (S_LEN * BATCH)     // 2048
#define ROWS_T (TLEN * BATCH)      // 4096

// ---------------- scratch buffers (device globals) ---------------------------
__device__ float g_ke[ROWS_T * DMODEL];
__device__ float g_kr[ROWS_T * DMODEL];
__device__ float g_v [ROWS_T * DMODEL];
__device__ float g_t [ROWS_X * DMODEL];
__device__ float g_t2[ROWS_X * DMODEL];
__device__ float g_u [ROWS_X * DMODEL];
// fp16 tensors
__device__ __half g_xh  [ROWS_X * DMODEL];
__device__ __half g_memh[ROWS_X * DMODEL];
__device__ __half g_ph  [ROWS_T * DMODEL];
__device__ __half g_wqh [DMODEL * DMODEL];
__device__ __half g_wkeh[DMODEL * DMODEL];
__device__ __half g_wkrh[DMODEL * DMODEL];
__device__ __half g_wvh [DMODEL * DMODEL];
__device__ __half g_wch [DMODEL * DMODEL];
__device__ __half g_w1h [FFDIM * DMODEL];
__device__ __half g_w2h [DMODEL * FFDIM];
__device__ __half g_qh  [ROWS_X * DMODEL];
__device__ __half g_avh [ROWS_X * DMODEL];
__device__ __half g_uh  [ROWS_X * DMODEL];
__device__ __half g_h1h [ROWS_X * FFDIM];
// flash-prep outputs (fp16 KK / V, fp32 bias)
__device__ __half g_kkh [BATCH * HEADS * TLEN * HDIM];
__device__ __half g_vh  [BATCH * HEADS * TLEN * HDIM];
__device__ float  g_bias[BATCH * HEADS * TLEN];

// ---------------- common PTX helpers ----------------------------------------
__device__ __forceinline__ void cp_async16(uint32_t saddr, const void* gptr) {
    asm volatile("cp.async.cg.shared.global [%0], [%1], 16;\n"
                 :: "r"(saddr), "l"(gptr));
}
__device__ __forceinline__ void cp_commit() {
    asm volatile("cp.async.commit_group;\n");
}
template <int N>
__device__ __forceinline__ void cp_wait() {
    asm volatile("cp.async.wait_group %0;\n" :: "n"(N));
}
__device__ __forceinline__ void mma_f16(float* d, const uint32_t* a, const uint32_t* b) {
    asm volatile(
        "mma.sync.aligned.m16n8k16.row.col.f32.f16.f16.f32 "
        "{%0,%1,%2,%3}, {%4,%5,%6,%7}, {%8,%9}, {%0,%1,%2,%3};\n"
        : "+f"(d[0]), "+f"(d[1]), "+f"(d[2]), "+f"(d[3])
        : "r"(a[0]), "r"(a[1]), "r"(a[2]), "r"(a[3]), "r"(b[0]), "r"(b[1]));
}
__device__ __forceinline__ void ldm_x4(uint32_t* r, uint32_t addr) {
    asm volatile("ldmatrix.sync.aligned.m8n8.x4.shared.b16 {%0,%1,%2,%3}, [%4];"
                 : "=r"(r[0]), "=r"(r[1]), "=r"(r[2]), "=r"(r[3]) : "r"(addr));
}
__device__ __forceinline__ void ldm_x4_t(uint32_t* r, uint32_t addr) {
    asm volatile("ldmatrix.sync.aligned.m8n8.x4.trans.shared.b16 {%0,%1,%2,%3}, [%4];"
                 : "=r"(r[0]), "=r"(r[1]), "=r"(r[2]), "=r"(r[3]) : "r"(addr));
}

// ---------------- fp32 -> fp16 conversion (merged segments) ------------------
#define MAXSEG 10
struct CvtSegs {
    const float* src[MAXSEG];
    __half*      dst[MAXSEG];
    int          end8[MAXSEG];
    int          nseg;
};

__global__ void __launch_bounds__(256)
cvt_all_kernel(CvtSegs segs, int total8)
{
    int idx = blockIdx.x * 256 + threadIdx.x;
    if (idx >= total8) return;
    int s = 0;
#pragma unroll
    for (int i = 0; i < MAXSEG; i++)
        if (i < segs.nseg && idx >= segs.end8[i]) s = i + 1;
    const int off = idx - (s ? segs.end8[s - 1] : 0);

    const float4* s4 = (const float4*)(segs.src[s] + (size_t)off * 8);
    float4 a = s4[0], b = s4[1];
    __half2 h[4];
    h[0] = __floats2half2_rn(a.x, a.y);
    h[1] = __floats2half2_rn(a.z, a.w);
    h[2] = __floats2half2_rn(b.x, b.y);
    h[3] = __floats2half2_rn(b.z, b.w);
    *(uint4*)(segs.dst[s] + (size_t)off * 8) = *(uint4*)h;
}

// ---------------- fp16 tensor-core GEMM (unchanged from R10) -----------------
struct GemmPtrs {
    const __half* A[7];
    const __half* W[7];
    float*        C[7];
    __half*       Ch[7];
    const float*  bias[7];
};

#define HROW 144u                      // smem row stride in bytes (72 halves)
#define TILE16 (128u * HROW)           // 18432 B per operand tile
#define STAGE16 (2u * TILE16)          // 36864 B per stage
#define GEMM16_SMEM (2 * 36864)        // 73728 B

__global__ void __launch_bounds__(256)
gemm16_kernel(GemmPtrs ptrs, int M, int N, int Klen, int Kstride, int act)
{
    extern __shared__ char smem[];
    const uint32_t sbase = (uint32_t)__cvta_generic_to_shared(smem);

    const __half* A    = ptrs.A[blockIdx.z];
    const __half* W    = ptrs.W[blockIdx.z];
    float*        C    = ptrs.C[blockIdx.z];
    __half*       Ch   = ptrs.Ch[blockIdx.z];
    const float*  bias = ptrs.bias[blockIdx.z];

    const int tid = threadIdx.x;
    const int lane = tid & 31, wrp = tid >> 5;
    const int wm = wrp & 1, wn = wrp >> 1;
    const int q = lane >> 2, r = lane & 3;
    const int m0 = blockIdx.y * 128;
    const int n0 = blockIdx.x * 128;

    float acc[4][4][4];
#pragma unroll
    for (int i = 0; i < 4; i++)
#pragma unroll
        for (int j = 0; j < 4; j++)
#pragma unroll
            for (int e = 0; e < 4; e++) acc[i][j][e] = 0.f;

    auto issue = [&](int buf, int k0) {   // k0 in halves
        const uint32_t so = sbase + (uint32_t)buf * STAGE16;
#pragma unroll
        for (int i = 0; i < 2; i++) {
            int id = tid + i * 256;            // 0..511
            int row = id >> 2, c = id & 3;
            uint32_t d = (uint32_t)row * HROW + (uint32_t)c * 16u;
            cp_async16(so + d,          A + (size_t)(m0 + row) * Kstride + k0 + c * 8);
            cp_async16(so + TILE16 + d, W + (size_t)(n0 + row) * Kstride + k0 + c * 8);
        }
    };

    const int KT = Klen >> 5;
    issue(0, 0);
    cp_commit();

    const int alr = lane & 15, alc = lane >> 4;
    const int bg = lane >> 3,  blr = lane & 7;

    for (int kt = 0; kt < KT; kt++) {
        const int cur = kt & 1;
        if (kt + 1 < KT) {
            issue(cur ^ 1, (kt + 1) << 5);
            cp_commit();
            cp_wait<1>();
        } else {
            cp_wait<0>();
        }
        __syncthreads();

        const uint32_t aBase = sbase + (uint32_t)cur * STAGE16;
        const uint32_t bBase = aBase + TILE16;

#pragma unroll
        for (int ks = 0; ks < 2; ks++) {
            uint32_t afr[4][4];
#pragma unroll
            for (int mt = 0; mt < 4; mt++) {
                uint32_t addr = aBase +
                    (uint32_t)(wm * 64 + mt * 16 + alr) * HROW +
                    (uint32_t)(ks * 32 + alc * 16);
                ldm_x4(afr[mt], addr);
            }
            uint32_t bfr[4][2];
#pragma unroll
            for (int ntp = 0; ntp < 2; ntp++) {
                uint32_t addr = bBase +
                    (uint32_t)(wn * 32 + ntp * 16 + (bg >> 1) * 8 + blr) * HROW +
                    (uint32_t)(ks * 32 + (bg & 1) * 16);
                uint32_t tmp[4];
                ldm_x4(tmp, addr);
                bfr[ntp * 2 + 0][0] = tmp[0]; bfr[ntp * 2 + 0][1] = tmp[1];
                bfr[ntp * 2 + 1][0] = tmp[2]; bfr[ntp * 2 + 1][1] = tmp[3];
            }
#pragma unroll
            for (int mt = 0; mt < 4; mt++)
#pragma unroll
                for (int nt = 0; nt < 4; nt++)
                    mma_f16(acc[mt][nt], afr[mt], bfr[nt]);
        }
        __syncthreads();
    }

#pragma unroll
    for (int mt = 0; mt < 4; mt++) {
        const int row0 = m0 + wm * 64 + mt * 16 + q;
#pragma unroll
        for (int nt = 0; nt < 4; nt++) {
            const int col = n0 + wn * 32 + nt * 8 + r * 2;
            float b0 = bias ? bias[col]     : 0.f;
            float b1 = bias ? bias[col + 1] : 0.f;
            float v0 = acc[mt][nt][0] + b0, v1 = acc[mt][nt][1] + b1;
            float v2 = acc[mt][nt][2] + b0, v3 = acc[mt][nt][3] + b1;
            if (act == 1) {
                v0 = fmaxf(v0, 0.f); v1 = fmaxf(v1, 0.f);
                v2 = fmaxf(v2, 0.f); v3 = fmaxf(v3, 0.f);
            }
            if (C) {
                *(float2*)(C + (size_t)row0 * N + col)       = make_float2(v0, v1);
                *(float2*)(C + (size_t)(row0 + 8) * N + col) = make_float2(v2, v3);
            }
            if (Ch) {
                *(__half2*)(Ch + (size_t)row0 * N + col)       = __floats2half2_rn(v0, v1);
                *(__half2*)(Ch + (size_t)(row0 + 8) * N + col) = __floats2half2_rn(v2, v3);
            }
        }
    }
}

// ---------------- prep: KK = ke+kr (fp16), bias = u.ke + v.kr, V fp16 --------
__global__ void __launch_bounds__(256)
prep_kernel(const float* __restrict__ ke, const float* __restrict__ kr,
            const float* __restrict__ v,
            const float* __restrict__ ub, const float* __restrict__ vb,
            __half* __restrict__ kkh, __half* __restrict__ vh,
            float* __restrict__ biasO)
{
    const int row = blockIdx.x;          // = t*BATCH + b
    const int t = row / BATCH, b = row % BATCH;
    const int tid = threadIdx.x;
    const int h = tid >> 4, l16 = tid & 15, d0 = l16 * 4;

    const size_t src = (size_t)row * DMODEL + h * HDIM + d0;
    float4 kev = *(const float4*)(ke + src);
    float4 krv = *(const float4*)(kr + src);
    float4 vv  = *(const float4*)(v  + src);

    const size_t dst = ((size_t)(b * HEADS + h) * TLEN + t) * HDIM + d0;
    __half2 kk01 = __floats2half2_rn(kev.x + krv.x, kev.y + krv.y);
    __half2 kk23 = __floats2half2_rn(kev.z + krv.z, kev.w + krv.w);
    __half2 v01  = __floats2half2_rn(vv.x, vv.y);
    __half2 v23  = __floats2half2_rn(vv.z, vv.w);
    *(uint2*)(kkh + dst) = make_uint2(*(uint32_t*)&kk01, *(uint32_t*)&kk23);
    *(uint2*)(vh  + dst) = make_uint2(*(uint32_t*)&v01,  *(uint32_t*)&v23);

    float4 u4 = *(const float4*)(ub + h * HDIM + d0);
    float4 w4 = *(const float4*)(vb + h * HDIM + d0);
    float bsum = u4.x * kev.x + u4.y * kev.y + u4.z * kev.z + u4.w * kev.w
               + w4.x * krv.x + w4.y * krv.y + w4.z * krv.z + w4.w * krv.w;
#pragma unroll
    for (int off = 8; off; off >>= 1)
        bsum += __shfl_xor_sync(0xffffffffu, bsum, off, 16);
    if (l16 == 0) biasO[(size_t)(b * HEADS + h) * TLEN + t] = bsum;
}

// ---------------- fp16 tensor-core flash attention ---------------------------
// Query tile 128, key tile 64. 8 warps x 16 query rows. fp16 mma m16n8k16.
// smem (bytes): QH 128x144 | PH 128x144 | KKH 64x144 | VH 64x144 | bias 2x256
#define QH_OFF 0u
#define PH_OFF 18432u
#define KK_OFF 36864u
#define V_OFF  46080u
#define BI_OFF 55296u
#define FLASH_SMEM 55808

__global__ void __launch_bounds__(256, 2)
flash16_kernel(const __half* __restrict__ qh,
               const __half* __restrict__ kkh,
               const __half* __restrict__ vhg,
               const float* __restrict__ biasG,
               __half* __restrict__ out)
{
    extern __shared__ char fsm[];
    const uint32_t sbase = (uint32_t)__cvta_generic_to_shared(fsm);
    __half* PhH = (__half*)(fsm + PH_OFF);
    const float* biasS = (const float*)(fsm + BI_OFF);

    const int qb = blockIdx.x, h = blockIdx.y, b = blockIdx.z;
    const int tid = threadIdx.x;
    const int lane = tid & 31, wid = tid >> 5;
    const int q = lane >> 2, r = lane & 3;
    const int mw = wid * 16;
    const int alr = lane & 15, alc = lane >> 4;
    const int bg = lane >> 3,  blr = lane & 7;

    const size_t  bh   = (size_t)(b * HEADS + h) * TLEN;
    const __half* kkbh = kkh + bh * HDIM;
    const __half* vbh  = vhg + bh * HDIM;
    const float*  bibh = biasG + bh;

    auto issueQ = [&]() {
#pragma unroll
        for (int it = 0; it < 4; it++) {
            int idx = tid + it * 256;            // 1024 chunks
            int row = idx >> 3, c = idx & 7;
            cp_async16(sbase + QH_OFF + (uint32_t)row * HROW + (uint32_t)c * 16u,
                       qh + ((size_t)((qb * 128 + row) * BATCH + b)) * DMODEL
                          + h * HDIM + c * 8);
        }
    };
    auto issueKK = [&](int t0, int pb) {
#pragma unroll
        for (int it = 0; it < 2; it++) {
            int idx = tid + it * 256;            // 512 chunks
            int row = idx >> 3, c = idx & 7;
            cp_async16(sbase + KK_OFF + (uint32_t)row * HROW + (uint32_t)c * 16u,
                       kkbh + (size_t)(t0 + row) * HDIM + c * 8);
        }
        if (tid < 16)
            cp_async16(sbase + BI_OFF + (uint32_t)(pb * 256 + tid * 16),
                       bibh + t0 + tid * 4);
    };
    auto issueV = [&](int t0) {
#pragma unroll
        for (int it = 0; it < 2; it++) {
            int idx = tid + it * 256;
            int row = idx >> 3, c = idx & 7;
            cp_async16(sbase + V_OFF + (uint32_t)row * HROW + (uint32_t)c * 16u,
                       vbh + (size_t)(t0 + row) * HDIM + c * 8);
        }
    };

    // prologue: groups [Q] [KK0+bias] [V0]
    issueQ();
    cp_commit();
    issueKK(0, 0);
    cp_commit();
    issueV(0);
    cp_commit();

    float m0 = -1e30f, m1 = -1e30f, l0 = 0.f, l1 = 0.f;
    float O[8][4];
#pragma unroll
    for (int nt = 0; nt < 8; nt++)
#pragma unroll
        for (int e = 0; e < 4; e++) O[nt][e] = 0.f;

    const int ntiles = 18 + 2 * qb;
    const int srow0 = qb * 128 + mw + q;

    for (int tt = 0; tt < ntiles; tt++) {
        const int t0 = tt * 64;
        const int pb = tt & 1;
        const bool more = (tt + 1 < ntiles);

        cp_wait<1>();          // Q (tt=0) + KK(tt)+bias complete; V(tt) pending
        __syncthreads();

        // ---- S = Q @ KK^T  (fp16 mma) --------------------------------------
        float sc[8][4];
#pragma unroll
        for (int nt = 0; nt < 8; nt++)
#pragma unroll
            for (int e = 0; e < 4; e++) sc[nt][e] = 0.f;

#pragma unroll
        for (int ks = 0; ks < 4; ks++) {
            uint32_t afr[4];
            ldm_x4(afr, sbase + QH_OFF + (uint32_t)(mw + alr) * HROW
                         + (uint32_t)(ks * 32 + alc * 16));
#pragma unroll
            for (int tb = 0; tb < 4; tb++) {
                uint32_t tmp[4];
                ldm_x4(tmp, sbase + KK_OFF
                             + (uint32_t)(tb * 16 + (bg >> 1) * 8 + blr) * HROW
                             + (uint32_t)(ks * 32 + (bg & 1) * 16));
                mma_f16(sc[tb * 2],     afr, tmp);
                mma_f16(sc[tb * 2 + 1], afr, tmp + 2);
            }
        }
        __syncthreads();       // all warps done reading KKH

        if (more) { issueKK(t0 + 64, pb ^ 1); cp_commit(); }

        // ---- bias + scale + causal mask + online softmax --------------------
        const float* bS = biasS + pb * 64;
        const bool mt_ = (tt >= 16 + 2 * qb);
        float tmax0 = -1e30f, tmax1 = -1e30f;
#pragma unroll
        for (int nt = 0; nt < 8; nt++) {
            const int colb = nt * 8 + 2 * r;
            const float bi0 = bS[colb], bi1 = bS[colb + 1];
            float v0 = (sc[nt][0] + bi0) * 0.125f;
            float v1 = (sc[nt][1] + bi1) * 0.125f;
            float v2 = (sc[nt][2] + bi0) * 0.125f;
            float v3 = (sc[nt][3] + bi1) * 0.125f;
            if (mt_) {
                const int tc = t0 + colb;
                if (tc     > S_LEN + srow0)     v0 = -1e30f;
                if (tc + 1 > S_LEN + srow0)     v1 = -1e30f;
                if (tc     > S_LEN + srow0 + 8) v2 = -1e30f;
                if (tc + 1 > S_LEN + srow0 + 8) v3 = -1e30f;
            }
            sc[nt][0] = v0; sc[nt][1] = v1; sc[nt][2] = v2; sc[nt][3] = v3;
            tmax0 = fmaxf(tmax0, fmaxf(v0, v1));
            tmax1 = fmaxf(tmax1, fmaxf(v2, v3));
        }
        tmax0 = fmaxf(tmax0, __shfl_xor_sync(0xffffffffu, tmax0, 1));
        tmax0 = fmaxf(tmax0, __shfl_xor_sync(0xffffffffu, tmax0, 2));
        tmax1 = fmaxf(tmax1, __shfl_xor_sync(0xffffffffu, tmax1, 1));
        tmax1 = fmaxf(tmax1, __shfl_xor_sync(0xffffffffu, tmax1, 2));

        const float mnew0 = fmaxf(m0, tmax0);
        const float mnew1 = fmaxf(m1, tmax1);
        const float c0 = __expf(m0 - mnew0);
        const float c1 = __expf(m1 - mnew1);
        m0 = mnew0; m1 = mnew1;
        l0 *= c0; l1 *= c1;

        float ps0 = 0.f, ps1 = 0.f;
#pragma unroll
        for (int nt = 0; nt < 8; nt++) {
            float p0 = __expf(sc[nt][0] - mnew0);
            float p1 = __expf(sc[nt][1] - mnew0);
            float p2 = __expf(sc[nt][2] - mnew1);
            float p3 = __expf(sc[nt][3] - mnew1);
            ps0 += p0 + p1; ps1 += p2 + p3;
            O[nt][0] *= c0; O[nt][1] *= c0;
            O[nt][2] *= c1; O[nt][3] *= c1;
            const int colp = nt * 8 + 2 * r;
            *(__half2*)&PhH[(size_t)(mw + q) * 72 + colp]     = __floats2half2_rn(p0, p1);
            *(__half2*)&PhH[(size_t)(mw + q + 8) * 72 + colp] = __floats2half2_rn(p2, p3);
        }
        l0 += ps0; l1 += ps1;
        __syncwarp();

        // ---- ensure V(tt) landed, then O += P @ V ---------------------------
        if (more) { cp_wait<1>(); } else { cp_wait<0>(); }
        __syncthreads();

#pragma unroll
        for (int ks = 0; ks < 4; ks++) {
            uint32_t afr[4];
            ldm_x4(afr, sbase + PH_OFF + (uint32_t)(mw + alr) * HROW
                         + (uint32_t)(ks * 32 + alc * 16));
#pragma unroll
            for (int dp = 0; dp < 4; dp++) {
                uint32_t tmp[4];
                ldm_x4_t(tmp, sbase + V_OFF
                               + (uint32_t)(ks * 16 + (bg & 1) * 8 + blr) * HROW
                               + (uint32_t)(dp * 32 + (bg >> 1) * 16));
                mma_f16(O[dp * 2],     afr, tmp);
                mma_f16(O[dp * 2 + 1], afr, tmp + 2);
            }
        }
        __syncthreads();       // all warps done reading VH

        if (more) { issueV(t0 + 64); cp_commit(); }
    }

    // ---- finalize: reduce l over quad, normalize, store fp16 ---------------
    l0 += __shfl_xor_sync(0xffffffffu, l0, 1);
    l0 += __shfl_xor_sync(0xffffffffu, l0, 2);
    l1 += __shfl_xor_sync(0xffffffffu, l1, 1);
    l1 += __shfl_xor_sync(0xffffffffu, l1, 2);
    const float inv0 = 1.f / l0, inv1 = 1.f / l1;

#pragma unroll
    for (int nt = 0; nt < 8; nt++) {
        const int col = nt * 8 + 2 * r;
        const int row0 = qb * 128 + mw + q;
        *(__half2*)(out + ((size_t)(row0 * BATCH + b)) * DMODEL + h * HDIM + col)
            = __floats2half2_rn(O[nt][0] * inv0, O[nt][1] * inv0);
        *(__half2*)(out + ((size_t)((row0 + 8) * BATCH + b)) * DMODEL + h * HDIM + col)
            = __floats2half2_rn(O[nt][2] * inv1, O[nt][3] * inv1);
    }
}

// ---------------- LayerNorm(a0 [+ a1] + res) * g + b -------------------------
__global__ void __launch_bounds__(256)
ln_kernel(const float* __restrict__ a0, const float* __restrict__ a1,
          const float* __restrict__ res,
          const float* __restrict__ g, const float* __restrict__ bta,
          float* __restrict__ out, __half* __restrict__ out_h)
{
    const int row = blockIdx.x;
    const int tid = threadIdx.x;
    const int lane = tid & 31, wrp = tid >> 5;
    __shared__ float red[8];
    __shared__ float bc;

    float vals[4];
    float s = 0.f;
    const float* ar = a0 + (size_t)row * DMODEL;
    const float* br = a1 ? a1 + (size_t)row * DMODEL : nullptr;
    const float* rr = res + (size_t)row * DMODEL;
#pragma unroll
    for (int i = 0; i < 4; i++) {
        int d = tid + i * 256;
        float v = ar[d] + rr[d];
        if (br) v += br[d];
        vals[i] = v;
        s += v;
    }
#pragma unroll
    for (int off = 16; off; off >>= 1) s += __shfl_xor_sync(0xffffffffu, s, off);
    if (lane == 0) red[wrp] = s;
    __syncthreads();
    if (tid == 0) {
        float t = 0.f;
#pragma unroll
        for (int w = 0; w < 8; w++) t += red[w];
        bc = t * (1.f / DMODEL);
    }
    __syncthreads();
    const float mu = bc;

    float vs = 0.f;
#pragma unroll
    for (int i = 0; i < 4; i++) {
        float dd = vals[i] - mu;
        vs += dd * dd;
    }
#pragma unroll
    for (int off = 16; off; off >>= 1) vs += __shfl_xor_sync(0xffffffffu, vs, off);
    __syncthreads();
    if (lane == 0) red[wrp] = vs;
    __syncthreads();
    if (tid == 0) {
        float t = 0.f;
#pragma unroll
        for (int w = 0; w < 8; w++) t += red[w];
        bc = rsqrtf(t * (1.f / DMODEL) + 1e-5f);
    }
    __syncthreads();
    const float rstd = bc;

    float* orow = out + (size_t)row * DMODEL;
    __half* hrow = out_h ? out_h + (size_t)row * DMODEL : nullptr;
#pragma unroll
    for (int i = 0; i < 4; i++) {
        int d = tid + i * 256;
        float vv = (vals[i] - mu) * rstd * g[d] + bta[d];
        orow[d] = vv;
        if (hrow) hrow[d] = __float2half(vv);
    }
}

// ---------------- launcher ---------------------------------------------------
extern "C" void kernel_launch(void* const* d_in, const int* in_sizes, int n_in,
                              void* d_out, int out_size)
{
    const float* x      = (const float*)d_in[0];
    const float* p      = (const float*)d_in[1];
    /* mask d_in[2] is analytic: unused */
    const float* memory = (const float*)d_in[3];
    const float* u_bias = (const float*)d_in[4];
    const float* v_bias = (const float*)d_in[5];
    const float* wq  = (const float*)d_in[6];
    const float* wke = (const float*)d_in[7];
    const float* wkr = (const float*)d_in[8];
    const float* wv  = (const float*)d_in[9];
    const float* wc  = (const float*)d_in[10];
    const float* w1  = (const float*)d_in[11];
    const float* w1b = (const float*)d_in[12];
    const float* w2  = (const float*)d_in[13];
    const float* w2b = (const float*)d_in[14];
    const float* ln1g = (const float*)d_in[15];
    const float* ln1b = (const float*)d_in[16];
    const float* ln2g = (const float*)d_in[17];
    const float* ln2b = (const float*)d_in[18];
    float* out = (float*)d_out;

    float *ke, *kr, *v, *tbuf, *t2buf, *ubuf, *bias2;
    __half *xh, *memh, *ph, *wqh, *wkeh, *wkrh, *wvh, *wch, *w1h, *w2h;
    __half *qh, *avh, *uh, *h1h, *kkh, *vh;
    cudaGetSymbolAddress((void**)&ke,    g_ke);
    cudaGetSymbolAddress((void**)&kr,    g_kr);
    cudaGetSymbolAddress((void**)&v,     g_v);
    cudaGetSymbolAddress((void**)&tbuf,  g_t);
    cudaGetSymbolAddress((void**)&t2buf, g_t2);
    cudaGetSymbolAddress((void**)&ubuf,  g_u);
    cudaGetSymbolAddress((void**)&xh,    g_xh);
    cudaGetSymbolAddress((void**)&memh,  g_memh);
    cudaGetSymbolAddress((void**)&ph,    g_ph);
    cudaGetSymbolAddress((void**)&wqh,   g_wqh);
    cudaGetSymbolAddress((void**)&wkeh,  g_wkeh);
    cudaGetSymbolAddress((void**)&wkrh,  g_wkrh);
    cudaGetSymbolAddress((void**)&wvh,   g_wvh);
    cudaGetSymbolAddress((void**)&wch,   g_wch);
    cudaGetSymbolAddress((void**)&w1h,   g_w1h);
    cudaGetSymbolAddress((void**)&w2h,   g_w2h);
    cudaGetSymbolAddress((void**)&qh,    g_qh);
    cudaGetSymbolAddress((void**)&avh,   g_avh);
    cudaGetSymbolAddress((void**)&uh,    g_uh);
    cudaGetSymbolAddress((void**)&h1h,   g_h1h);
    cudaGetSymbolAddress((void**)&kkh,   g_kkh);
    cudaGetSymbolAddress((void**)&vh,    g_vh);
    cudaGetSymbolAddress((void**)&bias2, g_bias);

    cudaFuncSetAttribute(gemm16_kernel,
                         cudaFuncAttributeMaxDynamicSharedMemorySize, GEMM16_SMEM);
    cudaFuncSetAttribute(flash16_kernel,
                         cudaFuncAttributeMaxDynamicSharedMemorySize, FLASH_SMEM);

    const dim3 blk(256);
    const size_t half = (size_t)ROWS_X * DMODEL;

    // ---- convert inputs + weights to fp16 (one merged launch) ---------------
    {
        CvtSegs cs{};
        int acc = 0, i = 0;
        auto add = [&](const float* s, __half* d, int n8) {
            cs.src[i] = s; cs.dst[i] = d; acc += n8; cs.end8[i] = acc; i++;
        };
        add(x,      xh,   ROWS_X * DMODEL / 8);
        add(memory, memh, ROWS_X * DMODEL / 8);
        add(p,      ph,   ROWS_T * DMODEL / 8);
        add(wq,  wqh,  DMODEL * DMODEL / 8);
        add(wke, wkeh, DMODEL * DMODEL / 8);
        add(wkr, wkrh, DMODEL * DMODEL / 8);
        add(wv,  wvh,  DMODEL * DMODEL / 8);
        add(wc,  wch,  DMODEL * DMODEL / 8);
        add(w1,  w1h,  FFDIM * DMODEL / 8);
        add(w2,  w2h,  FFDIM * DMODEL / 8);
        cs.nseg = i;
        cvt_all_kernel<<<(acc + 255) / 256, blk>>>(cs, acc);
    }

    // ---- all 6 projections in ONE launch (z = 0..6), fp16 mma ---------------
    // q emitted fp16 (flash consumes fp16 directly); ke/kr/v fp32 (prep input)
    {
        GemmPtrs gp{};
        gp.A[0] = xh;   gp.W[0] = wqh;  gp.Ch[0] = qh;
        gp.A[1] = xh;   gp.W[1] = wkeh; gp.C[1] = ke + half;
        gp.A[2] = xh;   gp.W[2] = wvh;  gp.C[2] = v + half;
        gp.A[3] = memh; gp.W[3] = wkeh; gp.C[3] = ke;
        gp.A[4] = memh; gp.W[4] = wvh;  gp.C[4] = v;
        gp.A[5] = ph;        gp.W[5] = wkrh; gp.C[5] = kr;
        gp.A[6] = ph + half; gp.W[6] = wkrh; gp.C[6] = kr + half;
        gemm16_kernel<<<dim3(8, 16, 7), blk, GEMM16_SMEM>>>(
            gp, ROWS_X, DMODEL, DMODEL, DMODEL, 0);
    }

    // prep: fuse KK (fp16), bias (fp32), V (fp16)
    prep_kernel<<<ROWS_T, blk>>>(ke, kr, v, u_bias, v_bias, kkh, vh, bias2);

    // fp16 flash attention
    flash16_kernel<<<dim3(8, HEADS, BATCH), blk, FLASH_SMEM>>>(
        qh, kkh, vh, bias2, avh);

    // output proj (split-K=2) + LN1 (fused add; emits uh fp16)
    {
        GemmPtrs gp{};
        gp.A[0] = avh;       gp.W[0] = wch;       gp.C[0] = tbuf;
        gp.A[1] = avh + 512; gp.W[1] = wch + 512; gp.C[1] = t2buf;
        gemm16_kernel<<<dim3(8, 16, 2), blk, GEMM16_SMEM>>>(
            gp, ROWS_X, DMODEL, 512, DMODEL, 0);
    }
    ln_kernel<<<ROWS_X, blk>>>(tbuf, t2buf, x, ln1g, ln1b, ubuf, uh);

    // FFN: w1 (relu, fp16 out), w2 (split-K=2) + LN2 (fused add)
    {
        GemmPtrs gp{};
        gp.A[0] = uh; gp.W[0] = w1h; gp.Ch[0] = h1h; gp.bias[0] = w1b;
        gemm16_kernel<<<dim3(32, 16, 1), blk, GEMM16_SMEM>>>(
            gp, ROWS_X, FFDIM, DMODEL, DMODEL, 1);
    }
    {
        GemmPtrs gp{};
        gp.A[0] = h1h;        gp.W[0] = w2h;        gp.C[0] = tbuf;  gp.bias[0] = w2b;
        gp.A[1] = h1h + 2048; gp.W[1] = w2h + 2048; gp.C[1] = t2buf;
        gemm16_kernel<<<dim3(8, 16, 2), blk, GEMM16_SMEM>>>(
            gp, ROWS_X, DMODEL, 2048, FFDIM, 0);
    }
    ln_kernel<<<ROWS_X, blk>>>(tbuf, t2buf, ubuf, ln2g, ln2b, out, nullptr);
}

// round 12
// speedup vs baseline: 1.8926x; 1.0268x over previous
#include <cuda_runtime.h>
#include <cuda_fp16.h>
#include <math.h>
#include <stdint.h>

// Problem constants
#define S_LEN 1024
#define BATCH 2
#define DMODEL 1024
#define HEADS 16
#define HDIM 64
#define TLEN 2048
#define FFDIM 4096
#define ROWS_X (S_LEN * BATCH)     // 2048
#define ROWS_T (TLEN * BATCH)      // 4096

// ---------------- scratch buffers (device globals) ---------------------------
__device__ float g_ke[ROWS_T * DMODEL];
__device__ float g_kr[ROWS_T * DMODEL];
__device__ float g_v [ROWS_T * DMODEL];
__device__ float g_t [ROWS_X * DMODEL];
__device__ float g_t2[ROWS_X * DMODEL];
__device__ float g_u [ROWS_X * DMODEL];
// fp16 tensors
__device__ __half g_xh  [ROWS_X * DMODEL];
__device__ __half g_memh[ROWS_X * DMODEL];
__device__ __half g_ph  [ROWS_T * DMODEL];
__device__ __half g_wqh [DMODEL * DMODEL];
__device__ __half g_wkeh[DMODEL * DMODEL];
__device__ __half g_wkrh[DMODEL * DMODEL];
__device__ __half g_wvh [DMODEL * DMODEL];
__device__ __half g_wch [DMODEL * DMODEL];
__device__ __half g_w1h [FFDIM * DMODEL];
__device__ __half g_w2h [DMODEL * FFDIM];
__device__ __half g_qh  [ROWS_X * DMODEL];
__device__ __half g_avh [ROWS_X * DMODEL];
__device__ __half g_uh  [ROWS_X * DMODEL];
__device__ __half g_h1h [ROWS_X * FFDIM];
// flash-prep outputs (fp16 KK / V, fp32 bias pre-scaled by 0.125)
__device__ __half g_kkh [BATCH * HEADS * TLEN * HDIM];
__device__ __half g_vh  [BATCH * HEADS * TLEN * HDIM];
__device__ float  g_bias[BATCH * HEADS * TLEN];

// ---------------- common PTX helpers ----------------------------------------
__device__ __forceinline__ void cp_async16(uint32_t saddr, const void* gptr) {
    asm volatile("cp.async.cg.shared.global [%0], [%1], 16;\n"
                 :: "r"(saddr), "l"(gptr));
}
__device__ __forceinline__ void cp_commit() {
    asm volatile("cp.async.commit_group;\n");
}
template <int N>
__device__ __forceinline__ void cp_wait() {
    asm volatile("cp.async.wait_group %0;\n" :: "n"(N));
}
__device__ __forceinline__ void mma_f16(float* d, const uint32_t* a, const uint32_t* b) {
    asm volatile(
        "mma.sync.aligned.m16n8k16.row.col.f32.f16.f16.f32 "
        "{%0,%1,%2,%3}, {%4,%5,%6,%7}, {%8,%9}, {%0,%1,%2,%3};\n"
        : "+f"(d[0]), "+f"(d[1]), "+f"(d[2]), "+f"(d[3])
        : "r"(a[0]), "r"(a[1]), "r"(a[2]), "r"(a[3]), "r"(b[0]), "r"(b[1]));
}
__device__ __forceinline__ void ldm_x4(uint32_t* r, uint32_t addr) {
    asm volatile("ldmatrix.sync.aligned.m8n8.x4.shared.b16 {%0,%1,%2,%3}, [%4];"
                 : "=r"(r[0]), "=r"(r[1]), "=r"(r[2]), "=r"(r[3]) : "r"(addr));
}
__device__ __forceinline__ void ldm_x4_t(uint32_t* r, uint32_t addr) {
    asm volatile("ldmatrix.sync.aligned.m8n8.x4.trans.shared.b16 {%0,%1,%2,%3}, [%4];"
                 : "=r"(r[0]), "=r"(r[1]), "=r"(r[2]), "=r"(r[3]) : "r"(addr));
}

// ---------------- fp32 -> fp16 conversion (merged segments) ------------------
#define MAXSEG 10
struct CvtSegs {
    const float* src[MAXSEG];
    __half*      dst[MAXSEG];
    int          end8[MAXSEG];
    int          nseg;
};

__global__ void __launch_bounds__(256)
cvt_all_kernel(CvtSegs segs, int total8)
{
    int idx = blockIdx.x * 256 + threadIdx.x;
    if (idx >= total8) return;
    int s = 0;
#pragma unroll
    for (int i = 0; i < MAXSEG; i++)
        if (i < segs.nseg && idx >= segs.end8[i]) s = i + 1;
    const int off = idx - (s ? segs.end8[s - 1] : 0);

    const float4* s4 = (const float4*)(segs.src[s] + (size_t)off * 8);
    float4 a = s4[0], b = s4[1];
    __half2 h[4];
    h[0] = __floats2half2_rn(a.x, a.y);
    h[1] = __floats2half2_rn(a.z, a.w);
    h[2] = __floats2half2_rn(b.x, b.y);
    h[3] = __floats2half2_rn(b.z, b.w);
    *(uint4*)(segs.dst[s] + (size_t)off * 8) = *(uint4*)h;
}

// ---------------- fp16 tensor-core GEMM (3-stage pipeline) -------------------
struct GemmPtrs {
    const __half* A[7];
    const __half* W[7];
    float*        C[7];
    __half*       Ch[7];
    const float*  bias[7];
};

#define HROW 144u                      // smem row stride in bytes (72 halves)
#define TILE16 (128u * HROW)           // 18432 B per operand tile
#define STAGE16 (2u * TILE16)          // 36864 B per stage
#define GEMM16_SMEM (3 * 36864)        // 110592 B (3 stages)

__global__ void __launch_bounds__(256)
gemm16_kernel(GemmPtrs ptrs, int M, int N, int Klen, int Kstride, int act)
{
    extern __shared__ char smem[];
    const uint32_t sbase = (uint32_t)__cvta_generic_to_shared(smem);

    const __half* A    = ptrs.A[blockIdx.z];
    const __half* W    = ptrs.W[blockIdx.z];
    float*        C    = ptrs.C[blockIdx.z];
    __half*       Ch   = ptrs.Ch[blockIdx.z];
    const float*  bias = ptrs.bias[blockIdx.z];

    const int tid = threadIdx.x;
    const int lane = tid & 31, wrp = tid >> 5;
    const int wm = wrp & 1, wn = wrp >> 1;
    const int q = lane >> 2, r = lane & 3;
    const int m0 = blockIdx.y * 128;
    const int n0 = blockIdx.x * 128;

    float acc[4][4][4];
#pragma unroll
    for (int i = 0; i < 4; i++)
#pragma unroll
        for (int j = 0; j < 4; j++)
#pragma unroll
            for (int e = 0; e < 4; e++) acc[i][j][e] = 0.f;

    auto issue = [&](int t) {              // tile index; stage = t % 3
        const uint32_t so = sbase + (uint32_t)(t % 3) * STAGE16;
        const int k0 = t << 5;             // halves
#pragma unroll
        for (int i = 0; i < 2; i++) {
            int id = tid + i * 256;
            int row = id >> 2, c = id & 3;
            uint32_t d = (uint32_t)row * HROW + (uint32_t)c * 16u;
            cp_async16(so + d,          A + (size_t)(m0 + row) * Kstride + k0 + c * 8);
            cp_async16(so + TILE16 + d, W + (size_t)(n0 + row) * Kstride + k0 + c * 8);
        }
    };

    const int KT = Klen >> 5;
    issue(0);
    cp_commit();
    if (KT > 1) { issue(1); cp_commit(); }

    const int alr = lane & 15, alc = lane >> 4;
    const int bg = lane >> 3,  blr = lane & 7;

    for (int kt = 0; kt < KT; kt++) {
        if (kt == KT - 1) { cp_wait<0>(); } else { cp_wait<1>(); }
        __syncthreads();
        if (kt + 2 < KT) { issue(kt + 2); cp_commit(); }

        const uint32_t aBase = sbase + (uint32_t)(kt % 3) * STAGE16;
        const uint32_t bBase = aBase + TILE16;

#pragma unroll
        for (int ks = 0; ks < 2; ks++) {
            uint32_t afr[4][4];
#pragma unroll
            for (int mt = 0; mt < 4; mt++) {
                uint32_t addr = aBase +
                    (uint32_t)(wm * 64 + mt * 16 + alr) * HROW +
                    (uint32_t)(ks * 32 + alc * 16);
                ldm_x4(afr[mt], addr);
            }
            uint32_t bfr[4][2];
#pragma unroll
            for (int ntp = 0; ntp < 2; ntp++) {
                uint32_t addr = bBase +
                    (uint32_t)(wn * 32 + ntp * 16 + (bg >> 1) * 8 + blr) * HROW +
                    (uint32_t)(ks * 32 + (bg & 1) * 16);
                uint32_t tmp[4];
                ldm_x4(tmp, addr);
                bfr[ntp * 2 + 0][0] = tmp[0]; bfr[ntp * 2 + 0][1] = tmp[1];
                bfr[ntp * 2 + 1][0] = tmp[2]; bfr[ntp * 2 + 1][1] = tmp[3];
            }
#pragma unroll
            for (int mt = 0; mt < 4; mt++)
#pragma unroll
                for (int nt = 0; nt < 4; nt++)
                    mma_f16(acc[mt][nt], afr[mt], bfr[nt]);
        }
    }

#pragma unroll
    for (int mt = 0; mt < 4; mt++) {
        const int row0 = m0 + wm * 64 + mt * 16 + q;
#pragma unroll
        for (int nt = 0; nt < 4; nt++) {
            const int col = n0 + wn * 32 + nt * 8 + r * 2;
            float b0 = bias ? bias[col]     : 0.f;
            float b1 = bias ? bias[col + 1] : 0.f;
            float v0 = acc[mt][nt][0] + b0, v1 = acc[mt][nt][1] + b1;
            float v2 = acc[mt][nt][2] + b0, v3 = acc[mt][nt][3] + b1;
            if (act == 1) {
                v0 = fmaxf(v0, 0.f); v1 = fmaxf(v1, 0.f);
                v2 = fmaxf(v2, 0.f); v3 = fmaxf(v3, 0.f);
            }
            if (C) {
                *(float2*)(C + (size_t)row0 * N + col)       = make_float2(v0, v1);
                *(float2*)(C + (size_t)(row0 + 8) * N + col) = make_float2(v2, v3);
            }
            if (Ch) {
                *(__half2*)(Ch + (size_t)row0 * N + col)       = __floats2half2_rn(v0, v1);
                *(__half2*)(Ch + (size_t)(row0 + 8) * N + col) = __floats2half2_rn(v2, v3);
            }
        }
    }
}

// ---------------- prep: KK = ke+kr (fp16), bias = (u.ke+v.kr)/8, V fp16 ------
__global__ void __launch_bounds__(256)
prep_kernel(const float* __restrict__ ke, const float* __restrict__ kr,
            const float* __restrict__ v,
            const float* __restrict__ ub, const float* __restrict__ vb,
            __half* __restrict__ kkh, __half* __restrict__ vh,
            float* __restrict__ biasO)
{
    const int row = blockIdx.x;          // = t*BATCH + b
    const int t = row / BATCH, b = row % BATCH;
    const int tid = threadIdx.x;
    const int h = tid >> 4, l16 = tid & 15, d0 = l16 * 4;

    const size_t src = (size_t)row * DMODEL + h * HDIM + d0;
    float4 kev = *(const float4*)(ke + src);
    float4 krv = *(const float4*)(kr + src);
    float4 vv  = *(const float4*)(v  + src);

    const size_t dst = ((size_t)(b * HEADS + h) * TLEN + t) * HDIM + d0;
    __half2 kk01 = __floats2half2_rn(kev.x + krv.x, kev.y + krv.y);
    __half2 kk23 = __floats2half2_rn(kev.z + krv.z, kev.w + krv.w);
    __half2 v01  = __floats2half2_rn(vv.x, vv.y);
    __half2 v23  = __floats2half2_rn(vv.z, vv.w);
    *(uint2*)(kkh + dst) = make_uint2(*(uint32_t*)&kk01, *(uint32_t*)&kk23);
    *(uint2*)(vh  + dst) = make_uint2(*(uint32_t*)&v01,  *(uint32_t*)&v23);

    float4 u4 = *(const float4*)(ub + h * HDIM + d0);
    float4 w4 = *(const float4*)(vb + h * HDIM + d0);
    float bsum = u4.x * kev.x + u4.y * kev.y + u4.z * kev.z + u4.w * kev.w
               + w4.x * krv.x + w4.y * krv.y + w4.z * krv.z + w4.w * krv.w;
#pragma unroll
    for (int off = 8; off; off >>= 1)
        bsum += __shfl_xor_sync(0xffffffffu, bsum, off, 16);
    if (l16 == 0)
        biasO[(size_t)(b * HEADS + h) * TLEN + t] = bsum * 0.125f;  // pre-scaled
}

// ---------------- fp16 tensor-core flash attention ---------------------------
// Query tile 128, key tile 64. 8 warps x 16 query rows. fp16 mma m16n8k16.
// smem (bytes): QH 128x144 | PH 128x144 | KKH 64x144 | VH 64x144 | bias 2x256
#define QH_OFF 0u
#define PH_OFF 18432u
#define KK_OFF 36864u
#define V_OFF  46080u
#define BI_OFF 55296u
#define FLASH_SMEM 55808

__global__ void __launch_bounds__(256, 2)
flash16_kernel(const __half* __restrict__ qh,
               const __half* __restrict__ kkh,
               const __half* __restrict__ vhg,
               const float* __restrict__ biasG,
               __half* __restrict__ out)
{
    extern __shared__ char fsm[];
    const uint32_t sbase = (uint32_t)__cvta_generic_to_shared(fsm);
    __half* PhH = (__half*)(fsm + PH_OFF);
    const float* biasS = (const float*)(fsm + BI_OFF);

    // heavy q-blocks first for wave balance (qb=7 has 32 tiles, qb=0 has 18)
    const int qb = 7 - (int)blockIdx.x;
    const int h = blockIdx.y, b = blockIdx.z;
    const int tid = threadIdx.x;
    const int lane = tid & 31, wid = tid >> 5;
    const int q = lane >> 2, r = lane & 3;
    const int mw = wid * 16;
    const int alr = lane & 15, alc = lane >> 4;
    const int bg = lane >> 3,  blr = lane & 7;

    const size_t  bh   = (size_t)(b * HEADS + h) * TLEN;
    const __half* kkbh = kkh + bh * HDIM;
    const __half* vbh  = vhg + bh * HDIM;
    const float*  bibh = biasG + bh;

    auto issueQ = [&]() {
#pragma unroll
        for (int it = 0; it < 4; it++) {
            int idx = tid + it * 256;
            int row = idx >> 3, c = idx & 7;
            cp_async16(sbase + QH_OFF + (uint32_t)row * HROW + (uint32_t)c * 16u,
                       qh + ((size_t)((qb * 128 + row) * BATCH + b)) * DMODEL
                          + h * HDIM + c * 8);
        }
    };
    auto issueKK = [&](int t0, int pb) {
#pragma unroll
        for (int it = 0; it < 2; it++) {
            int idx = tid + it * 256;
            int row = idx >> 3, c = idx & 7;
            cp_async16(sbase + KK_OFF + (uint32_t)row * HROW + (uint32_t)c * 16u,
                       kkbh + (size_t)(t0 + row) * HDIM + c * 8);
        }
        if (tid < 16)
            cp_async16(sbase + BI_OFF + (uint32_t)(pb * 256 + tid * 16),
                       bibh + t0 + tid * 4);
    };
    auto issueV = [&](int t0) {
#pragma unroll
        for (int it = 0; it < 2; it++) {
            int idx = tid + it * 256;
            int row = idx >> 3, c = idx & 7;
            cp_async16(sbase + V_OFF + (uint32_t)row * HROW + (uint32_t)c * 16u,
                       vbh + (size_t)(t0 + row) * HDIM + c * 8);
        }
    };

    // prologue: groups [Q] [KK0+bias] [V0]
    issueQ();
    cp_commit();
    issueKK(0, 0);
    cp_commit();
    issueV(0);
    cp_commit();

    float m0 = -1e30f, m1 = -1e30f, l0 = 0.f, l1 = 0.f;
    float O[8][4];
#pragma unroll
    for (int nt = 0; nt < 8; nt++)
#pragma unroll
        for (int e = 0; e < 4; e++) O[nt][e] = 0.f;

    const int ntiles = 18 + 2 * qb;
    const int srow0 = qb * 128 + mw + q;

    for (int tt = 0; tt < ntiles; tt++) {
        const int t0 = tt * 64;
        const int pb = tt & 1;
        const bool more = (tt + 1 < ntiles);

        cp_wait<1>();          // Q (tt=0) + KK(tt)+bias complete; V(tt) pending
        __syncthreads();

        // ---- S = Q @ KK^T  (fp16 mma) --------------------------------------
        float sc[8][4];
#pragma unroll
        for (int nt = 0; nt < 8; nt++)
#pragma unroll
            for (int e = 0; e < 4; e++) sc[nt][e] = 0.f;

#pragma unroll
        for (int ks = 0; ks < 4; ks++) {
            uint32_t afr[4];
            ldm_x4(afr, sbase + QH_OFF + (uint32_t)(mw + alr) * HROW
                         + (uint32_t)(ks * 32 + alc * 16));
#pragma unroll
            for (int tb = 0; tb < 4; tb++) {
                uint32_t tmp[4];
                ldm_x4(tmp, sbase + KK_OFF
                             + (uint32_t)(tb * 16 + (bg >> 1) * 8 + blr) * HROW
                             + (uint32_t)(ks * 32 + (bg & 1) * 16));
                mma_f16(sc[tb * 2],     afr, tmp);
                mma_f16(sc[tb * 2 + 1], afr, tmp + 2);
            }
        }
        __syncthreads();       // all warps done reading KKH

        if (more) { issueKK(t0 + 64, pb ^ 1); cp_commit(); }

        // ---- bias(pre-scaled) + scale + causal mask + online softmax --------
        const float* bS = biasS + pb * 64;
        const bool mt_ = (tt >= 16 + 2 * qb);
        float tmax0 = -1e30f, tmax1 = -1e30f;
#pragma unroll
        for (int nt = 0; nt < 8; nt++) {
            const int colb = nt * 8 + 2 * r;
            const float bi0 = bS[colb], bi1 = bS[colb + 1];
            float v0 = fmaf(sc[nt][0], 0.125f, bi0);
            float v1 = fmaf(sc[nt][1], 0.125f, bi1);
            float v2 = fmaf(sc[nt][2], 0.125f, bi0);
            float v3 = fmaf(sc[nt][3], 0.125f, bi1);
            if (mt_) {
                const int tc = t0 + colb;
                if (tc     > S_LEN + srow0)     v0 = -1e30f;
                if (tc + 1 > S_LEN + srow0)     v1 = -1e30f;
                if (tc     > S_LEN + srow0 + 8) v2 = -1e30f;
                if (tc + 1 > S_LEN + srow0 + 8) v3 = -1e30f;
            }
            sc[nt][0] = v0; sc[nt][1] = v1; sc[nt][2] = v2; sc[nt][3] = v3;
            tmax0 = fmaxf(tmax0, fmaxf(v0, v1));
            tmax1 = fmaxf(tmax1, fmaxf(v2, v3));
        }
        tmax0 = fmaxf(tmax0, __shfl_xor_sync(0xffffffffu, tmax0, 1));
        tmax0 = fmaxf(tmax0, __shfl_xor_sync(0xffffffffu, tmax0, 2));
        tmax1 = fmaxf(tmax1, __shfl_xor_sync(0xffffffffu, tmax1, 1));
        tmax1 = fmaxf(tmax1, __shfl_xor_sync(0xffffffffu, tmax1, 2));

        const float mnew0 = fmaxf(m0, tmax0);
        const float mnew1 = fmaxf(m1, tmax1);
        const float c0 = __expf(m0 - mnew0);
        const float c1 = __expf(m1 - mnew1);
        m0 = mnew0; m1 = mnew1;
        l0 *= c0; l1 *= c1;

        // skip the 32-fmul O rescale when no row in this warp saw a new max
        const bool doscale = !__all_sync(0xffffffffu, (c0 == 1.f) && (c1 == 1.f));

        float ps0 = 0.f, ps1 = 0.f;
#pragma unroll
        for (int nt = 0; nt < 8; nt++) {
            float p0 = __expf(sc[nt][0] - mnew0);
            float p1 = __expf(sc[nt][1] - mnew0);
            float p2 = __expf(sc[nt][2] - mnew1);
            float p3 = __expf(sc[nt][3] - mnew1);
            ps0 += p0 + p1; ps1 += p2 + p3;
            if (doscale) {
                O[nt][0] *= c0; O[nt][1] *= c0;
                O[nt][2] *= c1; O[nt][3] *= c1;
            }
            const int colp = nt * 8 + 2 * r;
            *(__half2*)&PhH[(size_t)(mw + q) * 72 + colp]     = __floats2half2_rn(p0, p1);
            *(__half2*)&PhH[(size_t)(mw + q + 8) * 72 + colp] = __floats2half2_rn(p2, p3);
        }
        l0 += ps0; l1 += ps1;
        __syncwarp();

        // ---- ensure V(tt) landed, then O += P @ V ---------------------------
        if (more) { cp_wait<1>(); } else { cp_wait<0>(); }
        __syncthreads();

#pragma unroll
        for (int ks = 0; ks < 4; ks++) {
            uint32_t afr[4];
            ldm_x4(afr, sbase + PH_OFF + (uint32_t)(mw + alr) * HROW
                         + (uint32_t)(ks * 32 + alc * 16));
#pragma unroll
            for (int dp = 0; dp < 4; dp++) {
                uint32_t tmp[4];
                ldm_x4_t(tmp, sbase + V_OFF
                               + (uint32_t)(ks * 16 + (bg & 1) * 8 + blr) * HROW
                               + (uint32_t)(dp * 32 + (bg >> 1) * 16));
                mma_f16(O[dp * 2],     afr, tmp);
                mma_f16(O[dp * 2 + 1], afr, tmp + 2);
            }
        }
        __syncthreads();       // all warps done reading VH

        if (more) { issueV(t0 + 64); cp_commit(); }
    }

    // ---- finalize: reduce l over quad, normalize, store fp16 ---------------
    l0 += __shfl_xor_sync(0xffffffffu, l0, 1);
    l0 += __shfl_xor_sync(0xffffffffu, l0, 2);
    l1 += __shfl_xor_sync(0xffffffffu, l1, 1);
    l1 += __shfl_xor_sync(0xffffffffu, l1, 2);
    const float inv0 = 1.f / l0, inv1 = 1.f / l1;

#pragma unroll
    for (int nt = 0; nt < 8; nt++) {
        const int col = nt * 8 + 2 * r;
        const int row0 = qb * 128 + mw + q;
        *(__half2*)(out + ((size_t)(row0 * BATCH + b)) * DMODEL + h * HDIM + col)
            = __floats2half2_rn(O[nt][0] * inv0, O[nt][1] * inv0);
        *(__half2*)(out + ((size_t)((row0 + 8) * BATCH + b)) * DMODEL + h * HDIM + col)
            = __floats2half2_rn(O[nt][2] * inv1, O[nt][3] * inv1);
    }
}

// ---------------- LayerNorm(a0 [+ a1] + res) * g + b -------------------------
__global__ void __launch_bounds__(256)
ln_kernel(const float* __restrict__ a0, const float* __restrict__ a1,
          const float* __restrict__ res,
          const float* __restrict__ g, const float* __restrict__ bta,
          float* __restrict__ out, __half* __restrict__ out_h)
{
    const int row = blockIdx.x;
    const int tid = threadIdx.x;
    const int lane = tid & 31, wrp = tid >> 5;
    __shared__ float red[8];
    __shared__ float bc;

    float vals[4];
    float s = 0.f;
    const float* ar = a0 + (size_t)row * DMODEL;
    const float* br = a1 ? a1 + (size_t)row * DMODEL : nullptr;
    const float* rr = res + (size_t)row * DMODEL;
#pragma unroll
    for (int i = 0; i < 4; i++) {
        int d = tid + i * 256;
        float v = ar[d] + rr[d];
        if (br) v += br[d];
        vals[i] = v;
        s += v;
    }
#pragma unroll
    for (int off = 16; off; off >>= 1) s += __shfl_xor_sync(0xffffffffu, s, off);
    if (lane == 0) red[wrp] = s;
    __syncthreads();
    if (tid == 0) {
        float t = 0.f;
#pragma unroll
        for (int w = 0; w < 8; w++) t += red[w];
        bc = t * (1.f / DMODEL);
    }
    __syncthreads();
    const float mu = bc;

    float vs = 0.f;
#pragma unroll
    for (int i = 0; i < 4; i++) {
        float dd = vals[i] - mu;
        vs += dd * dd;
    }
#pragma unroll
    for (int off = 16; off; off >>= 1) vs += __shfl_xor_sync(0xffffffffu, vs, off);
    __syncthreads();
    if (lane == 0) red[wrp] = vs;
    __syncthreads();
    if (tid == 0) {
        float t = 0.f;
#pragma unroll
        for (int w = 0; w < 8; w++) t += red[w];
        bc = rsqrtf(t * (1.f / DMODEL) + 1e-5f);
    }
    __syncthreads();
    const float rstd = bc;

    float* orow = out + (size_t)row * DMODEL;
    __half* hrow = out_h ? out_h + (size_t)row * DMODEL : nullptr;
#pragma unroll
    for (int i = 0; i < 4; i++) {
        int d = tid + i * 256;
        float vv = (vals[i] - mu) * rstd * g[d] + bta[d];
        orow[d] = vv;
        if (hrow) hrow[d] = __float2half(vv);
    }
}

// ---------------- launcher ---------------------------------------------------
extern "C" void kernel_launch(void* const* d_in, const int* in_sizes, int n_in,
                              void* d_out, int out_size)
{
    const float* x      = (const float*)d_in[0];
    const float* p      = (const float*)d_in[1];
    /* mask d_in[2] is analytic: unused */
    const float* memory = (const float*)d_in[3];
    const float* u_bias = (const float*)d_in[4];
    const float* v_bias = (const float*)d_in[5];
    const float* wq  = (const float*)d_in[6];
    const float* wke = (const float*)d_in[7];
    const float* wkr = (const float*)d_in[8];
    const float* wv  = (const float*)d_in[9];
    const float* wc  = (const float*)d_in[10];
    const float* w1  = (const float*)d_in[11];
    const float* w1b = (const float*)d_in[12];
    const float* w2  = (const float*)d_in[13];
    const float* w2b = (const float*)d_in[14];
    const float* ln1g = (const float*)d_in[15];
    const float* ln1b = (const float*)d_in[16];
    const float* ln2g = (const float*)d_in[17];
    const float* ln2b = (const float*)d_in[18];
    float* out = (float*)d_out;

    float *ke, *kr, *v, *tbuf, *t2buf, *ubuf, *bias2;
    __half *xh, *memh, *ph, *wqh, *wkeh, *wkrh, *wvh, *wch, *w1h, *w2h;
    __half *qh, *avh, *uh, *h1h, *kkh, *vh;
    cudaGetSymbolAddress((void**)&ke,    g_ke);
    cudaGetSymbolAddress((void**)&kr,    g_kr);
    cudaGetSymbolAddress((void**)&v,     g_v);
    cudaGetSymbolAddress((void**)&tbuf,  g_t);
    cudaGetSymbolAddress((void**)&t2buf, g_t2);
    cudaGetSymbolAddress((void**)&ubuf,  g_u);
    cudaGetSymbolAddress((void**)&xh,    g_xh);
    cudaGetSymbolAddress((void**)&memh,  g_memh);
    cudaGetSymbolAddress((void**)&ph,    g_ph);
    cudaGetSymbolAddress((void**)&wqh,   g_wqh);
    cudaGetSymbolAddress((void**)&wkeh,  g_wkeh);
    cudaGetSymbolAddress((void**)&wkrh,  g_wkrh);
    cudaGetSymbolAddress((void**)&wvh,   g_wvh);
    cudaGetSymbolAddress((void**)&wch,   g_wch);
    cudaGetSymbolAddress((void**)&w1h,   g_w1h);
    cudaGetSymbolAddress((void**)&w2h,   g_w2h);
    cudaGetSymbolAddress((void**)&qh,    g_qh);
    cudaGetSymbolAddress((void**)&avh,   g_avh);
    cudaGetSymbolAddress((void**)&uh,    g_uh);
    cudaGetSymbolAddress((void**)&h1h,   g_h1h);
    cudaGetSymbolAddress((void**)&kkh,   g_kkh);
    cudaGetSymbolAddress((void**)&vh,    g_vh);
    cudaGetSymbolAddress((void**)&bias2, g_bias);

    cudaFuncSetAttribute(gemm16_kernel,
                         cudaFuncAttributeMaxDynamicSharedMemorySize, GEMM16_SMEM);
    cudaFuncSetAttribute(flash16_kernel,
                         cudaFuncAttributeMaxDynamicSharedMemorySize, FLASH_SMEM);

    const dim3 blk(256);
    const size_t half = (size_t)ROWS_X * DMODEL;

    // ---- convert inputs + weights to fp16 (one merged launch) ---------------
    {
        CvtSegs cs{};
        int acc = 0, i = 0;
        auto add = [&](const float* s, __half* d, int n8) {
            cs.src[i] = s; cs.dst[i] = d; acc += n8; cs.end8[i] = acc; i++;
        };
        add(x,      xh,   ROWS_X * DMODEL / 8);
        add(memory, memh, ROWS_X * DMODEL / 8);
        add(p,      ph,   ROWS_T * DMODEL / 8);
        add(wq,  wqh,  DMODEL * DMODEL / 8);
        add(wke, wkeh, DMODEL * DMODEL / 8);
        add(wkr, wkrh, DMODEL * DMODEL / 8);
        add(wv,  wvh,  DMODEL * DMODEL / 8);
        add(wc,  wch,  DMODEL * DMODEL / 8);
        add(w1,  w1h,  FFDIM * DMODEL / 8);
        add(w2,  w2h,  FFDIM * DMODEL / 8);
        cs.nseg = i;
        cvt_all_kernel<<<(acc + 255) / 256, blk>>>(cs, acc);
    }

    // ---- all 6 projections in ONE launch (z = 0..6), fp16 mma ---------------
    {
        GemmPtrs gp{};
        gp.A[0] = xh;   gp.W[0] = wqh;  gp.Ch[0] = qh;
        gp.A[1] = xh;   gp.W[1] = wkeh; gp.C[1] = ke + half;
        gp.A[2] = xh;   gp.W[2] = wvh;  gp.C[2] = v + half;
        gp.A[3] = memh; gp.W[3] = wkeh; gp.C[3] = ke;
        gp.A[4] = memh; gp.W[4] = wvh;  gp.C[4] = v;
        gp.A[5] = ph;        gp.W[5] = wkrh; gp.C[5] = kr;
        gp.A[6] = ph + half; gp.W[6] = wkrh; gp.C[6] = kr + half;
        gemm16_kernel<<<dim3(8, 16, 7), blk, GEMM16_SMEM>>>(
            gp, ROWS_X, DMODEL, DMODEL, DMODEL, 0);
    }

    // prep: fuse KK (fp16), bias (fp32, pre-scaled), V (fp16)
    prep_kernel<<<ROWS_T, blk>>>(ke, kr, v, u_bias, v_bias, kkh, vh, bias2);

    // fp16 flash attention
    flash16_kernel<<<dim3(8, HEADS, BATCH), blk, FLASH_SMEM>>>(
        qh, kkh, vh, bias2, avh);

    // output proj (split-K=2) + LN1 (fused add; emits uh fp16)
    {
        GemmPtrs gp{};
        gp.A[0] = avh;       gp.W[0] = wch;       gp.C[0] = tbuf;
        gp.A[1] = avh + 512; gp.W[1] = wch + 512; gp.C[1] = t2buf;
        gemm16_kernel<<<dim3(8, 16, 2), blk, GEMM16_SMEM>>>(
            gp, ROWS_X, DMODEL, 512, DMODEL, 0);
    }
    ln_kernel<<<ROWS_X, blk>>>(tbuf, t2buf, x, ln1g, ln1b, ubuf, uh);

    // FFN: w1 (relu, fp16 out), w2 (split-K=2) + LN2 (fused add)
    {
        GemmPtrs gp{};
        gp.A[0] = uh; gp.W[0] = w1h; gp.Ch[0] = h1h; gp.bias[0] = w1b;
        gemm16_kernel<<<dim3(32, 16, 1), blk, GEMM16_SMEM>>>(
            gp, ROWS_X, FFDIM, DMODEL, DMODEL, 1);
    }
    {
        GemmPtrs gp{};
        gp.A[0] = h1h;        gp.W[0] = w2h;        gp.C[0] = tbuf;  gp.bias[0] = w2b;
        gp.A[1] = h1h + 2048; gp.W[1] = w2h + 2048; gp.C[1] = t2buf;
        gemm16_kernel<<<dim3(8, 16, 2), blk, GEMM16_SMEM>>>(
            gp, ROWS_X, DMODEL, 2048, FFDIM, 0);
    }
    ln_kernel<<<ROWS_X, blk>>>(tbuf, t2buf, ubuf, ln2g, ln2b, out, nullptr);
}

// round 13
// speedup vs baseline: 1.9335x; 1.0216x over previous
#include <cuda_runtime.h>
#include <cuda_fp16.h>
#include <math.h>
#include <stdint.h>

// Problem constants
#define S_LEN 1024
#define BATCH 2
#define DMODEL 1024
#define HEADS 16
#define HDIM 64
#define TLEN 2048
#define FFDIM 4096
#define ROWS_X (S_LEN * BATCH)     // 2048
#define ROWS_T (TLEN * BATCH)      // 4096

// ---------------- scratch buffers (device globals) ---------------------------
__device__ float g_t [ROWS_X * DMODEL];
__device__ float g_t2[ROWS_X * DMODEL];
__device__ float g_u [ROWS_X * DMODEL];
// fp16 tensors
__device__ __half g_xh  [ROWS_X * DMODEL];
__device__ __half g_memh[ROWS_X * DMODEL];
__device__ __half g_ph  [ROWS_T * DMODEL];
__device__ __half g_wqh [DMODEL * DMODEL];
__device__ __half g_wkeh[DMODEL * DMODEL];
__device__ __half g_wkrh[DMODEL * DMODEL];
__device__ __half g_wvh [DMODEL * DMODEL];
__device__ __half g_wch [DMODEL * DMODEL];
__device__ __half g_w1h [FFDIM * DMODEL];
__device__ __half g_w2h [DMODEL * FFDIM];
__device__ __half g_qh  [ROWS_X * DMODEL];
__device__ __half g_keh [ROWS_T * DMODEL];
__device__ __half g_krh [ROWS_T * DMODEL];
__device__ __half g_vxh [ROWS_T * DMODEL];
__device__ __half g_avh [ROWS_X * DMODEL];
__device__ __half g_uh  [ROWS_X * DMODEL];
__device__ __half g_h1h [ROWS_X * FFDIM];
// flash-prep outputs (fp16 KK / V, fp32 bias pre-scaled by 0.125)
__device__ __half g_kkh [BATCH * HEADS * TLEN * HDIM];
__device__ __half g_vh  [BATCH * HEADS * TLEN * HDIM];
__device__ float  g_bias[BATCH * HEADS * TLEN];

// ---------------- common PTX helpers ----------------------------------------
__device__ __forceinline__ void cp_async16(uint32_t saddr, const void* gptr) {
    asm volatile("cp.async.cg.shared.global [%0], [%1], 16;\n"
                 :: "r"(saddr), "l"(gptr));
}
__device__ __forceinline__ void cp_commit() {
    asm volatile("cp.async.commit_group;\n");
}
template <int N>
__device__ __forceinline__ void cp_wait() {
    asm volatile("cp.async.wait_group %0;\n" :: "n"(N));
}
__device__ __forceinline__ void mma_f16(float* d, const uint32_t* a, const uint32_t* b) {
    asm volatile(
        "mma.sync.aligned.m16n8k16.row.col.f32.f16.f16.f32 "
        "{%0,%1,%2,%3}, {%4,%5,%6,%7}, {%8,%9}, {%0,%1,%2,%3};\n"
        : "+f"(d[0]), "+f"(d[1]), "+f"(d[2]), "+f"(d[3])
        : "r"(a[0]), "r"(a[1]), "r"(a[2]), "r"(a[3]), "r"(b[0]), "r"(b[1]));
}
__device__ __forceinline__ void ldm_x4(uint32_t* r, uint32_t addr) {
    asm volatile("ldmatrix.sync.aligned.m8n8.x4.shared.b16 {%0,%1,%2,%3}, [%4];"
                 : "=r"(r[0]), "=r"(r[1]), "=r"(r[2]), "=r"(r[3]) : "r"(addr));
}
__device__ __forceinline__ void ldm_x4_t(uint32_t* r, uint32_t addr) {
    asm volatile("ldmatrix.sync.aligned.m8n8.x4.trans.shared.b16 {%0,%1,%2,%3}, [%4];"
                 : "=r"(r[0]), "=r"(r[1]), "=r"(r[2]), "=r"(r[3]) : "r"(addr));
}

// ---------------- fp32 -> fp16 conversion (merged segments) ------------------
#define MAXSEG 10
struct CvtSegs {
    const float* src[MAXSEG];
    __half*      dst[MAXSEG];
    int          end8[MAXSEG];
    int          nseg;
};

__global__ void __launch_bounds__(256)
cvt_all_kernel(CvtSegs segs, int total8)
{
    int idx = blockIdx.x * 256 + threadIdx.x;
    if (idx >= total8) return;
    int s = 0;
#pragma unroll
    for (int i = 0; i < MAXSEG; i++)
        if (i < segs.nseg && idx >= segs.end8[i]) s = i + 1;
    const int off = idx - (s ? segs.end8[s - 1] : 0);

    const float4* s4 = (const float4*)(segs.src[s] + (size_t)off * 8);
    float4 a = s4[0], b = s4[1];
    __half2 h[4];
    h[0] = __floats2half2_rn(a.x, a.y);
    h[1] = __floats2half2_rn(a.z, a.w);
    h[2] = __floats2half2_rn(b.x, b.y);
    h[3] = __floats2half2_rn(b.z, b.w);
    *(uint4*)(segs.dst[s] + (size_t)off * 8) = *(uint4*)h;
}

// ---------------- fp16 tensor-core GEMM (3-stage pipeline) -------------------
struct GemmPtrs {
    const __half* A[7];
    const __half* W[7];
    float*        C[7];
    __half*       Ch[7];
    const float*  bias[7];
};

#define HROW 144u                      // smem row stride in bytes (72 halves)
#define TILE16 (128u * HROW)           // 18432 B per operand tile
#define STAGE16 (2u * TILE16)          // 36864 B per stage
#define GEMM16_SMEM (3 * 36864)        // 110592 B (3 stages)

__global__ void __launch_bounds__(256)
gemm16_kernel(GemmPtrs ptrs, int M, int N, int Klen, int Kstride, int act)
{
    extern __shared__ char smem[];
    const uint32_t sbase = (uint32_t)__cvta_generic_to_shared(smem);

    const __half* A    = ptrs.A[blockIdx.z];
    const __half* W    = ptrs.W[blockIdx.z];
    float*        C    = ptrs.C[blockIdx.z];
    __half*       Ch   = ptrs.Ch[blockIdx.z];
    const float*  bias = ptrs.bias[blockIdx.z];

    const int tid = threadIdx.x;
    const int lane = tid & 31, wrp = tid >> 5;
    const int wm = wrp & 1, wn = wrp >> 1;
    const int q = lane >> 2, r = lane & 3;
    const int m0 = blockIdx.y * 128;
    const int n0 = blockIdx.x * 128;

    float acc[4][4][4];
#pragma unroll
    for (int i = 0; i < 4; i++)
#pragma unroll
        for (int j = 0; j < 4; j++)
#pragma unroll
            for (int e = 0; e < 4; e++) acc[i][j][e] = 0.f;

    auto issue = [&](int t) {              // tile index; stage = t % 3
        const uint32_t so = sbase + (uint32_t)(t % 3) * STAGE16;
        const int k0 = t << 5;             // halves
#pragma unroll
        for (int i = 0; i < 2; i++) {
            int id = tid + i * 256;
            int row = id >> 2, c = id & 3;
            uint32_t d = (uint32_t)row * HROW + (uint32_t)c * 16u;
            cp_async16(so + d,          A + (size_t)(m0 + row) * Kstride + k0 + c * 8);
            cp_async16(so + TILE16 + d, W + (size_t)(n0 + row) * Kstride + k0 + c * 8);
        }
    };

    const int KT = Klen >> 5;
    issue(0);
    cp_commit();
    if (KT > 1) { issue(1); cp_commit(); }

    const int alr = lane & 15, alc = lane >> 4;
    const int bg = lane >> 3,  blr = lane & 7;

    for (int kt = 0; kt < KT; kt++) {
        if (kt == KT - 1) { cp_wait<0>(); } else { cp_wait<1>(); }
        __syncthreads();
        if (kt + 2 < KT) { issue(kt + 2); cp_commit(); }

        const uint32_t aBase = sbase + (uint32_t)(kt % 3) * STAGE16;
        const uint32_t bBase = aBase + TILE16;

#pragma unroll
        for (int ks = 0; ks < 2; ks++) {
            uint32_t afr[4][4];
#pragma unroll
            for (int mt = 0; mt < 4; mt++) {
                uint32_t addr = aBase +
                    (uint32_t)(wm * 64 + mt * 16 + alr) * HROW +
                    (uint32_t)(ks * 32 + alc * 16);
                ldm_x4(afr[mt], addr);
            }
            uint32_t bfr[4][2];
#pragma unroll
            for (int ntp = 0; ntp < 2; ntp++) {
                uint32_t addr = bBase +
                    (uint32_t)(wn * 32 + ntp * 16 + (bg >> 1) * 8 + blr) * HROW +
                    (uint32_t)(ks * 32 + (bg & 1) * 16);
                uint32_t tmp[4];
                ldm_x4(tmp, addr);
                bfr[ntp * 2 + 0][0] = tmp[0]; bfr[ntp * 2 + 0][1] = tmp[1];
                bfr[ntp * 2 + 1][0] = tmp[2]; bfr[ntp * 2 + 1][1] = tmp[3];
            }
#pragma unroll
            for (int mt = 0; mt < 4; mt++)
#pragma unroll
                for (int nt = 0; nt < 4; nt++)
                    mma_f16(acc[mt][nt], afr[mt], bfr[nt]);
        }
    }

#pragma unroll
    for (int mt = 0; mt < 4; mt++) {
        const int row0 = m0 + wm * 64 + mt * 16 + q;
#pragma unroll
        for (int nt = 0; nt < 4; nt++) {
            const int col = n0 + wn * 32 + nt * 8 + r * 2;
            float b0 = bias ? bias[col]     : 0.f;
            float b1 = bias ? bias[col + 1] : 0.f;
            float v0 = acc[mt][nt][0] + b0, v1 = acc[mt][nt][1] + b1;
            float v2 = acc[mt][nt][2] + b0, v3 = acc[mt][nt][3] + b1;
            if (act == 1) {
                v0 = fmaxf(v0, 0.f); v1 = fmaxf(v1, 0.f);
                v2 = fmaxf(v2, 0.f); v3 = fmaxf(v3, 0.f);
            }
            if (C) {
                *(float2*)(C + (size_t)row0 * N + col)       = make_float2(v0, v1);
                *(float2*)(C + (size_t)(row0 + 8) * N + col) = make_float2(v2, v3);
            }
            if (Ch) {
                *(__half2*)(Ch + (size_t)row0 * N + col)       = __floats2half2_rn(v0, v1);
                *(__half2*)(Ch + (size_t)(row0 + 8) * N + col) = __floats2half2_rn(v2, v3);
            }
        }
    }
}

// ---------------- prep (fp16 in): KK = ke+kr, bias = (u.ke+v.kr)/8, V copy ---
__global__ void __launch_bounds__(256)
prep_kernel(const __half* __restrict__ keh, const __half* __restrict__ krh,
            const __half* __restrict__ vin,
            const float* __restrict__ ub, const float* __restrict__ vb,
            __half* __restrict__ kkh, __half* __restrict__ vh,
            float* __restrict__ biasO)
{
    const int row = blockIdx.x;          // = t*BATCH + b
    const int t = row / BATCH, b = row % BATCH;
    const int tid = threadIdx.x;
    const int h = tid >> 4, l16 = tid & 15, d0 = l16 * 4;

    const size_t src = (size_t)row * DMODEL + h * HDIM + d0;
    uint2 ke2 = *(const uint2*)(keh + src);
    uint2 kr2 = *(const uint2*)(krh + src);
    uint2 vv2 = *(const uint2*)(vin + src);

    float2 ke01 = __half22float2(*(__half2*)&ke2.x);
    float2 ke23 = __half22float2(*(__half2*)&ke2.y);
    float2 kr01 = __half22float2(*(__half2*)&kr2.x);
    float2 kr23 = __half22float2(*(__half2*)&kr2.y);

    const size_t dst = ((size_t)(b * HEADS + h) * TLEN + t) * HDIM + d0;
    __half2 kk01 = __floats2half2_rn(ke01.x + kr01.x, ke01.y + kr01.y);
    __half2 kk23 = __floats2half2_rn(ke23.x + kr23.x, ke23.y + kr23.y);
    *(uint2*)(kkh + dst) = make_uint2(*(uint32_t*)&kk01, *(uint32_t*)&kk23);
    *(uint2*)(vh  + dst) = vv2;          // passthrough relayout

    float4 u4 = *(const float4*)(ub + h * HDIM + d0);
    float4 w4 = *(const float4*)(vb + h * HDIM + d0);
    float bsum = u4.x * ke01.x + u4.y * ke01.y + u4.z * ke23.x + u4.w * ke23.y
               + w4.x * kr01.x + w4.y * kr01.y + w4.z * kr23.x + w4.w * kr23.y;
#pragma unroll
    for (int off = 8; off; off >>= 1)
        bsum += __shfl_xor_sync(0xffffffffu, bsum, off, 16);
    if (l16 == 0)
        biasO[(size_t)(b * HEADS + h) * TLEN + t] = bsum * 0.125f;  // pre-scaled
}

// ---------------- fp16 flash attention (double-buffered KV, 1 sync/tile) -----
// smem (bytes): QH 128x144 | PH 128x144 | KK[2] 64x144 | V[2] 64x144 | bias[2]
#define QH_OFF 0u
#define PH_OFF 18432u
#define KK_OFF 36864u          // + buf*9216
#define V_OFF  55296u          // + buf*9216
#define BI_OFF 73728u          // + buf*256
#define KVBUF  9216u
#define FLASH_SMEM 74240

__global__ void __launch_bounds__(256, 2)
flash16_kernel(const __half* __restrict__ qh,
               const __half* __restrict__ kkh,
               const __half* __restrict__ vhg,
               const float* __restrict__ biasG,
               __half* __restrict__ out)
{
    extern __shared__ char fsm[];
    const uint32_t sbase = (uint32_t)__cvta_generic_to_shared(fsm);
    __half* PhH = (__half*)(fsm + PH_OFF);

    // heavy q-blocks first for wave balance (qb=7 has 32 tiles, qb=0 has 18)
    const int qb = 7 - (int)blockIdx.x;
    const int h = blockIdx.y, b = blockIdx.z;
    const int tid = threadIdx.x;
    const int lane = tid & 31, wid = tid >> 5;
    const int q = lane >> 2, r = lane & 3;
    const int mw = wid * 16;
    const int alr = lane & 15, alc = lane >> 4;
    const int bg = lane >> 3,  blr = lane & 7;

    const size_t  bh   = (size_t)(b * HEADS + h) * TLEN;
    const __half* kkbh = kkh + bh * HDIM;
    const __half* vbh  = vhg + bh * HDIM;
    const float*  bibh = biasG + bh;

    auto issueQ = [&]() {
#pragma unroll
        for (int it = 0; it < 4; it++) {
            int idx = tid + it * 256;
            int row = idx >> 3, c = idx & 7;
            cp_async16(sbase + QH_OFF + (uint32_t)row * HROW + (uint32_t)c * 16u,
                       qh + ((size_t)((qb * 128 + row) * BATCH + b)) * DMODEL
                          + h * HDIM + c * 8);
        }
    };
    // one group: KK + V + bias for tile starting at t0, into buffer buf
    auto issueKV = [&](int t0, int buf) {
        const uint32_t kkB = sbase + KK_OFF + (uint32_t)buf * KVBUF;
        const uint32_t vB  = sbase + V_OFF  + (uint32_t)buf * KVBUF;
#pragma unroll
        for (int it = 0; it < 2; it++) {
            int idx = tid + it * 256;
            int row = idx >> 3, c = idx & 7;
            const uint32_t d = (uint32_t)row * HROW + (uint32_t)c * 16u;
            cp_async16(kkB + d, kkbh + (size_t)(t0 + row) * HDIM + c * 8);
            cp_async16(vB  + d, vbh  + (size_t)(t0 + row) * HDIM + c * 8);
        }
        if (tid < 16)
            cp_async16(sbase + BI_OFF + (uint32_t)(buf * 256 + tid * 16),
                       bibh + t0 + tid * 4);
    };

    // prologue: ONE group carrying Q + KV(0)
    issueQ();
    issueKV(0, 0);
    cp_commit();

    float m0 = -1e30f, m1 = -1e30f, l0 = 0.f, l1 = 0.f;
    float O[8][4];
#pragma unroll
    for (int nt = 0; nt < 8; nt++)
#pragma unroll
        for (int e = 0; e < 4; e++) O[nt][e] = 0.f;

    const int ntiles = 18 + 2 * qb;
    const int srow0 = qb * 128 + mw + q;

    for (int tt = 0; tt < ntiles; tt++) {
        const int t0 = tt * 64;
        const int buf = tt & 1;
        const bool more = (tt + 1 < ntiles);

        cp_wait<0>();          // KV(tt) (+Q at tt=0) resident
        __syncthreads();       // visible to all warps; also guards buf reuse

        // prefetch next tile into the other buffer (overlaps ALL compute below)
        if (more) { issueKV(t0 + 64, buf ^ 1); cp_commit(); }

        const uint32_t kkB = sbase + KK_OFF + (uint32_t)buf * KVBUF;
        const uint32_t vB  = sbase + V_OFF  + (uint32_t)buf * KVBUF;
        const float* bS = (const float*)(fsm + BI_OFF + buf * 256);

        // ---- S = Q @ KK^T  (fp16 mma) --------------------------------------
        float sc[8][4];
#pragma unroll
        for (int nt = 0; nt < 8; nt++)
#pragma unroll
            for (int e = 0; e < 4; e++) sc[nt][e] = 0.f;

#pragma unroll
        for (int ks = 0; ks < 4; ks++) {
            uint32_t afr[4];
            ldm_x4(afr, sbase + QH_OFF + (uint32_t)(mw + alr) * HROW
                         + (uint32_t)(ks * 32 + alc * 16));
#pragma unroll
            for (int tb = 0; tb < 4; tb++) {
                uint32_t tmp[4];
                ldm_x4(tmp, kkB
                             + (uint32_t)(tb * 16 + (bg >> 1) * 8 + blr) * HROW
                             + (uint32_t)(ks * 32 + (bg & 1) * 16));
                mma_f16(sc[tb * 2],     afr, tmp);
                mma_f16(sc[tb * 2 + 1], afr, tmp + 2);
            }
        }

        // ---- bias(pre-scaled) + causal mask + online softmax ----------------
        const bool mt_ = (tt >= 16 + 2 * qb);
        float tmax0 = -1e30f, tmax1 = -1e30f;
#pragma unroll
        for (int nt = 0; nt < 8; nt++) {
            const int colb = nt * 8 + 2 * r;
            const float bi0 = bS[colb], bi1 = bS[colb + 1];
            float v0 = fmaf(sc[nt][0], 0.125f, bi0);
            float v1 = fmaf(sc[nt][1], 0.125f, bi1);
            float v2 = fmaf(sc[nt][2], 0.125f, bi0);
            float v3 = fmaf(sc[nt][3], 0.125f, bi1);
            if (mt_) {
                const int tc = t0 + colb;
                if (tc     > S_LEN + srow0)     v0 = -1e30f;
                if (tc + 1 > S_LEN + srow0)     v1 = -1e30f;
                if (tc     > S_LEN + srow0 + 8) v2 = -1e30f;
                if (tc + 1 > S_LEN + srow0 + 8) v3 = -1e30f;
            }
            sc[nt][0] = v0; sc[nt][1] = v1; sc[nt][2] = v2; sc[nt][3] = v3;
            tmax0 = fmaxf(tmax0, fmaxf(v0, v1));
            tmax1 = fmaxf(tmax1, fmaxf(v2, v3));
        }
        tmax0 = fmaxf(tmax0, __shfl_xor_sync(0xffffffffu, tmax0, 1));
        tmax0 = fmaxf(tmax0, __shfl_xor_sync(0xffffffffu, tmax0, 2));
        tmax1 = fmaxf(tmax1, __shfl_xor_sync(0xffffffffu, tmax1, 1));
        tmax1 = fmaxf(tmax1, __shfl_xor_sync(0xffffffffu, tmax1, 2));

        const float mnew0 = fmaxf(m0, tmax0);
        const float mnew1 = fmaxf(m1, tmax1);
        const float c0 = __expf(m0 - mnew0);
        const float c1 = __expf(m1 - mnew1);
        m0 = mnew0; m1 = mnew1;
        l0 *= c0; l1 *= c1;

        const bool doscale = !__all_sync(0xffffffffu, (c0 == 1.f) && (c1 == 1.f));

        float ps0 = 0.f, ps1 = 0.f;
#pragma unroll
        for (int nt = 0; nt < 8; nt++) {
            float p0 = __expf(sc[nt][0] - mnew0);
            float p1 = __expf(sc[nt][1] - mnew0);
            float p2 = __expf(sc[nt][2] - mnew1);
            float p3 = __expf(sc[nt][3] - mnew1);
            ps0 += p0 + p1; ps1 += p2 + p3;
            if (doscale) {
                O[nt][0] *= c0; O[nt][1] *= c0;
                O[nt][2] *= c1; O[nt][3] *= c1;
            }
            const int colp = nt * 8 + 2 * r;
            *(__half2*)&PhH[(size_t)(mw + q) * 72 + colp]     = __floats2half2_rn(p0, p1);
            *(__half2*)&PhH[(size_t)(mw + q + 8) * 72 + colp] = __floats2half2_rn(p2, p3);
        }
        l0 += ps0; l1 += ps1;
        __syncwarp();          // P is warp-private (each warp reads its own rows)

        // ---- O += P @ V (V already resident; prefetch targets other buffer) -
#pragma unroll
        for (int ks = 0; ks < 4; ks++) {
            uint32_t afr[4];
            ldm_x4(afr, sbase + PH_OFF + (uint32_t)(mw + alr) * HROW
                         + (uint32_t)(ks * 32 + alc * 16));
#pragma unroll
            for (int dp = 0; dp < 4; dp++) {
                uint32_t tmp[4];
                ldm_x4_t(tmp, vB
                               + (uint32_t)(ks * 16 + (bg & 1) * 8 + blr) * HROW
                               + (uint32_t)(dp * 32 + (bg >> 1) * 16));
                mma_f16(O[dp * 2],     afr, tmp);
                mma_f16(O[dp * 2 + 1], afr, tmp + 2);
            }
        }
        // no trailing sync: next iteration's top syncthreads covers buf reuse
    }

    // ---- finalize: reduce l over quad, normalize, store fp16 ---------------
    l0 += __shfl_xor_sync(0xffffffffu, l0, 1);
    l0 += __shfl_xor_sync(0xffffffffu, l0, 2);
    l1 += __shfl_xor_sync(0xffffffffu, l1, 1);
    l1 += __shfl_xor_sync(0xffffffffu, l1, 2);
    const float inv0 = 1.f / l0, inv1 = 1.f / l1;

#pragma unroll
    for (int nt = 0; nt < 8; nt++) {
        const int col = nt * 8 + 2 * r;
        const int row0 = qb * 128 + mw + q;
        *(__half2*)(out + ((size_t)(row0 * BATCH + b)) * DMODEL + h * HDIM + col)
            = __floats2half2_rn(O[nt][0] * inv0, O[nt][1] * inv0);
        *(__half2*)(out + ((size_t)((row0 + 8) * BATCH + b)) * DMODEL + h * HDIM + col)
            = __floats2half2_rn(O[nt][2] * inv1, O[nt][3] * inv1);
    }
}

// ---------------- LayerNorm(a0 [+ a1] + res) * g + b -------------------------
__global__ void __launch_bounds__(256)
ln_kernel(const float* __restrict__ a0, const float* __restrict__ a1,
          const float* __restrict__ res,
          const float* __restrict__ g, const float* __restrict__ bta,
          float* __restrict__ out, __half* __restrict__ out_h)
{
    const int row = blockIdx.x;
    const int tid = threadIdx.x;
    const int lane = tid & 31, wrp = tid >> 5;
    __shared__ float red[8];
    __shared__ float bc;

    float vals[4];
    float s = 0.f;
    const float* ar = a0 + (size_t)row * DMODEL;
    const float* br = a1 ? a1 + (size_t)row * DMODEL : nullptr;
    const float* rr = res + (size_t)row * DMODEL;
#pragma unroll
    for (int i = 0; i < 4; i++) {
        int d = tid + i * 256;
        float v = ar[d] + rr[d];
        if (br) v += br[d];
        vals[i] = v;
        s += v;
    }
#pragma unroll
    for (int off = 16; off; off >>= 1) s += __shfl_xor_sync(0xffffffffu, s, off);
    if (lane == 0) red[wrp] = s;
    __syncthreads();
    if (tid == 0) {
        float t = 0.f;
#pragma unroll
        for (int w = 0; w < 8; w++) t += red[w];
        bc = t * (1.f / DMODEL);
    }
    __syncthreads();
    const float mu = bc;

    float vs = 0.f;
#pragma unroll
    for (int i = 0; i < 4; i++) {
        float dd = vals[i] - mu;
        vs += dd * dd;
    }
#pragma unroll
    for (int off = 16; off; off >>= 1) vs += __shfl_xor_sync(0xffffffffu, vs, off);
    __syncthreads();
    if (lane == 0) red[wrp] = vs;
    __syncthreads();
    if (tid == 0) {
        float t = 0.f;
#pragma unroll
        for (int w = 0; w < 8; w++) t += red[w];
        bc = rsqrtf(t * (1.f / DMODEL) + 1e-5f);
    }
    __syncthreads();
    const float rstd = bc;

    float* orow = out + (size_t)row * DMODEL;
    __half* hrow = out_h ? out_h + (size_t)row * DMODEL : nullptr;
#pragma unroll
    for (int i = 0; i < 4; i++) {
        int d = tid + i * 256;
        float vv = (vals[i] - mu) * rstd * g[d] + bta[d];
        orow[d] = vv;
        if (hrow) hrow[d] = __float2half(vv);
    }
}

// ---------------- launcher ---------------------------------------------------
extern "C" void kernel_launch(void* const* d_in, const int* in_sizes, int n_in,
                              void* d_out, int out_size)
{
    const float* x      = (const float*)d_in[0];
    const float* p      = (const float*)d_in[1];
    /* mask d_in[2] is analytic: unused */
    const float* memory = (const float*)d_in[3];
    const float* u_bias = (const float*)d_in[4];
    const float* v_bias = (const float*)d_in[5];
    const float* wq  = (const float*)d_in[6];
    const float* wke = (const float*)d_in[7];
    const float* wkr = (const float*)d_in[8];
    const float* wv  = (const float*)d_in[9];
    const float* wc  = (const float*)d_in[10];
    const float* w1  = (const float*)d_in[11];
    const float* w1b = (const float*)d_in[12];
    const float* w2  = (const float*)d_in[13];
    const float* w2b = (const float*)d_in[14];
    const float* ln1g = (const float*)d_in[15];
    const float* ln1b = (const float*)d_in[16];
    const float* ln2g = (const float*)d_in[17];
    const float* ln2b = (const float*)d_in[18];
    float* out = (float*)d_out;

    float *tbuf, *t2buf, *ubuf, *bias2;
    __half *xh, *memh, *ph, *wqh, *wkeh, *wkrh, *wvh, *wch, *w1h, *w2h;
    __half *qh, *keh, *krh, *vxh, *avh, *uh, *h1h, *kkh, *vh;
    cudaGetSymbolAddress((void**)&tbuf,  g_t);
    cudaGetSymbolAddress((void**)&t2buf, g_t2);
    cudaGetSymbolAddress((void**)&ubuf,  g_u);
    cudaGetSymbolAddress((void**)&xh,    g_xh);
    cudaGetSymbolAddress((void**)&memh,  g_memh);
    cudaGetSymbolAddress((void**)&ph,    g_ph);
    cudaGetSymbolAddress((void**)&wqh,   g_wqh);
    cudaGetSymbolAddress((void**)&wkeh,  g_wkeh);
    cudaGetSymbolAddress((void**)&wkrh,  g_wkrh);
    cudaGetSymbolAddress((void**)&wvh,   g_wvh);
    cudaGetSymbolAddress((void**)&wch,   g_wch);
    cudaGetSymbolAddress((void**)&w1h,   g_w1h);
    cudaGetSymbolAddress((void**)&w2h,   g_w2h);
    cudaGetSymbolAddress((void**)&qh,    g_qh);
    cudaGetSymbolAddress((void**)&keh,   g_keh);
    cudaGetSymbolAddress((void**)&krh,   g_krh);
    cudaGetSymbolAddress((void**)&vxh,   g_vxh);
    cudaGetSymbolAddress((void**)&avh,   g_avh);
    cudaGetSymbolAddress((void**)&uh,    g_uh);
    cudaGetSymbolAddress((void**)&h1h,   g_h1h);
    cudaGetSymbolAddress((void**)&kkh,   g_kkh);
    cudaGetSymbolAddress((void**)&vh,    g_vh);
    cudaGetSymbolAddress((void**)&bias2, g_bias);

    cudaFuncSetAttribute(gemm16_kernel,
                         cudaFuncAttributeMaxDynamicSharedMemorySize, GEMM16_SMEM);
    cudaFuncSetAttribute(flash16_kernel,
                         cudaFuncAttributeMaxDynamicSharedMemorySize, FLASH_SMEM);

    const dim3 blk(256);
    const size_t half = (size_t)ROWS_X * DMODEL;

    // ---- convert inputs + weights to fp16 (one merged launch) ---------------
    {
        CvtSegs cs{};
        int acc = 0, i = 0;
        auto add = [&](const float* s, __half* d, int n8) {
            cs.src[i] = s; cs.dst[i] = d; acc += n8; cs.end8[i] = acc; i++;
        };
        add(x,      xh,   ROWS_X * DMODEL / 8);
        add(memory, memh, ROWS_X * DMODEL / 8);
        add(p,      ph,   ROWS_T * DMODEL / 8);
        add(wq,  wqh,  DMODEL * DMODEL / 8);
        add(wke, wkeh, DMODEL * DMODEL / 8);
        add(wkr, wkrh, DMODEL * DMODEL / 8);
        add(wv,  wvh,  DMODEL * DMODEL / 8);
        add(wc,  wch,  DMODEL * DMODEL / 8);
        add(w1,  w1h,  FFDIM * DMODEL / 8);
        add(w2,  w2h,  FFDIM * DMODEL / 8);
        cs.nseg = i;
        cvt_all_kernel<<<(acc + 255) / 256, blk>>>(cs, acc);
    }

    // ---- all 6 projections in ONE launch (z = 0..6), fp16 in AND out --------
    {
        GemmPtrs gp{};
        gp.A[0] = xh;   gp.W[0] = wqh;  gp.Ch[0] = qh;
        gp.A[1] = xh;   gp.W[1] = wkeh; gp.Ch[1] = keh + half;
        gp.A[2] = xh;   gp.W[2] = wvh;  gp.Ch[2] = vxh + half;
        gp.A[3] = memh; gp.W[3] = wkeh; gp.Ch[3] = keh;
        gp.A[4] = memh; gp.W[4] = wvh;  gp.Ch[4] = vxh;
        gp.A[5] = ph;        gp.W[5] = wkrh; gp.Ch[5] = krh;
        gp.A[6] = ph + half; gp.W[6] = wkrh; gp.Ch[6] = krh + half;
        gemm16_kernel<<<dim3(8, 16, 7), blk, GEMM16_SMEM>>>(
            gp, ROWS_X, DMODEL, DMODEL, DMODEL, 0);
    }

    // prep: fuse KK (fp16), bias (fp32, pre-scaled), V relayout
    prep_kernel<<<ROWS_T, blk>>>(keh, krh, vxh, u_bias, v_bias, kkh, vh, bias2);

    // fp16 flash attention (double-buffered KV)
    flash16_kernel<<<dim3(8, HEADS, BATCH), blk, FLASH_SMEM>>>(
        qh, kkh, vh, bias2, avh);

    // output proj (split-K=2) + LN1 (fused add; emits uh fp16)
    {
        GemmPtrs gp{};
        gp.A[0] = avh;       gp.W[0] = wch;       gp.C[0] = tbuf;
        gp.A[1] = avh + 512; gp.W[1] = wch + 512; gp.C[1] = t2buf;
        gemm16_kernel<<<dim3(8, 16, 2), blk, GEMM16_SMEM>>>(
            gp, ROWS_X, DMODEL, 512, DMODEL, 0);
    }
    ln_kernel<<<ROWS_X, blk>>>(tbuf, t2buf, x, ln1g, ln1b, ubuf, uh);

    // FFN: w1 (relu, fp16 out), w2 (split-K=2) + LN2 (fused add)
    {
        GemmPtrs gp{};
        gp.A[0] = uh; gp.W[0] = w1h; gp.Ch[0] = h1h; gp.bias[0] = w1b;
        gemm16_kernel<<<dim3(32, 16, 1), blk, GEMM16_SMEM>>>(
            gp, ROWS_X, FFDIM, DMODEL, DMODEL, 1);
    }
    {
        GemmPtrs gp{};
        gp.A[0] = h1h;        gp.W[0] = w2h;        gp.C[0] = tbuf;  gp.bias[0] = w2b;
        gp.A[1] = h1h + 2048; gp.W[1] = w2h + 2048; gp.C[1] = t2buf;
        gemm16_kernel<<<dim3(8, 16, 2), blk, GEMM16_SMEM>>>(
            gp, ROWS_X, DMODEL, 2048, FFDIM, 0);
    }
    ln_kernel<<<ROWS_X, blk>>>(tbuf, t2buf, ubuf, ln2g, ln2b, out, nullptr);
}

// round 14
// speedup vs baseline: 1.9585x; 1.0129x over previous
#include <cuda_runtime.h>
#include <cuda_fp16.h>
#include <math.h>
#include <stdint.h>

// Problem constants
#define S_LEN 1024
#define BATCH 2
#define DMODEL 1024
#define HEADS 16
#define HDIM 64
#define TLEN 2048
#define FFDIM 4096
#define ROWS_X (S_LEN * BATCH)     // 2048
#define ROWS_T (TLEN * BATCH)      // 4096

// ---------------- scratch buffers (device globals) ---------------------------
__device__ float g_t [ROWS_X * DMODEL];
__device__ float g_t2[ROWS_X * DMODEL];
__device__ float g_u [ROWS_X * DMODEL];
// split-KV flash partials
__device__ float g_po0[ROWS_X * DMODEL];
__device__ float g_po1[ROWS_X * DMODEL];
__device__ float g_ml [2 * ROWS_X * HEADS * 2];
// fp16 tensors
__device__ __half g_xh  [ROWS_X * DMODEL];
__device__ __half g_memh[ROWS_X * DMODEL];
__device__ __half g_ph  [ROWS_T * DMODEL];
__device__ __half g_wqh [DMODEL * DMODEL];
__device__ __half g_wkeh[DMODEL * DMODEL];
__device__ __half g_wkrh[DMODEL * DMODEL];
__device__ __half g_wvh [DMODEL * DMODEL];
__device__ __half g_wch [DMODEL * DMODEL];
__device__ __half g_w1h [FFDIM * DMODEL];
__device__ __half g_w2h [DMODEL * FFDIM];
__device__ __half g_qh  [ROWS_X * DMODEL];
__device__ __half g_keh [ROWS_T * DMODEL];
__device__ __half g_krh [ROWS_T * DMODEL];
__device__ __half g_vxh [ROWS_T * DMODEL];
__device__ __half g_avh [ROWS_X * DMODEL];
__device__ __half g_uh  [ROWS_X * DMODEL];
__device__ __half g_h1h [ROWS_X * FFDIM];
// flash-prep outputs (fp16 KK / V, fp32 bias pre-scaled by 0.125)
__device__ __half g_kkh [BATCH * HEADS * TLEN * HDIM];
__device__ __half g_vh  [BATCH * HEADS * TLEN * HDIM];
__device__ float  g_bias[BATCH * HEADS * TLEN];

// ---------------- common PTX helpers ----------------------------------------
__device__ __forceinline__ void cp_async16(uint32_t saddr, const void* gptr) {
    asm volatile("cp.async.cg.shared.global [%0], [%1], 16;\n"
                 :: "r"(saddr), "l"(gptr));
}
__device__ __forceinline__ void cp_commit() {
    asm volatile("cp.async.commit_group;\n");
}
template <int N>
__device__ __forceinline__ void cp_wait() {
    asm volatile("cp.async.wait_group %0;\n" :: "n"(N));
}
__device__ __forceinline__ void mma_f16(float* d, const uint32_t* a, const uint32_t* b) {
    asm volatile(
        "mma.sync.aligned.m16n8k16.row.col.f32.f16.f16.f32 "
        "{%0,%1,%2,%3}, {%4,%5,%6,%7}, {%8,%9}, {%0,%1,%2,%3};\n"
        : "+f"(d[0]), "+f"(d[1]), "+f"(d[2]), "+f"(d[3])
        : "r"(a[0]), "r"(a[1]), "r"(a[2]), "r"(a[3]), "r"(b[0]), "r"(b[1]));
}
__device__ __forceinline__ void ldm_x4(uint32_t* r, uint32_t addr) {
    asm volatile("ldmatrix.sync.aligned.m8n8.x4.shared.b16 {%0,%1,%2,%3}, [%4];"
                 : "=r"(r[0]), "=r"(r[1]), "=r"(r[2]), "=r"(r[3]) : "r"(addr));
}
__device__ __forceinline__ void ldm_x4_t(uint32_t* r, uint32_t addr) {
    asm volatile("ldmatrix.sync.aligned.m8n8.x4.trans.shared.b16 {%0,%1,%2,%3}, [%4];"
                 : "=r"(r[0]), "=r"(r[1]), "=r"(r[2]), "=r"(r[3]) : "r"(addr));
}

// ---------------- fp32 -> fp16 conversion (merged segments) ------------------
#define MAXSEG 10
struct CvtSegs {
    const float* src[MAXSEG];
    __half*      dst[MAXSEG];
    int          end8[MAXSEG];
    int          nseg;
};

__global__ void __launch_bounds__(256)
cvt_all_kernel(CvtSegs segs, int total8)
{
    int idx = blockIdx.x * 256 + threadIdx.x;
    if (idx >= total8) return;
    int s = 0;
#pragma unroll
    for (int i = 0; i < MAXSEG; i++)
        if (i < segs.nseg && idx >= segs.end8[i]) s = i + 1;
    const int off = idx - (s ? segs.end8[s - 1] : 0);

    const float4* s4 = (const float4*)(segs.src[s] + (size_t)off * 8);
    float4 a = s4[0], b = s4[1];
    __half2 h[4];
    h[0] = __floats2half2_rn(a.x, a.y);
    h[1] = __floats2half2_rn(a.z, a.w);
    h[2] = __floats2half2_rn(b.x, b.y);
    h[3] = __floats2half2_rn(b.z, b.w);
    *(uint4*)(segs.dst[s] + (size_t)off * 8) = *(uint4*)h;
}

// ---------------- fp16 tensor-core GEMM (3-stage pipeline) -------------------
struct GemmPtrs {
    const __half* A[7];
    const __half* W[7];
    float*        C[7];
    __half*       Ch[7];
    const float*  bias[7];
};

#define HROW 144u                      // smem row stride in bytes (72 halves)
#define TILE16 (128u * HROW)           // 18432 B per operand tile
#define STAGE16 (2u * TILE16)          // 36864 B per stage
#define GEMM16_SMEM (3 * 36864)        // 110592 B (3 stages)

__global__ void __launch_bounds__(256)
gemm16_kernel(GemmPtrs ptrs, int M, int N, int Klen, int Kstride, int act)
{
    extern __shared__ char smem[];
    const uint32_t sbase = (uint32_t)__cvta_generic_to_shared(smem);

    const __half* A    = ptrs.A[blockIdx.z];
    const __half* W    = ptrs.W[blockIdx.z];
    float*        C    = ptrs.C[blockIdx.z];
    __half*       Ch   = ptrs.Ch[blockIdx.z];
    const float*  bias = ptrs.bias[blockIdx.z];

    const int tid = threadIdx.x;
    const int lane = tid & 31, wrp = tid >> 5;
    const int wm = wrp & 1, wn = wrp >> 1;
    const int q = lane >> 2, r = lane & 3;
    const int m0 = blockIdx.y * 128;
    const int n0 = blockIdx.x * 128;

    float acc[4][4][4];
#pragma unroll
    for (int i = 0; i < 4; i++)
#pragma unroll
        for (int j = 0; j < 4; j++)
#pragma unroll
            for (int e = 0; e < 4; e++) acc[i][j][e] = 0.f;

    auto issue = [&](int t) {              // tile index; stage = t % 3
        const uint32_t so = sbase + (uint32_t)(t % 3) * STAGE16;
        const int k0 = t << 5;             // halves
#pragma unroll
        for (int i = 0; i < 2; i++) {
            int id = tid + i * 256;
            int row = id >> 2, c = id & 3;
            uint32_t d = (uint32_t)row * HROW + (uint32_t)c * 16u;
            cp_async16(so + d,          A + (size_t)(m0 + row) * Kstride + k0 + c * 8);
            cp_async16(so + TILE16 + d, W + (size_t)(n0 + row) * Kstride + k0 + c * 8);
        }
    };

    const int KT = Klen >> 5;
    issue(0);
    cp_commit();
    if (KT > 1) { issue(1); cp_commit(); }

    const int alr = lane & 15, alc = lane >> 4;
    const int bg = lane >> 3,  blr = lane & 7;

    for (int kt = 0; kt < KT; kt++) {
        if (kt == KT - 1) { cp_wait<0>(); } else { cp_wait<1>(); }
        __syncthreads();
        if (kt + 2 < KT) { issue(kt + 2); cp_commit(); }

        const uint32_t aBase = sbase + (uint32_t)(kt % 3) * STAGE16;
        const uint32_t bBase = aBase + TILE16;

#pragma unroll
        for (int ks = 0; ks < 2; ks++) {
            uint32_t afr[4][4];
#pragma unroll
            for (int mt = 0; mt < 4; mt++) {
                uint32_t addr = aBase +
                    (uint32_t)(wm * 64 + mt * 16 + alr) * HROW +
                    (uint32_t)(ks * 32 + alc * 16);
                ldm_x4(afr[mt], addr);
            }
            uint32_t bfr[4][2];
#pragma unroll
            for (int ntp = 0; ntp < 2; ntp++) {
                uint32_t addr = bBase +
                    (uint32_t)(wn * 32 + ntp * 16 + (bg >> 1) * 8 + blr) * HROW +
                    (uint32_t)(ks * 32 + (bg & 1) * 16);
                uint32_t tmp[4];
                ldm_x4(tmp, addr);
                bfr[ntp * 2 + 0][0] = tmp[0]; bfr[ntp * 2 + 0][1] = tmp[1];
                bfr[ntp * 2 + 1][0] = tmp[2]; bfr[ntp * 2 + 1][1] = tmp[3];
            }
#pragma unroll
            for (int mt = 0; mt < 4; mt++)
#pragma unroll
                for (int nt = 0; nt < 4; nt++)
                    mma_f16(acc[mt][nt], afr[mt], bfr[nt]);
        }
    }

#pragma unroll
    for (int mt = 0; mt < 4; mt++) {
        const int row0 = m0 + wm * 64 + mt * 16 + q;
#pragma unroll
        for (int nt = 0; nt < 4; nt++) {
            const int col = n0 + wn * 32 + nt * 8 + r * 2;
            float b0 = bias ? bias[col]     : 0.f;
            float b1 = bias ? bias[col + 1] : 0.f;
            float v0 = acc[mt][nt][0] + b0, v1 = acc[mt][nt][1] + b1;
            float v2 = acc[mt][nt][2] + b0, v3 = acc[mt][nt][3] + b1;
            if (act == 1) {
                v0 = fmaxf(v0, 0.f); v1 = fmaxf(v1, 0.f);
                v2 = fmaxf(v2, 0.f); v3 = fmaxf(v3, 0.f);
            }
            if (C) {
                *(float2*)(C + (size_t)row0 * N + col)       = make_float2(v0, v1);
                *(float2*)(C + (size_t)(row0 + 8) * N + col) = make_float2(v2, v3);
            }
            if (Ch) {
                *(__half2*)(Ch + (size_t)row0 * N + col)       = __floats2half2_rn(v0, v1);
                *(__half2*)(Ch + (size_t)(row0 + 8) * N + col) = __floats2half2_rn(v2, v3);
            }
        }
    }
}

// ---------------- prep (fp16 in): KK = ke+kr, bias = (u.ke+v.kr)/8, V copy ---
__global__ void __launch_bounds__(256)
prep_kernel(const __half* __restrict__ keh, const __half* __restrict__ krh,
            const __half* __restrict__ vin,
            const float* __restrict__ ub, const float* __restrict__ vb,
            __half* __restrict__ kkh, __half* __restrict__ vh,
            float* __restrict__ biasO)
{
    const int row = blockIdx.x;          // = t*BATCH + b
    const int t = row / BATCH, b = row % BATCH;
    const int tid = threadIdx.x;
    const int h = tid >> 4, l16 = tid & 15, d0 = l16 * 4;

    const size_t src = (size_t)row * DMODEL + h * HDIM + d0;
    uint2 ke2 = *(const uint2*)(keh + src);
    uint2 kr2 = *(const uint2*)(krh + src);
    uint2 vv2 = *(const uint2*)(vin + src);

    float2 ke01 = __half22float2(*(__half2*)&ke2.x);
    float2 ke23 = __half22float2(*(__half2*)&ke2.y);
    float2 kr01 = __half22float2(*(__half2*)&kr2.x);
    float2 kr23 = __half22float2(*(__half2*)&kr2.y);

    const size_t dst = ((size_t)(b * HEADS + h) * TLEN + t) * HDIM + d0;
    __half2 kk01 = __floats2half2_rn(ke01.x + kr01.x, ke01.y + kr01.y);
    __half2 kk23 = __floats2half2_rn(ke23.x + kr23.x, ke23.y + kr23.y);
    *(uint2*)(kkh + dst) = make_uint2(*(uint32_t*)&kk01, *(uint32_t*)&kk23);
    *(uint2*)(vh  + dst) = vv2;          // passthrough relayout

    float4 u4 = *(const float4*)(ub + h * HDIM + d0);
    float4 w4 = *(const float4*)(vb + h * HDIM + d0);
    float bsum = u4.x * ke01.x + u4.y * ke01.y + u4.z * ke23.x + u4.w * ke23.y
               + w4.x * kr01.x + w4.y * kr01.y + w4.z * kr23.x + w4.w * kr23.y;
#pragma unroll
    for (int off = 8; off; off >>= 1)
        bsum += __shfl_xor_sync(0xffffffffu, bsum, off, 16);
    if (l16 == 0)
        biasO[(size_t)(b * HEADS + h) * TLEN + t] = bsum * 0.125f;  // pre-scaled
}

// ---------------- fp16 flash attention (split-KV, double-buffered) -----------
// grid.x = 16: encodes (qb, half). Each CTA handles half the key range of a
// 128-query block and writes UNNORMALIZED O (fp32) + per-row (m, l).
// smem (bytes): QH 128x144 | PH 128x144 | KK[2] 64x144 | V[2] 64x144 | bias[2]
#define QH_OFF 0u
#define PH_OFF 18432u
#define KK_OFF 36864u          // + buf*9216
#define V_OFF  55296u          // + buf*9216
#define BI_OFF 73728u          // + buf*256
#define KVBUF  9216u
#define FLASH_SMEM 74240
#define ML_HALF (ROWS_X * HEADS * 2)

__global__ void __launch_bounds__(256, 2)
flash16_kernel(const __half* __restrict__ qh,
               const __half* __restrict__ kkh,
               const __half* __restrict__ vhg,
               const float* __restrict__ biasG,
               float* __restrict__ po0, float* __restrict__ po1,
               float* __restrict__ ml)
{
    extern __shared__ char fsm[];
    const uint32_t sbase = (uint32_t)__cvta_generic_to_shared(fsm);
    __half* PhH = (__half*)(fsm + PH_OFF);

    // heavy q-blocks first; x encodes (qb, half)
    const int xid = blockIdx.x;
    const int qb = 7 - (xid >> 1);
    const int hf = xid & 1;
    const int h = blockIdx.y, b = blockIdx.z;
    const int tid = threadIdx.x;
    const int lane = tid & 31, wid = tid >> 5;
    const int q = lane >> 2, r = lane & 3;
    const int mw = wid * 16;
    const int alr = lane & 15, alc = lane >> 4;
    const int bg = lane >> 3,  blr = lane & 7;

    const int ntAll  = 18 + 2 * qb;           // always even
    const int tstart = hf ? (ntAll >> 1) : 0;
    const int tend   = hf ? ntAll : (ntAll >> 1);
    float* po = hf ? po1 : po0;
    float* mlp = ml + (size_t)hf * ML_HALF;

    const size_t  bh   = (size_t)(b * HEADS + h) * TLEN;
    const __half* kkbh = kkh + bh * HDIM;
    const __half* vbh  = vhg + bh * HDIM;
    const float*  bibh = biasG + bh;

    auto issueQ = [&]() {
#pragma unroll
        for (int it = 0; it < 4; it++) {
            int idx = tid + it * 256;
            int row = idx >> 3, c = idx & 7;
            cp_async16(sbase + QH_OFF + (uint32_t)row * HROW + (uint32_t)c * 16u,
                       qh + ((size_t)((qb * 128 + row) * BATCH + b)) * DMODEL
                          + h * HDIM + c * 8);
        }
    };
    auto issueKV = [&](int t0, int buf) {
        const uint32_t kkB = sbase + KK_OFF + (uint32_t)buf * KVBUF;
        const uint32_t vB  = sbase + V_OFF  + (uint32_t)buf * KVBUF;
#pragma unroll
        for (int it = 0; it < 2; it++) {
            int idx = tid + it * 256;
            int row = idx >> 3, c = idx & 7;
            const uint32_t d = (uint32_t)row * HROW + (uint32_t)c * 16u;
            cp_async16(kkB + d, kkbh + (size_t)(t0 + row) * HDIM + c * 8);
            cp_async16(vB  + d, vbh  + (size_t)(t0 + row) * HDIM + c * 8);
        }
        if (tid < 16)
            cp_async16(sbase + BI_OFF + (uint32_t)(buf * 256 + tid * 16),
                       bibh + t0 + tid * 4);
    };

    issueQ();
    issueKV(tstart * 64, tstart & 1);
    cp_commit();

    float m0 = -1e30f, m1 = -1e30f, l0 = 0.f, l1 = 0.f;
    float O[8][4];
#pragma unroll
    for (int nt = 0; nt < 8; nt++)
#pragma unroll
        for (int e = 0; e < 4; e++) O[nt][e] = 0.f;

    const int srow0 = qb * 128 + mw + q;

    for (int tt = tstart; tt < tend; tt++) {
        const int t0 = tt * 64;
        const int buf = tt & 1;
        const bool more = (tt + 1 < tend);

        cp_wait<0>();
        __syncthreads();

        if (more) { issueKV(t0 + 64, buf ^ 1); cp_commit(); }

        const uint32_t kkB = sbase + KK_OFF + (uint32_t)buf * KVBUF;
        const uint32_t vB  = sbase + V_OFF  + (uint32_t)buf * KVBUF;
        const float* bS = (const float*)(fsm + BI_OFF + buf * 256);

        // ---- S = Q @ KK^T  (fp16 mma) --------------------------------------
        float sc[8][4];
#pragma unroll
        for (int nt = 0; nt < 8; nt++)
#pragma unroll
            for (int e = 0; e < 4; e++) sc[nt][e] = 0.f;

#pragma unroll
        for (int ks = 0; ks < 4; ks++) {
            uint32_t afr[4];
            ldm_x4(afr, sbase + QH_OFF + (uint32_t)(mw + alr) * HROW
                         + (uint32_t)(ks * 32 + alc * 16));
#pragma unroll
            for (int tb = 0; tb < 4; tb++) {
                uint32_t tmp[4];
                ldm_x4(tmp, kkB
                             + (uint32_t)(tb * 16 + (bg >> 1) * 8 + blr) * HROW
                             + (uint32_t)(ks * 32 + (bg & 1) * 16));
                mma_f16(sc[tb * 2],     afr, tmp);
                mma_f16(sc[tb * 2 + 1], afr, tmp + 2);
            }
        }

        // ---- bias(pre-scaled) + causal mask + online softmax ----------------
        const bool mt_ = (tt >= 16 + 2 * qb);
        float tmax0 = -1e30f, tmax1 = -1e30f;
#pragma unroll
        for (int nt = 0; nt < 8; nt++) {
            const int colb = nt * 8 + 2 * r;
            const float bi0 = bS[colb], bi1 = bS[colb + 1];
            float v0 = fmaf(sc[nt][0], 0.125f, bi0);
            float v1 = fmaf(sc[nt][1], 0.125f, bi1);
            float v2 = fmaf(sc[nt][2], 0.125f, bi0);
            float v3 = fmaf(sc[nt][3], 0.125f, bi1);
            if (mt_) {
                const int tc = t0 + colb;
                if (tc     > S_LEN + srow0)     v0 = -1e30f;
                if (tc + 1 > S_LEN + srow0)     v1 = -1e30f;
                if (tc     > S_LEN + srow0 + 8) v2 = -1e30f;
                if (tc + 1 > S_LEN + srow0 + 8) v3 = -1e30f;
            }
            sc[nt][0] = v0; sc[nt][1] = v1; sc[nt][2] = v2; sc[nt][3] = v3;
            tmax0 = fmaxf(tmax0, fmaxf(v0, v1));
            tmax1 = fmaxf(tmax1, fmaxf(v2, v3));
        }
        tmax0 = fmaxf(tmax0, __shfl_xor_sync(0xffffffffu, tmax0, 1));
        tmax0 = fmaxf(tmax0, __shfl_xor_sync(0xffffffffu, tmax0, 2));
        tmax1 = fmaxf(tmax1, __shfl_xor_sync(0xffffffffu, tmax1, 1));
        tmax1 = fmaxf(tmax1, __shfl_xor_sync(0xffffffffu, tmax1, 2));

        const float mnew0 = fmaxf(m0, tmax0);
        const float mnew1 = fmaxf(m1, tmax1);
        const float c0 = __expf(m0 - mnew0);
        const float c1 = __expf(m1 - mnew1);
        m0 = mnew0; m1 = mnew1;
        l0 *= c0; l1 *= c1;

        const bool doscale = !__all_sync(0xffffffffu, (c0 == 1.f) && (c1 == 1.f));

        float ps0 = 0.f, ps1 = 0.f;
#pragma unroll
        for (int nt = 0; nt < 8; nt++) {
            float p0 = __expf(sc[nt][0] - mnew0);
            float p1 = __expf(sc[nt][1] - mnew0);
            float p2 = __expf(sc[nt][2] - mnew1);
            float p3 = __expf(sc[nt][3] - mnew1);
            ps0 += p0 + p1; ps1 += p2 + p3;
            if (doscale) {
                O[nt][0] *= c0; O[nt][1] *= c0;
                O[nt][2] *= c1; O[nt][3] *= c1;
            }
            const int colp = nt * 8 + 2 * r;
            *(__half2*)&PhH[(size_t)(mw + q) * 72 + colp]     = __floats2half2_rn(p0, p1);
            *(__half2*)&PhH[(size_t)(mw + q + 8) * 72 + colp] = __floats2half2_rn(p2, p3);
        }
        l0 += ps0; l1 += ps1;
        __syncwarp();          // P is warp-private

        // ---- O += P @ V ------------------------------------------------------
#pragma unroll
        for (int ks = 0; ks < 4; ks++) {
            uint32_t afr[4];
            ldm_x4(afr, sbase + PH_OFF + (uint32_t)(mw + alr) * HROW
                         + (uint32_t)(ks * 32 + alc * 16));
#pragma unroll
            for (int dp = 0; dp < 4; dp++) {
                uint32_t tmp[4];
                ldm_x4_t(tmp, vB
                               + (uint32_t)(ks * 16 + (bg & 1) * 8 + blr) * HROW
                               + (uint32_t)(dp * 32 + (bg >> 1) * 16));
                mma_f16(O[dp * 2],     afr, tmp);
                mma_f16(O[dp * 2 + 1], afr, tmp + 2);
            }
        }
        // next iteration's top syncthreads covers buf reuse
    }

    // ---- finalize: reduce l over quad; store UNNORMALIZED O (fp32) + (m,l) --
    l0 += __shfl_xor_sync(0xffffffffu, l0, 1);
    l0 += __shfl_xor_sync(0xffffffffu, l0, 2);
    l1 += __shfl_xor_sync(0xffffffffu, l1, 1);
    l1 += __shfl_xor_sync(0xffffffffu, l1, 2);

    const int row0 = qb * 128 + mw + q;
#pragma unroll
    for (int nt = 0; nt < 8; nt++) {
        const int col = nt * 8 + 2 * r;
        *(float2*)(po + ((size_t)(row0 * BATCH + b)) * DMODEL + h * HDIM + col)
            = make_float2(O[nt][0], O[nt][1]);
        *(float2*)(po + ((size_t)((row0 + 8) * BATCH + b)) * DMODEL + h * HDIM + col)
            = make_float2(O[nt][2], O[nt][3]);
    }
    if (r == 0) {
        const size_t i0 = (((size_t)(row0 * BATCH + b)) * HEADS + h) * 2;
        mlp[i0]     = m0;
        mlp[i0 + 1] = l0;
        const size_t i1 = (((size_t)((row0 + 8) * BATCH + b)) * HEADS + h) * 2;
        mlp[i1]     = m1;
        mlp[i1 + 1] = l1;
    }
}

// ---------------- combine split-KV partials -> fp16 av -----------------------
__global__ void __launch_bounds__(256)
combine_kernel(const float* __restrict__ po0, const float* __restrict__ po1,
               const float* __restrict__ ml, __half* __restrict__ out)
{
    const int row = blockIdx.x;          // = s*BATCH + b
    const int tid = threadIdx.x;
    const int d0 = tid * 4;
    const int h = d0 >> 6;

    const float* ml0 = ml + ((size_t)row * HEADS + h) * 2;
    const float* ml1 = ml0 + ML_HALF;
    const float m0 = ml0[0], l0 = ml0[1];
    const float m1 = ml1[0], l1 = ml1[1];
    const float M  = fmaxf(m0, m1);
    float w0 = __expf(m0 - M), w1 = __expf(m1 - M);
    const float inv = 1.f / (l0 * w0 + l1 * w1);
    w0 *= inv; w1 *= inv;

    const float4 a = *(const float4*)(po0 + (size_t)row * DMODEL + d0);
    const float4 c = *(const float4*)(po1 + (size_t)row * DMODEL + d0);
    __half2 o01 = __floats2half2_rn(a.x * w0 + c.x * w1, a.y * w0 + c.y * w1);
    __half2 o23 = __floats2half2_rn(a.z * w0 + c.z * w1, a.w * w0 + c.w * w1);
    *(uint2*)(out + (size_t)row * DMODEL + d0)
        = make_uint2(*(uint32_t*)&o01, *(uint32_t*)&o23);
}

// ---------------- LayerNorm(a0 [+ a1] + res) * g + b -------------------------
__global__ void __launch_bounds__(256)
ln_kernel(const float* __restrict__ a0, const float* __restrict__ a1,
          const float* __restrict__ res,
          const float* __restrict__ g, const float* __restrict__ bta,
          float* __restrict__ out, __half* __restrict__ out_h)
{
    const int row = blockIdx.x;
    const int tid = threadIdx.x;
    const int lane = tid & 31, wrp = tid >> 5;
    __shared__ float red[8];
    __shared__ float bc;

    float vals[4];
    float s = 0.f;
    const float* ar = a0 + (size_t)row * DMODEL;
    const float* br = a1 ? a1 + (size_t)row * DMODEL : nullptr;
    const float* rr = res + (size_t)row * DMODEL;
#pragma unroll
    for (int i = 0; i < 4; i++) {
        int d = tid + i * 256;
        float v = ar[d] + rr[d];
        if (br) v += br[d];
        vals[i] = v;
        s += v;
    }
#pragma unroll
    for (int off = 16; off; off >>= 1) s += __shfl_xor_sync(0xffffffffu, s, off);
    if (lane == 0) red[wrp] = s;
    __syncthreads();
    if (tid == 0) {
        float t = 0.f;
#pragma unroll
        for (int w = 0; w < 8; w++) t += red[w];
        bc = t * (1.f / DMODEL);
    }
    __syncthreads();
    const float mu = bc;

    float vs = 0.f;
#pragma unroll
    for (int i = 0; i < 4; i++) {
        float dd = vals[i] - mu;
        vs += dd * dd;
    }
#pragma unroll
    for (int off = 16; off; off >>= 1) vs += __shfl_xor_sync(0xffffffffu, vs, off);
    __syncthreads();
    if (lane == 0) red[wrp] = vs;
    __syncthreads();
    if (tid == 0) {
        float t = 0.f;
#pragma unroll
        for (int w = 0; w < 8; w++) t += red[w];
        bc = rsqrtf(t * (1.f / DMODEL) + 1e-5f);
    }
    __syncthreads();
    const float rstd = bc;

    float* orow = out + (size_t)row * DMODEL;
    __half* hrow = out_h ? out_h + (size_t)row * DMODEL : nullptr;
#pragma unroll
    for (int i = 0; i < 4; i++) {
        int d = tid + i * 256;
        float vv = (vals[i] - mu) * rstd * g[d] + bta[d];
        orow[d] = vv;
        if (hrow) hrow[d] = __float2half(vv);
    }
}

// ---------------- launcher ---------------------------------------------------
extern "C" void kernel_launch(void* const* d_in, const int* in_sizes, int n_in,
                              void* d_out, int out_size)
{
    const float* x      = (const float*)d_in[0];
    const float* p      = (const float*)d_in[1];
    /* mask d_in[2] is analytic: unused */
    const float* memory = (const float*)d_in[3];
    const float* u_bias = (const float*)d_in[4];
    const float* v_bias = (const float*)d_in[5];
    const float* wq  = (const float*)d_in[6];
    const float* wke = (const float*)d_in[7];
    const float* wkr = (const float*)d_in[8];
    const float* wv  = (const float*)d_in[9];
    const float* wc  = (const float*)d_in[10];
    const float* w1  = (const float*)d_in[11];
    const float* w1b = (const float*)d_in[12];
    const float* w2  = (const float*)d_in[13];
    const float* w2b = (const float*)d_in[14];
    const float* ln1g = (const float*)d_in[15];
    const float* ln1b = (const float*)d_in[16];
    const float* ln2g = (const float*)d_in[17];
    const float* ln2b = (const float*)d_in[18];
    float* out = (float*)d_out;

    float *tbuf, *t2buf, *ubuf, *bias2, *po0, *po1, *mlb;
    __half *xh, *memh, *ph, *wqh, *wkeh, *wkrh, *wvh, *wch, *w1h, *w2h;
    __half *qh, *keh, *krh, *vxh, *avh, *uh, *h1h, *kkh, *vh;
    cudaGetSymbolAddress((void**)&tbuf,  g_t);
    cudaGetSymbolAddress((void**)&t2buf, g_t2);
    cudaGetSymbolAddress((void**)&ubuf,  g_u);
    cudaGetSymbolAddress((void**)&po0,   g_po0);
    cudaGetSymbolAddress((void**)&po1,   g_po1);
    cudaGetSymbolAddress((void**)&mlb,   g_ml);
    cudaGetSymbolAddress((void**)&xh,    g_xh);
    cudaGetSymbolAddress((void**)&memh,  g_memh);
    cudaGetSymbolAddress((void**)&ph,    g_ph);
    cudaGetSymbolAddress((void**)&wqh,   g_wqh);
    cudaGetSymbolAddress((void**)&wkeh,  g_wkeh);
    cudaGetSymbolAddress((void**)&wkrh,  g_wkrh);
    cudaGetSymbolAddress((void**)&wvh,   g_wvh);
    cudaGetSymbolAddress((void**)&wch,   g_wch);
    cudaGetSymbolAddress((void**)&w1h,   g_w1h);
    cudaGetSymbolAddress((void**)&w2h,   g_w2h);
    cudaGetSymbolAddress((void**)&qh,    g_qh);
    cudaGetSymbolAddress((void**)&keh,   g_keh);
    cudaGetSymbolAddress((void**)&krh,   g_krh);
    cudaGetSymbolAddress((void**)&vxh,   g_vxh);
    cudaGetSymbolAddress((void**)&avh,   g_avh);
    cudaGetSymbolAddress((void**)&uh,    g_uh);
    cudaGetSymbolAddress((void**)&h1h,   g_h1h);
    cudaGetSymbolAddress((void**)&kkh,   g_kkh);
    cudaGetSymbolAddress((void**)&vh,    g_vh);
    cudaGetSymbolAddress((void**)&bias2, g_bias);

    cudaFuncSetAttribute(gemm16_kernel,
                         cudaFuncAttributeMaxDynamicSharedMemorySize, GEMM16_SMEM);
    cudaFuncSetAttribute(flash16_kernel,
                         cudaFuncAttributeMaxDynamicSharedMemorySize, FLASH_SMEM);

    const dim3 blk(256);
    const size_t half = (size_t)ROWS_X * DMODEL;

    // ---- convert inputs + weights to fp16 (one merged launch) ---------------
    {
        CvtSegs cs{};
        int acc = 0, i = 0;
        auto add = [&](const float* s, __half* d, int n8) {
            cs.src[i] = s; cs.dst[i] = d; acc += n8; cs.end8[i] = acc; i++;
        };
        add(x,      xh,   ROWS_X * DMODEL / 8);
        add(memory, memh, ROWS_X * DMODEL / 8);
        add(p,      ph,   ROWS_T * DMODEL / 8);
        add(wq,  wqh,  DMODEL * DMODEL / 8);
        add(wke, wkeh, DMODEL * DMODEL / 8);
        add(wkr, wkrh, DMODEL * DMODEL / 8);
        add(wv,  wvh,  DMODEL * DMODEL / 8);
        add(wc,  wch,  DMODEL * DMODEL / 8);
        add(w1,  w1h,  FFDIM * DMODEL / 8);
        add(w2,  w2h,  FFDIM * DMODEL / 8);
        cs.nseg = i;
        cvt_all_kernel<<<(acc + 255) / 256, blk>>>(cs, acc);
    }

    // ---- all 6 projections in ONE launch (z = 0..6), fp16 in AND out --------
    {
        GemmPtrs gp{};
        gp.A[0] = xh;   gp.W[0] = wqh;  gp.Ch[0] = qh;
        gp.A[1] = xh;   gp.W[1] = wkeh; gp.Ch[1] = keh + half;
        gp.A[2] = xh;   gp.W[2] = wvh;  gp.Ch[2] = vxh + half;
        gp.A[3] = memh; gp.W[3] = wkeh; gp.Ch[3] = keh;
        gp.A[4] = memh; gp.W[4] = wvh;  gp.Ch[4] = vxh;
        gp.A[5] = ph;        gp.W[5] = wkrh; gp.Ch[5] = krh;
        gp.A[6] = ph + half; gp.W[6] = wkrh; gp.Ch[6] = krh + half;
        gemm16_kernel<<<dim3(8, 16, 7), blk, GEMM16_SMEM>>>(
            gp, ROWS_X, DMODEL, DMODEL, DMODEL, 0);
    }

    // prep: fuse KK (fp16), bias (fp32, pre-scaled), V relayout
    prep_kernel<<<ROWS_T, blk>>>(keh, krh, vxh, u_bias, v_bias, kkh, vh, bias2);

    // split-KV fp16 flash attention + combine
    flash16_kernel<<<dim3(16, HEADS, BATCH), blk, FLASH_SMEM>>>(
        qh, kkh, vh, bias2, po0, po1, mlb);
    combine_kernel<<<ROWS_X, blk>>>(po0, po1, mlb, avh);

    // output proj (split-K=2) + LN1 (fused add; emits uh fp16)
    {
        GemmPtrs gp{};
        gp.A[0] = avh;       gp.W[0] = wch;       gp.C[0] = tbuf;
        gp.A[1] = avh + 512; gp.W[1] = wch + 512; gp.C[1] = t2buf;
        gemm16_kernel<<<dim3(8, 16, 2), blk, GEMM16_SMEM>>>(
            gp, ROWS_X, DMODEL, 512, DMODEL, 0);
    }
    ln_kernel<<<ROWS_X, blk>>>(tbuf, t2buf, x, ln1g, ln1b, ubuf, uh);

    // FFN: w1 (relu, fp16 out), w2 (split-K=2) + LN2 (fused add)
    {
        GemmPtrs gp{};
        gp.A[0] = uh; gp.W[0] = w1h; gp.Ch[0] = h1h; gp.bias[0] = w1b;
        gemm16_kernel<<<dim3(32, 16, 1), blk, GEMM16_SMEM>>>(
            gp, ROWS_X, FFDIM, DMODEL, DMODEL, 1);
    }
    {
        GemmPtrs gp{};
        gp.A[0] = h1h;        gp.W[0] = w2h;        gp.C[0] = tbuf;  gp.bias[0] = w2b;
        gp.A[1] = h1h + 2048; gp.W[1] = w2h + 2048; gp.C[1] = t2buf;
        gemm16_kernel<<<dim3(8, 16, 2), blk, GEMM16_SMEM>>>(
            gp, ROWS_X, DMODEL, 2048, FFDIM, 0);
    }
    ln_kernel<<<ROWS_X, blk>>>(tbuf, t2buf, ubuf, ln2g, ln2b, out, nullptr);
}

// round 15
// speedup vs baseline: 2.0835x; 1.0638x over previous
#include <cuda_runtime.h>
#include <cuda_fp16.h>
#include <math.h>
#include <stdint.h>

// Problem constants
#define S_LEN 1024
#define BATCH 2
#define DMODEL 1024
#define HEADS 16
#define HDIM 64
#define TLEN 2048
#define FFDIM 4096
#define ROWS_X (S_LEN * BATCH)     // 2048
#define ROWS_T (TLEN * BATCH)      // 4096
#define NSPLIT 4

// ---------------- scratch buffers (device globals) ---------------------------
__device__ float g_t [ROWS_X * DMODEL];
__device__ float g_t2[ROWS_X * DMODEL];
__device__ float g_u [ROWS_X * DMODEL];
// split-KV flash partials
__device__ float g_po [NSPLIT * ROWS_X * DMODEL];
__device__ float g_ml [NSPLIT * ROWS_X * HEADS * 2];
// fp16 tensors
__device__ __half g_xh  [ROWS_X * DMODEL];
__device__ __half g_memh[ROWS_X * DMODEL];
__device__ __half g_ph  [ROWS_T * DMODEL];
__device__ __half g_wqh [DMODEL * DMODEL];
__device__ __half g_wkeh[DMODEL * DMODEL];
__device__ __half g_wkrh[DMODEL * DMODEL];
__device__ __half g_wvh [DMODEL * DMODEL];
__device__ __half g_wch [DMODEL * DMODEL];
__device__ __half g_w1h [FFDIM * DMODEL];
__device__ __half g_w2h [DMODEL * FFDIM];
__device__ __half g_qh  [ROWS_X * DMODEL];
__device__ __half g_keh [ROWS_T * DMODEL];
__device__ __half g_krh [ROWS_T * DMODEL];
__device__ __half g_avh [ROWS_X * DMODEL];
__device__ __half g_uh  [ROWS_X * DMODEL];
__device__ __half g_h1h [ROWS_X * FFDIM];
// flash-prep outputs (fp16 KK; V written directly by projection; fp32 bias/8)
__device__ __half g_kkh [BATCH * HEADS * TLEN * HDIM];
__device__ __half g_vh  [BATCH * HEADS * TLEN * HDIM];
__device__ float  g_bias[BATCH * HEADS * TLEN];

// ---------------- common PTX helpers ----------------------------------------
__device__ __forceinline__ void cp_async16(uint32_t saddr, const void* gptr) {
    asm volatile("cp.async.cg.shared.global [%0], [%1], 16;\n"
                 :: "r"(saddr), "l"(gptr));
}
__device__ __forceinline__ void cp_commit() {
    asm volatile("cp.async.commit_group;\n");
}
template <int N>
__device__ __forceinline__ void cp_wait() {
    asm volatile("cp.async.wait_group %0;\n" :: "n"(N));
}
__device__ __forceinline__ void mma_f16(float* d, const uint32_t* a, const uint32_t* b) {
    asm volatile(
        "mma.sync.aligned.m16n8k16.row.col.f32.f16.f16.f32 "
        "{%0,%1,%2,%3}, {%4,%5,%6,%7}, {%8,%9}, {%0,%1,%2,%3};\n"
        : "+f"(d[0]), "+f"(d[1]), "+f"(d[2]), "+f"(d[3])
        : "r"(a[0]), "r"(a[1]), "r"(a[2]), "r"(a[3]), "r"(b[0]), "r"(b[1]));
}
__device__ __forceinline__ void ldm_x4(uint32_t* r, uint32_t addr) {
    asm volatile("ldmatrix.sync.aligned.m8n8.x4.shared.b16 {%0,%1,%2,%3}, [%4];"
                 : "=r"(r[0]), "=r"(r[1]), "=r"(r[2]), "=r"(r[3]) : "r"(addr));
}
__device__ __forceinline__ void ldm_x4_t(uint32_t* r, uint32_t addr) {
    asm volatile("ldmatrix.sync.aligned.m8n8.x4.trans.shared.b16 {%0,%1,%2,%3}, [%4];"
                 : "=r"(r[0]), "=r"(r[1]), "=r"(r[2]), "=r"(r[3]) : "r"(addr));
}

// ---------------- fp32 -> fp16 conversion (merged segments) ------------------
#define MAXSEG 10
struct CvtSegs {
    const float* src[MAXSEG];
    __half*      dst[MAXSEG];
    int          end8[MAXSEG];
    int          nseg;
};

__global__ void __launch_bounds__(256)
cvt_all_kernel(CvtSegs segs, int total8)
{
    int idx = blockIdx.x * 256 + threadIdx.x;
    if (idx >= total8) return;
    int s = 0;
#pragma unroll
    for (int i = 0; i < MAXSEG; i++)
        if (i < segs.nseg && idx >= segs.end8[i]) s = i + 1;
    const int off = idx - (s ? segs.end8[s - 1] : 0);

    const float4* s4 = (const float4*)(segs.src[s] + (size_t)off * 8);
    float4 a = s4[0], b = s4[1];
    __half2 h[4];
    h[0] = __floats2half2_rn(a.x, a.y);
    h[1] = __floats2half2_rn(a.z, a.w);
    h[2] = __floats2half2_rn(b.x, b.y);
    h[3] = __floats2half2_rn(b.z, b.w);
    *(uint4*)(segs.dst[s] + (size_t)off * 8) = *(uint4*)h;
}

// ---------------- fp16 tensor-core GEMM (3-stage pipeline) -------------------
// vmask: bit z set -> Ch is the flash V buffer [b,h,t,64]; voff = t offset.
struct GemmPtrs {
    const __half* A[7];
    const __half* W[7];
    float*        C[7];
    __half*       Ch[7];
    const float*  bias[7];
    int           voff[7];
};

#define HROW 144u                      // smem row stride in bytes (72 halves)
#define TILE16 (128u * HROW)           // 18432 B per operand tile
#define STAGE16 (2u * TILE16)          // 36864 B per stage
#define GEMM16_SMEM (3 * 36864)        // 110592 B (3 stages)

__global__ void __launch_bounds__(256)
gemm16_kernel(GemmPtrs ptrs, int M, int N, int Klen, int Kstride, int act,
              int vmask)
{
    extern __shared__ char smem[];
    const uint32_t sbase = (uint32_t)__cvta_generic_to_shared(smem);

    const __half* A    = ptrs.A[blockIdx.z];
    const __half* W    = ptrs.W[blockIdx.z];
    float*        C    = ptrs.C[blockIdx.z];
    __half*       Ch   = ptrs.Ch[blockIdx.z];
    const float*  bias = ptrs.bias[blockIdx.z];
    const bool    vfuse = (vmask >> blockIdx.z) & 1;
    const int     voff  = ptrs.voff[blockIdx.z];

    const int tid = threadIdx.x;
    const int lane = tid & 31, wrp = tid >> 5;
    const int wm = wrp & 1, wn = wrp >> 1;
    const int q = lane >> 2, r = lane & 3;
    const int m0 = blockIdx.y * 128;
    const int n0 = blockIdx.x * 128;

    float acc[4][4][4];
#pragma unroll
    for (int i = 0; i < 4; i++)
#pragma unroll
        for (int j = 0; j < 4; j++)
#pragma unroll
            for (int e = 0; e < 4; e++) acc[i][j][e] = 0.f;

    auto issue = [&](int t) {              // tile index; stage = t % 3
        const uint32_t so = sbase + (uint32_t)(t % 3) * STAGE16;
        const int k0 = t << 5;             // halves
#pragma unroll
        for (int i = 0; i < 2; i++) {
            int id = tid + i * 256;
            int row = id >> 2, c = id & 3;
            uint32_t d = (uint32_t)row * HROW + (uint32_t)c * 16u;
            cp_async16(so + d,          A + (size_t)(m0 + row) * Kstride + k0 + c * 8);
            cp_async16(so + TILE16 + d, W + (size_t)(n0 + row) * Kstride + k0 + c * 8);
        }
    };

    const int KT = Klen >> 5;
    issue(0);
    cp_commit();
    if (KT > 1) { issue(1); cp_commit(); }

    const int alr = lane & 15, alc = lane >> 4;
    const int bg = lane >> 3,  blr = lane & 7;

    for (int kt = 0; kt < KT; kt++) {
        if (kt == KT - 1) { cp_wait<0>(); } else { cp_wait<1>(); }
        __syncthreads();
        if (kt + 2 < KT) { issue(kt + 2); cp_commit(); }

        const uint32_t aBase = sbase + (uint32_t)(kt % 3) * STAGE16;
        const uint32_t bBase = aBase + TILE16;

#pragma unroll
        for (int ks = 0; ks < 2; ks++) {
            uint32_t afr[4][4];
#pragma unroll
            for (int mt = 0; mt < 4; mt++) {
                uint32_t addr = aBase +
                    (uint32_t)(wm * 64 + mt * 16 + alr) * HROW +
                    (uint32_t)(ks * 32 + alc * 16);
                ldm_x4(afr[mt], addr);
            }
            uint32_t bfr[4][2];
#pragma unroll
            for (int ntp = 0; ntp < 2; ntp++) {
                uint32_t addr = bBase +
                    (uint32_t)(wn * 32 + ntp * 16 + (bg >> 1) * 8 + blr) * HROW +
                    (uint32_t)(ks * 32 + (bg & 1) * 16);
                uint32_t tmp[4];
                ldm_x4(tmp, addr);
                bfr[ntp * 2 + 0][0] = tmp[0]; bfr[ntp * 2 + 0][1] = tmp[1];
                bfr[ntp * 2 + 1][0] = tmp[2]; bfr[ntp * 2 + 1][1] = tmp[3];
            }
#pragma unroll
            for (int mt = 0; mt < 4; mt++)
#pragma unroll
                for (int nt = 0; nt < 4; nt++)
                    mma_f16(acc[mt][nt], afr[mt], bfr[nt]);
        }
    }

#pragma unroll
    for (int mt = 0; mt < 4; mt++) {
        const int row0 = m0 + wm * 64 + mt * 16 + q;
#pragma unroll
        for (int nt = 0; nt < 4; nt++) {
            const int col = n0 + wn * 32 + nt * 8 + r * 2;
            float b0 = bias ? bias[col]     : 0.f;
            float b1 = bias ? bias[col + 1] : 0.f;
            float v0 = acc[mt][nt][0] + b0, v1 = acc[mt][nt][1] + b1;
            float v2 = acc[mt][nt][2] + b0, v3 = acc[mt][nt][3] + b1;
            if (act == 1) {
                v0 = fmaxf(v0, 0.f); v1 = fmaxf(v1, 0.f);
                v2 = fmaxf(v2, 0.f); v3 = fmaxf(v3, 0.f);
            }
            if (C) {
                *(float2*)(C + (size_t)row0 * N + col)       = make_float2(v0, v1);
                *(float2*)(C + (size_t)(row0 + 8) * N + col) = make_float2(v2, v3);
            }
            if (Ch) {
                if (vfuse) {
                    // row encodes (t_local, b); col encodes (h, d)
                    const int h = col >> 6, d = col & 63;
                    const int t0 = (row0 >> 1), b0r = row0 & 1;
                    const int t1 = ((row0 + 8) >> 1), b1r = (row0 + 8) & 1;
                    *(__half2*)(Ch + (((size_t)(b0r * HEADS + h) * TLEN + voff + t0) * HDIM + d))
                        = __floats2half2_rn(v0, v1);
                    *(__half2*)(Ch + (((size_t)(b1r * HEADS + h) * TLEN + voff + t1) * HDIM + d))
                        = __floats2half2_rn(v2, v3);
                } else {
                    *(__half2*)(Ch + (size_t)row0 * N + col)       = __floats2half2_rn(v0, v1);
                    *(__half2*)(Ch + (size_t)(row0 + 8) * N + col) = __floats2half2_rn(v2, v3);
                }
            }
        }
    }
}

// ---------------- prep (fp16 in): KK = ke+kr, bias = (u.ke+v.kr)/8 -----------
__global__ void __launch_bounds__(256)
prep_kernel(const __half* __restrict__ keh, const __half* __restrict__ krh,
            const float* __restrict__ ub, const float* __restrict__ vb,
            __half* __restrict__ kkh, float* __restrict__ biasO)
{
    const int row = blockIdx.x;          // = t*BATCH + b
    const int t = row / BATCH, b = row % BATCH;
    const int tid = threadIdx.x;
    const int h = tid >> 4, l16 = tid & 15, d0 = l16 * 4;

    const size_t src = (size_t)row * DMODEL + h * HDIM + d0;
    uint2 ke2 = *(const uint2*)(keh + src);
    uint2 kr2 = *(const uint2*)(krh + src);

    float2 ke01 = __half22float2(*(__half2*)&ke2.x);
    float2 ke23 = __half22float2(*(__half2*)&ke2.y);
    float2 kr01 = __half22float2(*(__half2*)&kr2.x);
    float2 kr23 = __half22float2(*(__half2*)&kr2.y);

    const size_t dst = ((size_t)(b * HEADS + h) * TLEN + t) * HDIM + d0;
    __half2 kk01 = __floats2half2_rn(ke01.x + kr01.x, ke01.y + kr01.y);
    __half2 kk23 = __floats2half2_rn(ke23.x + kr23.x, ke23.y + kr23.y);
    *(uint2*)(kkh + dst) = make_uint2(*(uint32_t*)&kk01, *(uint32_t*)&kk23);

    float4 u4 = *(const float4*)(ub + h * HDIM + d0);
    float4 w4 = *(const float4*)(vb + h * HDIM + d0);
    float bsum = u4.x * ke01.x + u4.y * ke01.y + u4.z * ke23.x + u4.w * ke23.y
               + w4.x * kr01.x + w4.y * kr01.y + w4.z * kr23.x + w4.w * kr23.y;
#pragma unroll
    for (int off = 8; off; off >>= 1)
        bsum += __shfl_xor_sync(0xffffffffu, bsum, off, 16);
    if (l16 == 0)
        biasO[(size_t)(b * HEADS + h) * TLEN + t] = bsum * 0.125f;  // pre-scaled
}

// ---------------- fp16 flash attention (split-KV x4, double-buffered) --------
// grid.x = 32: encodes (qb heavy-first, quarter). Each CTA handles ~1/4 of the
// key range of a 128-query block; writes UNNORMALIZED O (fp32) + (m, l).
#define QH_OFF 0u
#define PH_OFF 18432u
#define KK_OFF 36864u          // + buf*9216
#define V_OFF  55296u          // + buf*9216
#define BI_OFF 73728u          // + buf*256
#define KVBUF  9216u
#define FLASH_SMEM 74240
#define ML_HALF (ROWS_X * HEADS * 2)
#define PO_HALF ((size_t)ROWS_X * DMODEL)

__global__ void __launch_bounds__(256, 2)
flash16_kernel(const __half* __restrict__ qh,
               const __half* __restrict__ kkh,
               const __half* __restrict__ vhg,
               const float* __restrict__ biasG,
               float* __restrict__ poAll, float* __restrict__ mlAll)
{
    extern __shared__ char fsm[];
    const uint32_t sbase = (uint32_t)__cvta_generic_to_shared(fsm);
    __half* PhH = (__half*)(fsm + PH_OFF);

    const int xid = blockIdx.x;
    const int qb = 7 - (xid >> 2);       // heavy q-blocks first
    const int hf = xid & 3;
    const int h = blockIdx.y, b = blockIdx.z;
    const int tid = threadIdx.x;
    const int lane = tid & 31, wid = tid >> 5;
    const int q = lane >> 2, r = lane & 3;
    const int mw = wid * 16;
    const int alr = lane & 15, alc = lane >> 4;
    const int bg = lane >> 3,  blr = lane & 7;

    const int ntAll = 18 + 2 * qb;
    const int base = ntAll >> 2, rem = ntAll & 3;
    const int tstart = hf * base + min(hf, rem);
    const int tend   = tstart + base + (hf < rem ? 1 : 0);
    float* po  = poAll + (size_t)hf * PO_HALF;
    float* mlp = mlAll + (size_t)hf * ML_HALF;

    const size_t  bh   = (size_t)(b * HEADS + h) * TLEN;
    const __half* kkbh = kkh + bh * HDIM;
    const __half* vbh  = vhg + bh * HDIM;
    const float*  bibh = biasG + bh;

    auto issueQ = [&]() {
#pragma unroll
        for (int it = 0; it < 4; it++) {
            int idx = tid + it * 256;
            int row = idx >> 3, c = idx & 7;
            cp_async16(sbase + QH_OFF + (uint32_t)row * HROW + (uint32_t)c * 16u,
                       qh + ((size_t)((qb * 128 + row) * BATCH + b)) * DMODEL
                          + h * HDIM + c * 8);
        }
    };
    auto issueKV = [&](int t0, int buf) {
        const uint32_t kkB = sbase + KK_OFF + (uint32_t)buf * KVBUF;
        const uint32_t vB  = sbase + V_OFF  + (uint32_t)buf * KVBUF;
#pragma unroll
        for (int it = 0; it < 2; it++) {
            int idx = tid + it * 256;
            int row = idx >> 3, c = idx & 7;
            const uint32_t d = (uint32_t)row * HROW + (uint32_t)c * 16u;
            cp_async16(kkB + d, kkbh + (size_t)(t0 + row) * HDIM + c * 8);
            cp_async16(vB  + d, vbh  + (size_t)(t0 + row) * HDIM + c * 8);
        }
        if (tid < 16)
            cp_async16(sbase + BI_OFF + (uint32_t)(buf * 256 + tid * 16),
                       bibh + t0 + tid * 4);
    };

    issueQ();
    issueKV(tstart * 64, tstart & 1);
    cp_commit();

    float m0 = -1e30f, m1 = -1e30f, l0 = 0.f, l1 = 0.f;
    float O[8][4];
#pragma unroll
    for (int nt = 0; nt < 8; nt++)
#pragma unroll
        for (int e = 0; e < 4; e++) O[nt][e] = 0.f;

    const int srow0 = qb * 128 + mw + q;

    for (int tt = tstart; tt < tend; tt++) {
        const int t0 = tt * 64;
        const int buf = tt & 1;
        const bool more = (tt + 1 < tend);

        cp_wait<0>();
        __syncthreads();

        if (more) { issueKV(t0 + 64, buf ^ 1); cp_commit(); }

        const uint32_t kkB = sbase + KK_OFF + (uint32_t)buf * KVBUF;
        const uint32_t vB  = sbase + V_OFF  + (uint32_t)buf * KVBUF;
        const float* bS = (const float*)(fsm + BI_OFF + buf * 256);

        // ---- S = Q @ KK^T  (fp16 mma) --------------------------------------
        float sc[8][4];
#pragma unroll
        for (int nt = 0; nt < 8; nt++)
#pragma unroll
            for (int e = 0; e < 4; e++) sc[nt][e] = 0.f;

#pragma unroll
        for (int ks = 0; ks < 4; ks++) {
            uint32_t afr[4];
            ldm_x4(afr, sbase + QH_OFF + (uint32_t)(mw + alr) * HROW
                         + (uint32_t)(ks * 32 + alc * 16));
#pragma unroll
            for (int tb = 0; tb < 4; tb++) {
                uint32_t tmp[4];
                ldm_x4(tmp, kkB
                             + (uint32_t)(tb * 16 + (bg >> 1) * 8 + blr) * HROW
                             + (uint32_t)(ks * 32 + (bg & 1) * 16));
                mma_f16(sc[tb * 2],     afr, tmp);
                mma_f16(sc[tb * 2 + 1], afr, tmp + 2);
            }
        }

        // ---- bias(pre-scaled) + causal mask + online softmax ----------------
        const bool mt_ = (tt >= 16 + 2 * qb);
        float tmax0 = -1e30f, tmax1 = -1e30f;
#pragma unroll
        for (int nt = 0; nt < 8; nt++) {
            const int colb = nt * 8 + 2 * r;
            const float bi0 = bS[colb], bi1 = bS[colb + 1];
            float v0 = fmaf(sc[nt][0], 0.125f, bi0);
            float v1 = fmaf(sc[nt][1], 0.125f, bi1);
            float v2 = fmaf(sc[nt][2], 0.125f, bi0);
            float v3 = fmaf(sc[nt][3], 0.125f, bi1);
            if (mt_) {
                const int tc = t0 + colb;
                if (tc     > S_LEN + srow0)     v0 = -1e30f;
                if (tc + 1 > S_LEN + srow0)     v1 = -1e30f;
                if (tc     > S_LEN + srow0 + 8) v2 = -1e30f;
                if (tc + 1 > S_LEN + srow0 + 8) v3 = -1e30f;
            }
            sc[nt][0] = v0; sc[nt][1] = v1; sc[nt][2] = v2; sc[nt][3] = v3;
            tmax0 = fmaxf(tmax0, fmaxf(v0, v1));
            tmax1 = fmaxf(tmax1, fmaxf(v2, v3));
        }
        tmax0 = fmaxf(tmax0, __shfl_xor_sync(0xffffffffu, tmax0, 1));
        tmax0 = fmaxf(tmax0, __shfl_xor_sync(0xffffffffu, tmax0, 2));
        tmax1 = fmaxf(tmax1, __shfl_xor_sync(0xffffffffu, tmax1, 1));
        tmax1 = fmaxf(tmax1, __shfl_xor_sync(0xffffffffu, tmax1, 2));

        const float mnew0 = fmaxf(m0, tmax0);
        const float mnew1 = fmaxf(m1, tmax1);
        const float c0 = __expf(m0 - mnew0);
        const float c1 = __expf(m1 - mnew1);
        m0 = mnew0; m1 = mnew1;
        l0 *= c0; l1 *= c1;

        const bool doscale = !__all_sync(0xffffffffu, (c0 == 1.f) && (c1 == 1.f));

        float ps0 = 0.f, ps1 = 0.f;
#pragma unroll
        for (int nt = 0; nt < 8; nt++) {
            float p0 = __expf(sc[nt][0] - mnew0);
            float p1 = __expf(sc[nt][1] - mnew0);
            float p2 = __expf(sc[nt][2] - mnew1);
            float p3 = __expf(sc[nt][3] - mnew1);
            ps0 += p0 + p1; ps1 += p2 + p3;
            if (doscale) {
                O[nt][0] *= c0; O[nt][1] *= c0;
                O[nt][2] *= c1; O[nt][3] *= c1;
            }
            const int colp = nt * 8 + 2 * r;
            *(__half2*)&PhH[(size_t)(mw + q) * 72 + colp]     = __floats2half2_rn(p0, p1);
            *(__half2*)&PhH[(size_t)(mw + q + 8) * 72 + colp] = __floats2half2_rn(p2, p3);
        }
        l0 += ps0; l1 += ps1;
        __syncwarp();          // P is warp-private

        // ---- O += P @ V ------------------------------------------------------
#pragma unroll
        for (int ks = 0; ks < 4; ks++) {
            uint32_t afr[4];
            ldm_x4(afr, sbase + PH_OFF + (uint32_t)(mw + alr) * HROW
                         + (uint32_t)(ks * 32 + alc * 16));
#pragma unroll
            for (int dp = 0; dp < 4; dp++) {
                uint32_t tmp[4];
                ldm_x4_t(tmp, vB
                               + (uint32_t)(ks * 16 + (bg & 1) * 8 + blr) * HROW
                               + (uint32_t)(dp * 32 + (bg >> 1) * 16));
                mma_f16(O[dp * 2],     afr, tmp);
                mma_f16(O[dp * 2 + 1], afr, tmp + 2);
            }
        }
        // next iteration's top syncthreads covers buf reuse
    }

    // ---- finalize: reduce l over quad; store UNNORMALIZED O (fp32) + (m,l) --
    l0 += __shfl_xor_sync(0xffffffffu, l0, 1);
    l0 += __shfl_xor_sync(0xffffffffu, l0, 2);
    l1 += __shfl_xor_sync(0xffffffffu, l1, 1);
    l1 += __shfl_xor_sync(0xffffffffu, l1, 2);

    const int row0 = qb * 128 + mw + q;
#pragma unroll
    for (int nt = 0; nt < 8; nt++) {
        const int col = nt * 8 + 2 * r;
        *(float2*)(po + ((size_t)(row0 * BATCH + b)) * DMODEL + h * HDIM + col)
            = make_float2(O[nt][0], O[nt][1]);
        *(float2*)(po + ((size_t)((row0 + 8) * BATCH + b)) * DMODEL + h * HDIM + col)
            = make_float2(O[nt][2], O[nt][3]);
    }
    if (r == 0) {
        const size_t i0 = (((size_t)(row0 * BATCH + b)) * HEADS + h) * 2;
        mlp[i0]     = m0;
        mlp[i0 + 1] = l0;
        const size_t i1 = (((size_t)((row0 + 8) * BATCH + b)) * HEADS + h) * 2;
        mlp[i1]     = m1;
        mlp[i1 + 1] = l1;
    }
}

// ---------------- combine split-KV partials (4-way) -> fp16 av ---------------
__global__ void __launch_bounds__(256)
combine_kernel(const float* __restrict__ poAll, const float* __restrict__ mlAll,
               __half* __restrict__ out)
{
    const int row = blockIdx.x;          // = s*BATCH + b
    const int tid = threadIdx.x;
    const int d0 = tid * 4;
    const int h = d0 >> 6;

    float mv[NSPLIT], lv[NSPLIT];
    float M = -1e30f;
#pragma unroll
    for (int i = 0; i < NSPLIT; i++) {
        const float* mlp = mlAll + (size_t)i * ML_HALF + ((size_t)row * HEADS + h) * 2;
        mv[i] = mlp[0];
        lv[i] = mlp[1];
        M = fmaxf(M, mv[i]);
    }
    float w[NSPLIT], lsum = 0.f;
#pragma unroll
    for (int i = 0; i < NSPLIT; i++) {
        w[i] = __expf(mv[i] - M);
        lsum += lv[i] * w[i];
    }
    const float inv = 1.f / lsum;
#pragma unroll
    for (int i = 0; i < NSPLIT; i++) w[i] *= inv;

    float o0 = 0.f, o1 = 0.f, o2 = 0.f, o3 = 0.f;
#pragma unroll
    for (int i = 0; i < NSPLIT; i++) {
        const float4 a = *(const float4*)(poAll + (size_t)i * PO_HALF
                                          + (size_t)row * DMODEL + d0);
        o0 += a.x * w[i]; o1 += a.y * w[i];
        o2 += a.z * w[i]; o3 += a.w * w[i];
    }
    __half2 h01 = __floats2half2_rn(o0, o1);
    __half2 h23 = __floats2half2_rn(o2, o3);
    *(uint2*)(out + (size_t)row * DMODEL + d0)
        = make_uint2(*(uint32_t*)&h01, *(uint32_t*)&h23);
}

// ---------------- LayerNorm(a0 [+ a1] + res) * g + b -------------------------
__global__ void __launch_bounds__(256)
ln_kernel(const float* __restrict__ a0, const float* __restrict__ a1,
          const float* __restrict__ res,
          const float* __restrict__ g, const float* __restrict__ bta,
          float* __restrict__ out, __half* __restrict__ out_h)
{
    const int row = blockIdx.x;
    const int tid = threadIdx.x;
    const int lane = tid & 31, wrp = tid >> 5;
    __shared__ float red[8];
    __shared__ float bc;

    float vals[4];
    float s = 0.f;
    const float* ar = a0 + (size_t)row * DMODEL;
    const float* br = a1 ? a1 + (size_t)row * DMODEL : nullptr;
    const float* rr = res + (size_t)row * DMODEL;
#pragma unroll
    for (int i = 0; i < 4; i++) {
        int d = tid + i * 256;
        float v = ar[d] + rr[d];
        if (br) v += br[d];
        vals[i] = v;
        s += v;
    }
#pragma unroll
    for (int off = 16; off; off >>= 1) s += __shfl_xor_sync(0xffffffffu, s, off);
    if (lane == 0) red[wrp] = s;
    __syncthreads();
    if (tid == 0) {
        float t = 0.f;
#pragma unroll
        for (int w = 0; w < 8; w++) t += red[w];
        bc = t * (1.f / DMODEL);
    }
    __syncthreads();
    const float mu = bc;

    float vs = 0.f;
#pragma unroll
    for (int i = 0; i < 4; i++) {
        float dd = vals[i] - mu;
        vs += dd * dd;
    }
#pragma unroll
    for (int off = 16; off; off >>= 1) vs += __shfl_xor_sync(0xffffffffu, vs, off);
    __syncthreads();
    if (lane == 0) red[wrp] = vs;
    __syncthreads();
    if (tid == 0) {
        float t = 0.f;
#pragma unroll
        for (int w = 0; w < 8; w++) t += red[w];
        bc = rsqrtf(t * (1.f / DMODEL) + 1e-5f);
    }
    __syncthreads();
    const float rstd = bc;

    float* orow = out + (size_t)row * DMODEL;
    __half* hrow = out_h ? out_h + (size_t)row * DMODEL : nullptr;
#pragma unroll
    for (int i = 0; i < 4; i++) {
        int d = tid + i * 256;
        float vv = (vals[i] - mu) * rstd * g[d] + bta[d];
        orow[d] = vv;
        if (hrow) hrow[d] = __float2half(vv);
    }
}

// ---------------- launcher ---------------------------------------------------
extern "C" void kernel_launch(void* const* d_in, const int* in_sizes, int n_in,
                              void* d_out, int out_size)
{
    const float* x      = (const float*)d_in[0];
    const float* p      = (const float*)d_in[1];
    /* mask d_in[2] is analytic: unused */
    const float* memory = (const float*)d_in[3];
    const float* u_bias = (const float*)d_in[4];
    const float* v_bias = (const float*)d_in[5];
    const float* wq  = (const float*)d_in[6];
    const float* wke = (const float*)d_in[7];
    const float* wkr = (const float*)d_in[8];
    const float* wv  = (const float*)d_in[9];
    const float* wc  = (const float*)d_in[10];
    const float* w1  = (const float*)d_in[11];
    const float* w1b = (const float*)d_in[12];
    const float* w2  = (const float*)d_in[13];
    const float* w2b = (const float*)d_in[14];
    const float* ln1g = (const float*)d_in[15];
    const float* ln1b = (const float*)d_in[16];
    const float* ln2g = (const float*)d_in[17];
    const float* ln2b = (const float*)d_in[18];
    float* out = (float*)d_out;

    float *tbuf, *t2buf, *ubuf, *bias2, *poAll, *mlAll;
    __half *xh, *memh, *ph, *wqh, *wkeh, *wkrh, *wvh, *wch, *w1h, *w2h;
    __half *qh, *keh, *krh, *avh, *uh, *h1h, *kkh, *vh;
    cudaGetSymbolAddress((void**)&tbuf,  g_t);
    cudaGetSymbolAddress((void**)&t2buf, g_t2);
    cudaGetSymbolAddress((void**)&ubuf,  g_u);
    cudaGetSymbolAddress((void**)&poAll, g_po);
    cudaGetSymbolAddress((void**)&mlAll, g_ml);
    cudaGetSymbolAddress((void**)&xh,    g_xh);
    cudaGetSymbolAddress((void**)&memh,  g_memh);
    cudaGetSymbolAddress((void**)&ph,    g_ph);
    cudaGetSymbolAddress((void**)&wqh,   g_wqh);
    cudaGetSymbolAddress((void**)&wkeh,  g_wkeh);
    cudaGetSymbolAddress((void**)&wkrh,  g_wkrh);
    cudaGetSymbolAddress((void**)&wvh,   g_wvh);
    cudaGetSymbolAddress((void**)&wch,   g_wch);
    cudaGetSymbolAddress((void**)&w1h,   g_w1h);
    cudaGetSymbolAddress((void**)&w2h,   g_w2h);
    cudaGetSymbolAddress((void**)&qh,    g_qh);
    cudaGetSymbolAddress((void**)&keh,   g_keh);
    cudaGetSymbolAddress((void**)&krh,   g_krh);
    cudaGetSymbolAddress((void**)&avh,   g_avh);
    cudaGetSymbolAddress((void**)&uh,    g_uh);
    cudaGetSymbolAddress((void**)&h1h,   g_h1h);
    cudaGetSymbolAddress((void**)&kkh,   g_kkh);
    cudaGetSymbolAddress((void**)&vh,    g_vh);
    cudaGetSymbolAddress((void**)&bias2, g_bias);

    cudaFuncSetAttribute(gemm16_kernel,
                         cudaFuncAttributeMaxDynamicSharedMemorySize, GEMM16_SMEM);
    cudaFuncSetAttribute(flash16_kernel,
                         cudaFuncAttributeMaxDynamicSharedMemorySize, FLASH_SMEM);

    const dim3 blk(256);
    const size_t half = (size_t)ROWS_X * DMODEL;

    // ---- convert inputs + weights to fp16 (one merged launch) ---------------
    {
        CvtSegs cs{};
        int acc = 0, i = 0;
        auto add = [&](const float* s, __half* d, int n8) {
            cs.src[i] = s; cs.dst[i] = d; acc += n8; cs.end8[i] = acc; i++;
        };
        add(x,      xh,   ROWS_X * DMODEL / 8);
        add(memory, memh, ROWS_X * DMODEL / 8);
        add(p,      ph,   ROWS_T * DMODEL / 8);
        add(wq,  wqh,  DMODEL * DMODEL / 8);
        add(wke, wkeh, DMODEL * DMODEL / 8);
        add(wkr, wkrh, DMODEL * DMODEL / 8);
        add(wv,  wvh,  DMODEL * DMODEL / 8);
        add(wc,  wch,  DMODEL * DMODEL / 8);
        add(w1,  w1h,  FFDIM * DMODEL / 8);
        add(w2,  w2h,  FFDIM * DMODEL / 8);
        cs.nseg = i;
        cvt_all_kernel<<<(acc + 255) / 256, blk>>>(cs, acc);
    }

    // ---- all 6 projections in ONE launch (z = 0..6), fp16 in AND out --------
    // V slices (z=2, z=4) write DIRECTLY into the flash V layout [b,h,t,64].
    {
        GemmPtrs gp{};
        gp.A[0] = xh;   gp.W[0] = wqh;  gp.Ch[0] = qh;
        gp.A[1] = xh;   gp.W[1] = wkeh; gp.Ch[1] = keh + half;
        gp.A[2] = xh;   gp.W[2] = wvh;  gp.Ch[2] = vh;  gp.voff[2] = S_LEN;
        gp.A[3] = memh; gp.W[3] = wkeh; gp.Ch[3] = keh;
        gp.A[4] = memh; gp.W[4] = wvh;  gp.Ch[4] = vh;  gp.voff[4] = 0;
        gp.A[5] = ph;        gp.W[5] = wkrh; gp.Ch[5] = krh;
        gp.A[6] = ph + half; gp.W[6] = wkrh; gp.Ch[6] = krh + half;
        gemm16_kernel<<<dim3(8, 16, 7), blk, GEMM16_SMEM>>>(
            gp, ROWS_X, DMODEL, DMODEL, DMODEL, 0, (1 << 2) | (1 << 4));
    }

    // prep: fuse KK (fp16), bias (fp32, pre-scaled)
    prep_kernel<<<ROWS_T, blk>>>(keh, krh, u_bias, v_bias, kkh, bias2);

    // split-KV x4 fp16 flash attention + combine
    flash16_kernel<<<dim3(32, HEADS, BATCH), blk, FLASH_SMEM>>>(
        qh, kkh, vh, bias2, poAll, mlAll);
    combine_kernel<<<ROWS_X, blk>>>(poAll, mlAll, avh);

    // output proj (split-K=2) + LN1 (fused add; emits uh fp16)
    {
        GemmPtrs gp{};
        gp.A[0] = avh;       gp.W[0] = wch;       gp.C[0] = tbuf;
        gp.A[1] = avh + 512; gp.W[1] = wch + 512; gp.C[1] = t2buf;
        gemm16_kernel<<<dim3(8, 16, 2), blk, GEMM16_SMEM>>>(
            gp, ROWS_X, DMODEL, 512, DMODEL, 0, 0);
    }
    ln_kernel<<<ROWS_X, blk>>>(tbuf, t2buf, x, ln1g, ln1b, ubuf, uh);

    // FFN: w1 (relu, fp16 out), w2 (split-K=2) + LN2 (fused add)
    {
        GemmPtrs gp{};
        gp.A[0] = uh; gp.W[0] = w1h; gp.Ch[0] = h1h; gp.bias[0] = w1b;
        gemm16_kernel<<<dim3(32, 16, 1), blk, GEMM16_SMEM>>>(
            gp, ROWS_X, FFDIM, DMODEL, DMODEL, 1, 0);
    }
    {
        GemmPtrs gp{};
        gp.A[0] = h1h;        gp.W[0] = w2h;        gp.C[0] = tbuf;  gp.bias[0] = w2b;
        gp.A[1] = h1h + 2048; gp.W[1] = w2h + 2048; gp.C[1] = t2buf;
        gemm16_kernel<<<dim3(8, 16, 2), blk, GEMM16_SMEM>>>(
            gp, ROWS_X, DMODEL, 2048, FFDIM, 0, 0);
    }
    ln_kernel<<<ROWS_X, blk>>>(tbuf, t2buf, ubuf, ln2g, ln2b, out, nullptr);
}

// round 16
// speedup vs baseline: 2.2149x; 1.0631x over previous
#include <cuda_runtime.h>
#include <cuda_fp16.h>
#include <math.h>
#include <stdint.h>

// Problem constants
#define S_LEN 1024
#define BATCH 2
#define DMODEL 1024
#define HEADS 16
#define HDIM 64
#define TLEN 2048
#define FFDIM 4096
#define ROWS_X (S_LEN * BATCH)     // 2048
#define ROWS_T (TLEN * BATCH)      // 4096
#define NSPLIT 4

// ---------------- scratch buffers (device globals) ---------------------------
__device__ float g_t [ROWS_X * DMODEL];
__device__ float g_t2[ROWS_X * DMODEL];
__device__ float g_u [ROWS_X * DMODEL];
// split-KV flash partials
__device__ float g_po [NSPLIT * ROWS_X * DMODEL];
__device__ float g_ml [NSPLIT * ROWS_X * HEADS * 2];
// fp16 tensors
__device__ __half g_xh  [ROWS_X * DMODEL];
__device__ __half g_memh[ROWS_X * DMODEL];
__device__ __half g_ph  [ROWS_T * DMODEL];
__device__ __half g_wqh [DMODEL * DMODEL];
__device__ __half g_wkeh[DMODEL * DMODEL];
__device__ __half g_wkrh[DMODEL * DMODEL];
__device__ __half g_wvh [DMODEL * DMODEL];
__device__ __half g_wch [DMODEL * DMODEL];
__device__ __half g_w1h [FFDIM * DMODEL];
__device__ __half g_w2h [DMODEL * FFDIM];
__device__ __half g_qh  [ROWS_X * DMODEL];
__device__ __half g_keh [ROWS_T * DMODEL];
__device__ __half g_krh [ROWS_T * DMODEL];
__device__ __half g_avh [ROWS_X * DMODEL];
__device__ __half g_uh  [ROWS_X * DMODEL];
__device__ __half g_h1h [ROWS_X * FFDIM];
// flash-prep outputs (fp16 KK; V written directly by projection; fp32 bias/8)
__device__ __half g_kkh [BATCH * HEADS * TLEN * HDIM];
__device__ __half g_vh  [BATCH * HEADS * TLEN * HDIM];
__device__ float  g_bias[BATCH * HEADS * TLEN];

// ---------------- common PTX helpers ----------------------------------------
__device__ __forceinline__ void cp_async16(uint32_t saddr, const void* gptr) {
    asm volatile("cp.async.cg.shared.global [%0], [%1], 16;\n"
                 :: "r"(saddr), "l"(gptr));
}
__device__ __forceinline__ void cp_commit() {
    asm volatile("cp.async.commit_group;\n");
}
template <int N>
__device__ __forceinline__ void cp_wait() {
    asm volatile("cp.async.wait_group %0;\n" :: "n"(N));
}
__device__ __forceinline__ void mma_f16(float* d, const uint32_t* a, const uint32_t* b) {
    asm volatile(
        "mma.sync.aligned.m16n8k16.row.col.f32.f16.f16.f32 "
        "{%0,%1,%2,%3}, {%4,%5,%6,%7}, {%8,%9}, {%0,%1,%2,%3};\n"
        : "+f"(d[0]), "+f"(d[1]), "+f"(d[2]), "+f"(d[3])
        : "r"(a[0]), "r"(a[1]), "r"(a[2]), "r"(a[3]), "r"(b[0]), "r"(b[1]));
}
__device__ __forceinline__ void ldm_x4(uint32_t* r, uint32_t addr) {
    asm volatile("ldmatrix.sync.aligned.m8n8.x4.shared.b16 {%0,%1,%2,%3}, [%4];"
                 : "=r"(r[0]), "=r"(r[1]), "=r"(r[2]), "=r"(r[3]) : "r"(addr));
}
__device__ __forceinline__ void ldm_x4_t(uint32_t* r, uint32_t addr) {
    asm volatile("ldmatrix.sync.aligned.m8n8.x4.trans.shared.b16 {%0,%1,%2,%3}, [%4];"
                 : "=r"(r[0]), "=r"(r[1]), "=r"(r[2]), "=r"(r[3]) : "r"(addr));
}

// ---------------- fp32 -> fp16 conversion (merged segments) ------------------
#define MAXSEG 10
struct CvtSegs {
    const float* src[MAXSEG];
    __half*      dst[MAXSEG];
    int          end8[MAXSEG];
    int          nseg;
};

__global__ void __launch_bounds__(256)
cvt_all_kernel(CvtSegs segs, int total8)
{
    int idx = blockIdx.x * 256 + threadIdx.x;
    if (idx >= total8) return;
    int s = 0;
#pragma unroll
    for (int i = 0; i < MAXSEG; i++)
        if (i < segs.nseg && idx >= segs.end8[i]) s = i + 1;
    const int off = idx - (s ? segs.end8[s - 1] : 0);

    const float4* s4 = (const float4*)(segs.src[s] + (size_t)off * 8);
    float4 a = s4[0], b = s4[1];
    __half2 h[4];
    h[0] = __floats2half2_rn(a.x, a.y);
    h[1] = __floats2half2_rn(a.z, a.w);
    h[2] = __floats2half2_rn(b.x, b.y);
    h[3] = __floats2half2_rn(b.z, b.w);
    *(uint4*)(segs.dst[s] + (size_t)off * 8) = *(uint4*)h;
}

// ---------------- fp16 tensor-core GEMM (BK=64, 3-stage) ---------------------
// vmask: bit z set -> Ch is the flash V buffer [b,h,t,64]; voff = t offset.
struct GemmPtrs {
    const __half* A[7];
    const __half* W[7];
    float*        C[7];
    __half*       Ch[7];
    const float*  bias[7];
    int           voff[7];
};

#define HROW 144u                      // smem row stride in bytes (64h data+pad)
#define TILE16 (128u * HROW)           // 18432 B per operand tile (K=64)
#define STAGE16 (2u * TILE16)          // 36864 B per stage
#define GEMM16_SMEM (3 * 36864)        // 110592 B (3 stages)

__global__ void __launch_bounds__(256)
gemm16_kernel(GemmPtrs ptrs, int M, int N, int Klen, int Kstride, int act,
              int vmask)
{
    extern __shared__ char smem[];
    const uint32_t sbase = (uint32_t)__cvta_generic_to_shared(smem);

    const __half* A    = ptrs.A[blockIdx.z];
    const __half* W    = ptrs.W[blockIdx.z];
    float*        C    = ptrs.C[blockIdx.z];
    __half*       Ch   = ptrs.Ch[blockIdx.z];
    const float*  bias = ptrs.bias[blockIdx.z];
    const bool    vfuse = (vmask >> blockIdx.z) & 1;
    const int     voff  = ptrs.voff[blockIdx.z];

    const int tid = threadIdx.x;
    const int lane = tid & 31, wrp = tid >> 5;
    const int wm = wrp & 1, wn = wrp >> 1;
    const int q = lane >> 2, r = lane & 3;
    const int m0 = blockIdx.y * 128;
    const int n0 = blockIdx.x * 128;

    float acc[4][4][4];
#pragma unroll
    for (int i = 0; i < 4; i++)
#pragma unroll
        for (int j = 0; j < 4; j++)
#pragma unroll
            for (int e = 0; e < 4; e++) acc[i][j][e] = 0.f;

    auto issue = [&](int t) {              // K-chunk index (64 halves); stage t%3
        const uint32_t so = sbase + (uint32_t)(t % 3) * STAGE16;
        const int k0 = t << 6;             // halves
#pragma unroll
        for (int i = 0; i < 4; i++) {
            int id = tid + i * 256;        // 0..1023
            int row = id >> 3, c = id & 7; // 8 x 16B chunks per row
            uint32_t d = (uint32_t)row * HROW + (uint32_t)c * 16u;
            cp_async16(so + d,          A + (size_t)(m0 + row) * Kstride + k0 + c * 8);
            cp_async16(so + TILE16 + d, W + (size_t)(n0 + row) * Kstride + k0 + c * 8);
        }
    };

    const int KT = Klen >> 6;
    issue(0);
    cp_commit();
    if (KT > 1) { issue(1); cp_commit(); }

    const int alr = lane & 15, alc = lane >> 4;
    const int bg = lane >> 3,  blr = lane & 7;

    for (int kt = 0; kt < KT; kt++) {
        if (kt == KT - 1) { cp_wait<0>(); } else { cp_wait<1>(); }
        __syncthreads();
        if (kt + 2 < KT) { issue(kt + 2); cp_commit(); }

        const uint32_t aBase = sbase + (uint32_t)(kt % 3) * STAGE16;
        const uint32_t bBase = aBase + TILE16;

#pragma unroll
        for (int ks = 0; ks < 4; ks++) {
            uint32_t afr[4][4];
#pragma unroll
            for (int mt = 0; mt < 4; mt++) {
                uint32_t addr = aBase +
                    (uint32_t)(wm * 64 + mt * 16 + alr) * HROW +
                    (uint32_t)(ks * 32 + alc * 16);
                ldm_x4(afr[mt], addr);
            }
            uint32_t bfr[4][2];
#pragma unroll
            for (int ntp = 0; ntp < 2; ntp++) {
                uint32_t addr = bBase +
                    (uint32_t)(wn * 32 + ntp * 16 + (bg >> 1) * 8 + blr) * HROW +
                    (uint32_t)(ks * 32 + (bg & 1) * 16);
                uint32_t tmp[4];
                ldm_x4(tmp, addr);
                bfr[ntp * 2 + 0][0] = tmp[0]; bfr[ntp * 2 + 0][1] = tmp[1];
                bfr[ntp * 2 + 1][0] = tmp[2]; bfr[ntp * 2 + 1][1] = tmp[3];
            }
#pragma unroll
            for (int mt = 0; mt < 4; mt++)
#pragma unroll
                for (int nt = 0; nt < 4; nt++)
                    mma_f16(acc[mt][nt], afr[mt], bfr[nt]);
        }
    }

#pragma unroll
    for (int mt = 0; mt < 4; mt++) {
        const int row0 = m0 + wm * 64 + mt * 16 + q;
#pragma unroll
        for (int nt = 0; nt < 4; nt++) {
            const int col = n0 + wn * 32 + nt * 8 + r * 2;
            float b0 = bias ? bias[col]     : 0.f;
            float b1 = bias ? bias[col + 1] : 0.f;
            float v0 = acc[mt][nt][0] + b0, v1 = acc[mt][nt][1] + b1;
            float v2 = acc[mt][nt][2] + b0, v3 = acc[mt][nt][3] + b1;
            if (act == 1) {
                v0 = fmaxf(v0, 0.f); v1 = fmaxf(v1, 0.f);
                v2 = fmaxf(v2, 0.f); v3 = fmaxf(v3, 0.f);
            }
            if (C) {
                *(float2*)(C + (size_t)row0 * N + col)       = make_float2(v0, v1);
                *(float2*)(C + (size_t)(row0 + 8) * N + col) = make_float2(v2, v3);
            }
            if (Ch) {
                if (vfuse) {
                    const int h = col >> 6, d = col & 63;
                    const int t0 = (row0 >> 1), b0r = row0 & 1;
                    const int t1 = ((row0 + 8) >> 1), b1r = (row0 + 8) & 1;
                    *(__half2*)(Ch + (((size_t)(b0r * HEADS + h) * TLEN + voff + t0) * HDIM + d))
                        = __floats2half2_rn(v0, v1);
                    *(__half2*)(Ch + (((size_t)(b1r * HEADS + h) * TLEN + voff + t1) * HDIM + d))
                        = __floats2half2_rn(v2, v3);
                } else {
                    *(__half2*)(Ch + (size_t)row0 * N + col)       = __floats2half2_rn(v0, v1);
                    *(__half2*)(Ch + (size_t)(row0 + 8) * N + col) = __floats2half2_rn(v2, v3);
                }
            }
        }
    }
}

// ---------------- prep (fp16 in): KK = ke+kr, bias = (u.ke+v.kr)/8 -----------
__global__ void __launch_bounds__(256)
prep_kernel(const __half* __restrict__ keh, const __half* __restrict__ krh,
            const float* __restrict__ ub, const float* __restrict__ vb,
            __half* __restrict__ kkh, float* __restrict__ biasO)
{
    const int row = blockIdx.x;          // = t*BATCH + b
    const int t = row / BATCH, b = row % BATCH;
    const int tid = threadIdx.x;
    const int h = tid >> 4, l16 = tid & 15, d0 = l16 * 4;

    const size_t src = (size_t)row * DMODEL + h * HDIM + d0;
    uint2 ke2 = *(const uint2*)(keh + src);
    uint2 kr2 = *(const uint2*)(krh + src);

    float2 ke01 = __half22float2(*(__half2*)&ke2.x);
    float2 ke23 = __half22float2(*(__half2*)&ke2.y);
    float2 kr01 = __half22float2(*(__half2*)&kr2.x);
    float2 kr23 = __half22float2(*(__half2*)&kr2.y);

    const size_t dst = ((size_t)(b * HEADS + h) * TLEN + t) * HDIM + d0;
    __half2 kk01 = __floats2half2_rn(ke01.x + kr01.x, ke01.y + kr01.y);
    __half2 kk23 = __floats2half2_rn(ke23.x + kr23.x, ke23.y + kr23.y);
    *(uint2*)(kkh + dst) = make_uint2(*(uint32_t*)&kk01, *(uint32_t*)&kk23);

    float4 u4 = *(const float4*)(ub + h * HDIM + d0);
    float4 w4 = *(const float4*)(vb + h * HDIM + d0);
    float bsum = u4.x * ke01.x + u4.y * ke01.y + u4.z * ke23.x + u4.w * ke23.y
               + w4.x * kr01.x + w4.y * kr01.y + w4.z * kr23.x + w4.w * kr23.y;
#pragma unroll
    for (int off = 8; off; off >>= 1)
        bsum += __shfl_xor_sync(0xffffffffu, bsum, off, 16);
    if (l16 == 0)
        biasO[(size_t)(b * HEADS + h) * TLEN + t] = bsum * 0.125f;  // pre-scaled
}

// ---------------- fp16 flash attention (split-KV x4, double-buffered) --------
#define QH_OFF 0u
#define PH_OFF 18432u
#define KK_OFF 36864u          // + buf*9216
#define V_OFF  55296u          // + buf*9216
#define BI_OFF 73728u          // + buf*256
#define KVBUF  9216u
#define FLASH_SMEM 74240
#define ML_HALF (ROWS_X * HEADS * 2)
#define PO_HALF ((size_t)ROWS_X * DMODEL)

__global__ void __launch_bounds__(256, 2)
flash16_kernel(const __half* __restrict__ qh,
               const __half* __restrict__ kkh,
               const __half* __restrict__ vhg,
               const float* __restrict__ biasG,
               float* __restrict__ poAll, float* __restrict__ mlAll)
{
    extern __shared__ char fsm[];
    const uint32_t sbase = (uint32_t)__cvta_generic_to_shared(fsm);
    __half* PhH = (__half*)(fsm + PH_OFF);

    const int xid = blockIdx.x;
    const int qb = 7 - (xid >> 2);       // heavy q-blocks first
    const int hf = xid & 3;
    const int h = blockIdx.y, b = blockIdx.z;
    const int tid = threadIdx.x;
    const int lane = tid & 31, wid = tid >> 5;
    const int q = lane >> 2, r = lane & 3;
    const int mw = wid * 16;
    const int alr = lane & 15, alc = lane >> 4;
    const int bg = lane >> 3,  blr = lane & 7;

    const int ntAll = 18 + 2 * qb;
    const int base = ntAll >> 2, rem = ntAll & 3;
    const int tstart = hf * base + min(hf, rem);
    const int tend   = tstart + base + (hf < rem ? 1 : 0);
    float* po  = poAll + (size_t)hf * PO_HALF;
    float* mlp = mlAll + (size_t)hf * ML_HALF;

    const size_t  bh   = (size_t)(b * HEADS + h) * TLEN;
    const __half* kkbh = kkh + bh * HDIM;
    const __half* vbh  = vhg + bh * HDIM;
    const float*  bibh = biasG + bh;

    auto issueQ = [&]() {
#pragma unroll
        for (int it = 0; it < 4; it++) {
            int idx = tid + it * 256;
            int row = idx >> 3, c = idx & 7;
            cp_async16(sbase + QH_OFF + (uint32_t)row * HROW + (uint32_t)c * 16u,
                       qh + ((size_t)((qb * 128 + row) * BATCH + b)) * DMODEL
                          + h * HDIM + c * 8);
        }
    };
    auto issueKV = [&](int t0, int buf) {
        const uint32_t kkB = sbase + KK_OFF + (uint32_t)buf * KVBUF;
        const uint32_t vB  = sbase + V_OFF  + (uint32_t)buf * KVBUF;
#pragma unroll
        for (int it = 0; it < 2; it++) {
            int idx = tid + it * 256;
            int row = idx >> 3, c = idx & 7;
            const uint32_t d = (uint32_t)row * HROW + (uint32_t)c * 16u;
            cp_async16(kkB + d, kkbh + (size_t)(t0 + row) * HDIM + c * 8);
            cp_async16(vB  + d, vbh  + (size_t)(t0 + row) * HDIM + c * 8);
        }
        if (tid < 16)
            cp_async16(sbase + BI_OFF + (uint32_t)(buf * 256 + tid * 16),
                       bibh + t0 + tid * 4);
    };

    issueQ();
    issueKV(tstart * 64, tstart & 1);
    cp_commit();

    float m0 = -1e30f, m1 = -1e30f, l0 = 0.f, l1 = 0.f;
    float O[8][4];
#pragma unroll
    for (int nt = 0; nt < 8; nt++)
#pragma unroll
        for (int e = 0; e < 4; e++) O[nt][e] = 0.f;

    const int srow0 = qb * 128 + mw + q;

    for (int tt = tstart; tt < tend; tt++) {
        const int t0 = tt * 64;
        const int buf = tt & 1;
        const bool more = (tt + 1 < tend);

        cp_wait<0>();
        __syncthreads();

        if (more) { issueKV(t0 + 64, buf ^ 1); cp_commit(); }

        const uint32_t kkB = sbase + KK_OFF + (uint32_t)buf * KVBUF;
        const uint32_t vB  = sbase + V_OFF  + (uint32_t)buf * KVBUF;
        const float* bS = (const float*)(fsm + BI_OFF + buf * 256);

        // ---- S = Q @ KK^T  (fp16 mma) --------------------------------------
        float sc[8][4];
#pragma unroll
        for (int nt = 0; nt < 8; nt++)
#pragma unroll
            for (int e = 0; e < 4; e++) sc[nt][e] = 0.f;

#pragma unroll
        for (int ks = 0; ks < 4; ks++) {
            uint32_t afr[4];
            ldm_x4(afr, sbase + QH_OFF + (uint32_t)(mw + alr) * HROW
                         + (uint32_t)(ks * 32 + alc * 16));
#pragma unroll
            for (int tb = 0; tb < 4; tb++) {
                uint32_t tmp[4];
                ldm_x4(tmp, kkB
                             + (uint32_t)(tb * 16 + (bg >> 1) * 8 + blr) * HROW
                             + (uint32_t)(ks * 32 + (bg & 1) * 16));
                mma_f16(sc[tb * 2],     afr, tmp);
                mma_f16(sc[tb * 2 + 1], afr, tmp + 2);
            }
        }

        // ---- bias(pre-scaled) + causal mask + online softmax ----------------
        const bool mt_ = (tt >= 16 + 2 * qb);
        float tmax0 = -1e30f, tmax1 = -1e30f;
#pragma unroll
        for (int nt = 0; nt < 8; nt++) {
            const int colb = nt * 8 + 2 * r;
            const float bi0 = bS[colb], bi1 = bS[colb + 1];
            float v0 = fmaf(sc[nt][0], 0.125f, bi0);
            float v1 = fmaf(sc[nt][1], 0.125f, bi1);
            float v2 = fmaf(sc[nt][2], 0.125f, bi0);
            float v3 = fmaf(sc[nt][3], 0.125f, bi1);
            if (mt_) {
                const int tc = t0 + colb;
                if (tc     > S_LEN + srow0)     v0 = -1e30f;
                if (tc + 1 > S_LEN + srow0)     v1 = -1e30f;
                if (tc     > S_LEN + srow0 + 8) v2 = -1e30f;
                if (tc + 1 > S_LEN + srow0 + 8) v3 = -1e30f;
            }
            sc[nt][0] = v0; sc[nt][1] = v1; sc[nt][2] = v2; sc[nt][3] = v3;
            tmax0 = fmaxf(tmax0, fmaxf(v0, v1));
            tmax1 = fmaxf(tmax1, fmaxf(v2, v3));
        }
        tmax0 = fmaxf(tmax0, __shfl_xor_sync(0xffffffffu, tmax0, 1));
        tmax0 = fmaxf(tmax0, __shfl_xor_sync(0xffffffffu, tmax0, 2));
        tmax1 = fmaxf(tmax1, __shfl_xor_sync(0xffffffffu, tmax1, 1));
        tmax1 = fmaxf(tmax1, __shfl_xor_sync(0xffffffffu, tmax1, 2));

        const float mnew0 = fmaxf(m0, tmax0);
        const float mnew1 = fmaxf(m1, tmax1);
        const float c0 = __expf(m0 - mnew0);
        const float c1 = __expf(m1 - mnew1);
        m0 = mnew0; m1 = mnew1;
        l0 *= c0; l1 *= c1;

        const bool doscale = !__all_sync(0xffffffffu, (c0 == 1.f) && (c1 == 1.f));

        float ps0 = 0.f, ps1 = 0.f;
#pragma unroll
        for (int nt = 0; nt < 8; nt++) {
            float p0 = __expf(sc[nt][0] - mnew0);
            float p1 = __expf(sc[nt][1] - mnew0);
            float p2 = __expf(sc[nt][2] - mnew1);
            float p3 = __expf(sc[nt][3] - mnew1);
            ps0 += p0 + p1; ps1 += p2 + p3;
            if (doscale) {
                O[nt][0] *= c0; O[nt][1] *= c0;
                O[nt][2] *= c1; O[nt][3] *= c1;
            }
            const int colp = nt * 8 + 2 * r;
            *(__half2*)&PhH[(size_t)(mw + q) * 72 + colp]     = __floats2half2_rn(p0, p1);
            *(__half2*)&PhH[(size_t)(mw + q + 8) * 72 + colp] = __floats2half2_rn(p2, p3);
        }
        l0 += ps0; l1 += ps1;
        __syncwarp();          // P is warp-private

        // ---- O += P @ V ------------------------------------------------------
#pragma unroll
        for (int ks = 0; ks < 4; ks++) {
            uint32_t afr[4];
            ldm_x4(afr, sbase + PH_OFF + (uint32_t)(mw + alr) * HROW
                         + (uint32_t)(ks * 32 + alc * 16));
#pragma unroll
            for (int dp = 0; dp < 4; dp++) {
                uint32_t tmp[4];
                ldm_x4_t(tmp, vB
                               + (uint32_t)(ks * 16 + (bg & 1) * 8 + blr) * HROW
                               + (uint32_t)(dp * 32 + (bg >> 1) * 16));
                mma_f16(O[dp * 2],     afr, tmp);
                mma_f16(O[dp * 2 + 1], afr, tmp + 2);
            }
        }
        // next iteration's top syncthreads covers buf reuse
    }

    // ---- finalize: reduce l over quad; store UNNORMALIZED O (fp32) + (m,l) --
    l0 += __shfl_xor_sync(0xffffffffu, l0, 1);
    l0 += __shfl_xor_sync(0xffffffffu, l0, 2);
    l1 += __shfl_xor_sync(0xffffffffu, l1, 1);
    l1 += __shfl_xor_sync(0xffffffffu, l1, 2);

    const int row0 = qb * 128 + mw + q;
#pragma unroll
    for (int nt = 0; nt < 8; nt++) {
        const int col = nt * 8 + 2 * r;
        *(float2*)(po + ((size_t)(row0 * BATCH + b)) * DMODEL + h * HDIM + col)
            = make_float2(O[nt][0], O[nt][1]);
        *(float2*)(po + ((size_t)((row0 + 8) * BATCH + b)) * DMODEL + h * HDIM + col)
            = make_float2(O[nt][2], O[nt][3]);
    }
    if (r == 0) {
        const size_t i0 = (((size_t)(row0 * BATCH + b)) * HEADS + h) * 2;
        mlp[i0]     = m0;
        mlp[i0 + 1] = l0;
        const size_t i1 = (((size_t)((row0 + 8) * BATCH + b)) * HEADS + h) * 2;
        mlp[i1]     = m1;
        mlp[i1 + 1] = l1;
    }
}

// ---------------- combine split-KV partials (4-way) -> fp16 av ---------------
__global__ void __launch_bounds__(256)
combine_kernel(const float* __restrict__ poAll, const float* __restrict__ mlAll,
               __half* __restrict__ out)
{
    const int row = blockIdx.x;          // = s*BATCH + b
    const int tid = threadIdx.x;
    const int d0 = tid * 4;
    const int h = d0 >> 6;

    float mv[NSPLIT], lv[NSPLIT];
    float M = -1e30f;
#pragma unroll
    for (int i = 0; i < NSPLIT; i++) {
        const float* mlp = mlAll + (size_t)i * ML_HALF + ((size_t)row * HEADS + h) * 2;
        mv[i] = mlp[0];
        lv[i] = mlp[1];
        M = fmaxf(M, mv[i]);
    }
    float w[NSPLIT], lsum = 0.f;
#pragma unroll
    for (int i = 0; i < NSPLIT; i++) {
        w[i] = __expf(mv[i] - M);
        lsum += lv[i] * w[i];
    }
    const float inv = 1.f / lsum;
#pragma unroll
    for (int i = 0; i < NSPLIT; i++) w[i] *= inv;

    float o0 = 0.f, o1 = 0.f, o2 = 0.f, o3 = 0.f;
#pragma unroll
    for (int i = 0; i < NSPLIT; i++) {
        const float4 a = *(const float4*)(poAll + (size_t)i * PO_HALF
                                          + (size_t)row * DMODEL + d0);
        o0 += a.x * w[i]; o1 += a.y * w[i];
        o2 += a.z * w[i]; o3 += a.w * w[i];
    }
    __half2 h01 = __floats2half2_rn(o0, o1);
    __half2 h23 = __floats2half2_rn(o2, o3);
    *(uint2*)(out + (size_t)row * DMODEL + d0)
        = make_uint2(*(uint32_t*)&h01, *(uint32_t*)&h23);
}

// ---------------- LayerNorm(a0 [+ a1] + res) * g + b -------------------------
__global__ void __launch_bounds__(256)
ln_kernel(const float* __restrict__ a0, const float* __restrict__ a1,
          const float* __restrict__ res,
          const float* __restrict__ g, const float* __restrict__ bta,
          float* __restrict__ out, __half* __restrict__ out_h)
{
    const int row = blockIdx.x;
    const int tid = threadIdx.x;
    const int lane = tid & 31, wrp = tid >> 5;
    __shared__ float red[8];
    __shared__ float bc;

    float vals[4];
    float s = 0.f;
    const float* ar = a0 + (size_t)row * DMODEL;
    const float* br = a1 ? a1 + (size_t)row * DMODEL : nullptr;
    const float* rr = res + (size_t)row * DMODEL;
#pragma unroll
    for (int i = 0; i < 4; i++) {
        int d = tid + i * 256;
        float v = ar[d] + rr[d];
        if (br) v += br[d];
        vals[i] = v;
        s += v;
    }
#pragma unroll
    for (int off = 16; off; off >>= 1) s += __shfl_xor_sync(0xffffffffu, s, off);
    if (lane == 0) red[wrp] = s;
    __syncthreads();
    if (tid == 0) {
        float t = 0.f;
#pragma unroll
        for (int w = 0; w < 8; w++) t += red[w];
        bc = t * (1.f / DMODEL);
    }
    __syncthreads();
    const float mu = bc;

    float vs = 0.f;
#pragma unroll
    for (int i = 0; i < 4; i++) {
        float dd = vals[i] - mu;
        vs += dd * dd;
    }
#pragma unroll
    for (int off = 16; off; off >>= 1) vs += __shfl_xor_sync(0xffffffffu, vs, off);
    __syncthreads();
    if (lane == 0) red[wrp] = vs;
    __syncthreads();
    if (tid == 0) {
        float t = 0.f;
#pragma unroll
        for (int w = 0; w < 8; w++) t += red[w];
        bc = rsqrtf(t * (1.f / DMODEL) + 1e-5f);
    }
    __syncthreads();
    const float rstd = bc;

    float* orow = out + (size_t)row * DMODEL;
    __half* hrow = out_h ? out_h + (size_t)row * DMODEL : nullptr;
#pragma unroll
    for (int i = 0; i < 4; i++) {
        int d = tid + i * 256;
        float vv = (vals[i] - mu) * rstd * g[d] + bta[d];
        orow[d] = vv;
        if (hrow) hrow[d] = __float2half(vv);
    }
}

// ---------------- launcher ---------------------------------------------------
extern "C" void kernel_launch(void* const* d_in, const int* in_sizes, int n_in,
                              void* d_out, int out_size)
{
    const float* x      = (const float*)d_in[0];
    const float* p      = (const float*)d_in[1];
    /* mask d_in[2] is analytic: unused */
    const float* memory = (const float*)d_in[3];
    const float* u_bias = (const float*)d_in[4];
    const float* v_bias = (const float*)d_in[5];
    const float* wq  = (const float*)d_in[6];
    const float* wke = (const float*)d_in[7];
    const float* wkr = (const float*)d_in[8];
    const float* wv  = (const float*)d_in[9];
    const float* wc  = (const float*)d_in[10];
    const float* w1  = (const float*)d_in[11];
    const float* w1b = (const float*)d_in[12];
    const float* w2  = (const float*)d_in[13];
    const float* w2b = (const float*)d_in[14];
    const float* ln1g = (const float*)d_in[15];
    const float* ln1b = (const float*)d_in[16];
    const float* ln2g = (const float*)d_in[17];
    const float* ln2b = (const float*)d_in[18];
    float* out = (float*)d_out;

    float *tbuf, *t2buf, *ubuf, *bias2, *poAll, *mlAll;
    __half *xh, *memh, *ph, *wqh, *wkeh, *wkrh, *wvh, *wch, *w1h, *w2h;
    __half *qh, *keh, *krh, *avh, *uh, *h1h, *kkh, *vh;
    cudaGetSymbolAddress((void**)&tbuf,  g_t);
    cudaGetSymbolAddress((void**)&t2buf, g_t2);
    cudaGetSymbolAddress((void**)&ubuf,  g_u);
    cudaGetSymbolAddress((void**)&poAll, g_po);
    cudaGetSymbolAddress((void**)&mlAll, g_ml);
    cudaGetSymbolAddress((void**)&xh,    g_xh);
    cudaGetSymbolAddress((void**)&memh,  g_memh);
    cudaGetSymbolAddress((void**)&ph,    g_ph);
    cudaGetSymbolAddress((void**)&wqh,   g_wqh);
    cudaGetSymbolAddress((void**)&wkeh,  g_wkeh);
    cudaGetSymbolAddress((void**)&wkrh,  g_wkrh);
    cudaGetSymbolAddress((void**)&wvh,   g_wvh);
    cudaGetSymbolAddress((void**)&wch,   g_wch);
    cudaGetSymbolAddress((void**)&w1h,   g_w1h);
    cudaGetSymbolAddress((void**)&w2h,   g_w2h);
    cudaGetSymbolAddress((void**)&qh,    g_qh);
    cudaGetSymbolAddress((void**)&keh,   g_keh);
    cudaGetSymbolAddress((void**)&krh,   g_krh);
    cudaGetSymbolAddress((void**)&avh,   g_avh);
    cudaGetSymbolAddress((void**)&uh,    g_uh);
    cudaGetSymbolAddress((void**)&h1h,   g_h1h);
    cudaGetSymbolAddress((void**)&kkh,   g_kkh);
    cudaGetSymbolAddress((void**)&vh,    g_vh);
    cudaGetSymbolAddress((void**)&bias2, g_bias);

    cudaFuncSetAttribute(gemm16_kernel,
                         cudaFuncAttributeMaxDynamicSharedMemorySize, GEMM16_SMEM);
    cudaFuncSetAttribute(flash16_kernel,
                         cudaFuncAttributeMaxDynamicSharedMemorySize, FLASH_SMEM);

    const dim3 blk(256);
    const size_t half = (size_t)ROWS_X * DMODEL;

    // ---- convert inputs + weights to fp16 (one merged launch) ---------------
    {
        CvtSegs cs{};
        int acc = 0, i = 0;
        auto add = [&](const float* s, __half* d, int n8) {
            cs.src[i] = s; cs.dst[i] = d; acc += n8; cs.end8[i] = acc; i++;
        };
        add(x,      xh,   ROWS_X * DMODEL / 8);
        add(memory, memh, ROWS_X * DMODEL / 8);
        add(p,      ph,   ROWS_T * DMODEL / 8);
        add(wq,  wqh,  DMODEL * DMODEL / 8);
        add(wke, wkeh, DMODEL * DMODEL / 8);
        add(wkr, wkrh, DMODEL * DMODEL / 8);
        add(wv,  wvh,  DMODEL * DMODEL / 8);
        add(wc,  wch,  DMODEL * DMODEL / 8);
        add(w1,  w1h,  FFDIM * DMODEL / 8);
        add(w2,  w2h,  FFDIM * DMODEL / 8);
        cs.nseg = i;
        cvt_all_kernel<<<(acc + 255) / 256, blk>>>(cs, acc);
    }

    // ---- all 6 projections in ONE launch (z = 0..6), fp16 in AND out --------
    // V slices (z=2, z=4) write DIRECTLY into the flash V layout [b,h,t,64].
    {
        GemmPtrs gp{};
        gp.A[0] = xh;   gp.W[0] = wqh;  gp.Ch[0] = qh;
        gp.A[1] = xh;   gp.W[1] = wkeh; gp.Ch[1] = keh + half;
        gp.A[2] = xh;   gp.W[2] = wvh;  gp.Ch[2] = vh;  gp.voff[2] = S_LEN;
        gp.A[3] = memh; gp.W[3] = wkeh; gp.Ch[3] = keh;
        gp.A[4] = memh; gp.W[4] = wvh;  gp.Ch[4] = vh;  gp.voff[4] = 0;
        gp.A[5] = ph;        gp.W[5] = wkrh; gp.Ch[5] = krh;
        gp.A[6] = ph + half; gp.W[6] = wkrh; gp.Ch[6] = krh + half;
        gemm16_kernel<<<dim3(8, 16, 7), blk, GEMM16_SMEM>>>(
            gp, ROWS_X, DMODEL, DMODEL, DMODEL, 0, (1 << 2) | (1 << 4));
    }

    // prep: fuse KK (fp16), bias (fp32, pre-scaled)
    prep_kernel<<<ROWS_T, blk>>>(keh, krh, u_bias, v_bias, kkh, bias2);

    // split-KV x4 fp16 flash attention + combine
    flash16_kernel<<<dim3(32, HEADS, BATCH), blk, FLASH_SMEM>>>(
        qh, kkh, vh, bias2, poAll, mlAll);
    combine_kernel<<<ROWS_X, blk>>>(poAll, mlAll, avh);

    // output proj (split-K=2) + LN1 (fused add; emits uh fp16)
    {
        GemmPtrs gp{};
        gp.A[0] = avh;       gp.W[0] = wch;       gp.C[0] = tbuf;
        gp.A[1] = avh + 512; gp.W[1] = wch + 512; gp.C[1] = t2buf;
        gemm16_kernel<<<dim3(8, 16, 2), blk, GEMM16_SMEM>>>(
            gp, ROWS_X, DMODEL, 512, DMODEL, 0, 0);
    }
    ln_kernel<<<ROWS_X, blk>>>(tbuf, t2buf, x, ln1g, ln1b, ubuf, uh);

    // FFN: w1 (relu, fp16 out), w2 (split-K=2) + LN2 (fused add)
    {
        GemmPtrs gp{};
        gp.A[0] = uh; gp.W[0] = w1h; gp.Ch[0] = h1h; gp.bias[0] = w1b;
        gemm16_kernel<<<dim3(32, 16, 1), blk, GEMM16_SMEM>>>(
            gp, ROWS_X, FFDIM, DMODEL, DMODEL, 1, 0);
    }
    {
        GemmPtrs gp{};
        gp.A[0] = h1h;        gp.W[0] = w2h;        gp.C[0] = tbuf;  gp.bias[0] = w2b;
        gp.A[1] = h1h + 2048; gp.W[1] = w2h + 2048; gp.C[1] = t2buf;
        gemm16_kernel<<<dim3(8, 16, 2), blk, GEMM16_SMEM>>>(
            gp, ROWS_X, DMODEL, 2048, FFDIM, 0, 0);
    }
    ln_kernel<<<ROWS_X, blk>>>(tbuf, t2buf, ubuf, ln2g, ln2b, out, nullptr);
}